// round 11
// baseline (speedup 1.0000x reference)
#include <cuda_runtime.h>
#include <cuda_bf16.h>
#include <math.h>
#include <stdint.h>

// ---------------- problem constants ----------------
#define BB 4
#define TT 2048
#define EE 1024
#define NHH 16
#define DHH 64
#define NEE 2048
#define HIDD 16
#define MTOK (BB*TT)          // 8192 tokens
#define LN_EPS 1e-5f

// ---------------- scratch (device globals; no runtime allocation) ----------
__device__ float g_h[MTOK * EE];          // LN2 output fp32 (for MoE)
__device__ unsigned long long g_part[MTOK * 16];  // per-(row, bn-tile) argmax partials
__device__ int   g_idx[MTOK];             // argmax expert per token
__device__ int   g_hist[NEE];
__device__ int   g_cursor[NEE];
__device__ int   g_offsets[NEE];
__device__ int   g_perm[MTOK];
__device__ __nv_bfloat16 g_Ahi[MTOK * EE];       // GEMM A operand hi [M,K]
__device__ __nv_bfloat16 g_Alo[MTOK * EE];
__device__ __nv_bfloat16 g_Bhi[3 * EE * EE];     // weights transposed [N,K]
__device__ __nv_bfloat16 g_Blo[3 * EE * EE];
__device__ __nv_bfloat16 g_QKVhi[MTOK * 3 * EE]; // qkv bf16 hi/lo
__device__ __nv_bfloat16 g_QKVlo[MTOK * 3 * EE];

// =====================================================================
// PTX helpers (family-portable: cp.async / ldmatrix / mma.sync only)
// =====================================================================
__device__ __forceinline__ uint32_t smem_u32(const void* p){
    uint32_t a;
    asm("{ .reg .u64 t; cvta.to.shared.u64 t, %1; cvt.u32.u64 %0, t; }"
        : "=r"(a) : "l"(p));
    return a;
}
__device__ __forceinline__ void cp_async16(uint32_t dst, const void* src){
    asm volatile("cp.async.cg.shared.global [%0], [%1], 16;"
        :: "r"(dst), "l"(src));
}
__device__ __forceinline__ void cp_commit(){
    asm volatile("cp.async.commit_group;");
}
template<int N> __device__ __forceinline__ void cp_wait(){
    asm volatile("cp.async.wait_group %0;" :: "n"(N));
}
__device__ __forceinline__ void ldsm_x4(uint32_t* r, uint32_t a){
    asm volatile("ldmatrix.sync.aligned.m8n8.x4.shared.b16 {%0,%1,%2,%3}, [%4];"
        : "=r"(r[0]), "=r"(r[1]), "=r"(r[2]), "=r"(r[3]) : "r"(a));
}
__device__ __forceinline__ void ldsm_x4_t(uint32_t* r, uint32_t a){
    asm volatile("ldmatrix.sync.aligned.m8n8.x4.trans.shared.b16 {%0,%1,%2,%3}, [%4];"
        : "=r"(r[0]), "=r"(r[1]), "=r"(r[2]), "=r"(r[3]) : "r"(a));
}
__device__ __forceinline__ void mma16816(float* d, const uint32_t* a, const uint32_t* b){
    asm volatile(
        "mma.sync.aligned.m16n8k16.row.col.f32.bf16.bf16.f32 "
        "{%0,%1,%2,%3}, {%4,%5,%6,%7}, {%8,%9}, {%0,%1,%2,%3};"
        : "+f"(d[0]), "+f"(d[1]), "+f"(d[2]), "+f"(d[3])
        : "r"(a[0]), "r"(a[1]), "r"(a[2]), "r"(a[3]), "r"(b[0]), "r"(b[1]));
}
__device__ __forceinline__ uint32_t packsplit(float x, float y, uint32_t& lo){
    __nv_bfloat162 h = __floats2bfloat162_rn(x, y);
    __nv_bfloat162 l = __floats2bfloat162_rn(x - __bfloat162float(h.x),
                                             y - __bfloat162float(h.y));
    lo = *(uint32_t*)&l;
    return *(uint32_t*)&h;
}
// monotone encoding of (float value, col) for argmax-with-first-tiebreak
__device__ __forceinline__ unsigned long long enc_argmax(float v, int col){
    uint32_t u = __float_as_uint(v);
    u = (u & 0x80000000u) ? ~u : (u | 0x80000000u);
    return ((unsigned long long)u << 32) | (uint32_t)(~col);
}
__device__ __forceinline__ int dec_argmax(unsigned long long k){
    return (int)(~(uint32_t)k);
}

// =====================================================================
// Weights: fp32 W[K,N] -> transposed bf16 hi/lo [N,K]
// =====================================================================
__global__ __launch_bounds__(256) void convW_kernel(
    const float* __restrict__ W, __nv_bfloat16* __restrict__ hi,
    __nv_bfloat16* __restrict__ lo, int N, int K)
{
    __shared__ float tile[64][65];
    const int k0 = blockIdx.y * 64;
    const int n0 = blockIdx.x * 64;
    for (int i = threadIdx.x; i < 4096; i += 256) {
        const int r = i >> 6, c = i & 63;
        tile[r][c] = W[(size_t)(k0 + r) * N + n0 + c];
    }
    __syncthreads();
    for (int i = threadIdx.x; i < 4096; i += 256) {
        const int r = i >> 6, c = i & 63;
        const float v = tile[c][r];
        const __nv_bfloat16 h = __float2bfloat16(v);
        const __nv_bfloat16 l = __float2bfloat16(v - __bfloat162float(h));
        const size_t o = (size_t)(n0 + r) * K + k0 + c;
        hi[o] = h;
        lo[o] = l;
    }
}

// =====================================================================
// split-bf16 HMMA GEMM: C[M,N] = A[M,K] @ W[K,N] + bias (+ res)
// CTA 128x128, BK=32, 2-stage cp.async, 2 CTAs/SM, 8 warps (2x4),
// warp tile 64x32, term-major MMA ordering (RAW chains broken).
// Epilogue: fp32 (Cf) / bf16 hi-lo (outHi/outLo) / argmax partials (part)
// =====================================================================
#define RS 80                      // smem row stride bytes (40 bf16)
#define MATB (128*RS)              // 10240 B per matrix tile
#define STGB (4*MATB)              // 40960 B per stage
#define GEMM_SMEM (512 + 2*STGB)   // bias + 2 stages = 82432 -> 2 CTAs/SM

__global__ __launch_bounds__(256, 2)
void gemm_tc(const __nv_bfloat16* __restrict__ Ahi, const __nv_bfloat16* __restrict__ Alo,
             const __nv_bfloat16* __restrict__ Bhi, const __nv_bfloat16* __restrict__ Blo,
             const float* __restrict__ bias, const float* __restrict__ res,
             float* __restrict__ Cf,
             __nv_bfloat16* __restrict__ outHi, __nv_bfloat16* __restrict__ outLo,
             unsigned long long* __restrict__ part,
             int N, int K)
{
    extern __shared__ __align__(128) char smem[];
    const int tid = threadIdx.x;
    const int lane = tid & 31, wid = tid >> 5;
    const int warp_m = wid & 1, warp_n = wid >> 1;     // 2 x 4
    const int bn = blockIdx.x, bm = blockIdx.y;
    const uint32_t sb = smem_u32(smem);
    float* bsm = (float*)smem;

    if (tid < 128) bsm[tid] = bias[bn * 128 + tid];

    const __nv_bfloat16* gA[2] = { Ahi + (size_t)bm * 128 * K,
                                   Alo + (size_t)bm * 128 * K };
    const __nv_bfloat16* gB[2] = { Bhi + (size_t)bn * 128 * K,
                                   Blo + (size_t)bn * 128 * K };

    const int r0 = tid >> 2, c0 = tid & 3;
    const int r1 = r0 + 64;

    auto load_stage = [&](int s, int k0){
        const uint32_t st = sb + 512 + s * STGB;
        #pragma unroll
        for (int m = 0; m < 2; m++) {
            const __nv_bfloat16* src = gA[m] + k0;
            const uint32_t d = st + m * MATB;
            cp_async16(d + r0 * RS + c0 * 16, src + (size_t)r0 * K + c0 * 8);
            cp_async16(d + r1 * RS + c0 * 16, src + (size_t)r1 * K + c0 * 8);
        }
        #pragma unroll
        for (int m = 0; m < 2; m++) {
            const __nv_bfloat16* src = gB[m] + k0;
            const uint32_t d = st + (2 + m) * MATB;
            cp_async16(d + r0 * RS + c0 * 16, src + (size_t)r0 * K + c0 * 8);
            cp_async16(d + r1 * RS + c0 * 16, src + (size_t)r1 * K + c0 * 8);
        }
    };

    float acc[4][4][4];
    #pragma unroll
    for (int i = 0; i < 4; i++)
        #pragma unroll
        for (int j = 0; j < 4; j++)
            #pragma unroll
            for (int t = 0; t < 4; t++) acc[i][j][t] = 0.f;

    const int nk = K >> 5;
    load_stage(0, 0);  cp_commit();
    load_stage(1, 32); cp_commit();

    const int l15 = lane & 15;
    const uint32_t aRowOff = (uint32_t)(warp_m * 64 + l15) * RS + (uint32_t)(lane >> 4) * 16;
    const uint32_t bRowOff = (uint32_t)(warp_n * 32 + (lane & 7) + ((lane >> 4) << 3)) * RS
                           + (uint32_t)((lane >> 3) & 1) * 16;

    for (int c = 0; c < nk; c++) {
        if (c == nk - 1) cp_wait<0>(); else cp_wait<1>();
        __syncthreads();

        const uint32_t st = sb + 512 + (c & 1) * STGB;
        #pragma unroll
        for (int kk = 0; kk < 2; kk++) {
            uint32_t bh[2][4], bl[2][4];
            #pragma unroll
            for (int np = 0; np < 2; np++) {
                const uint32_t ba = st + bRowOff + (uint32_t)np * 16 * RS + kk * 32;
                ldsm_x4(bh[np], ba + 2 * MATB);
                ldsm_x4(bl[np], ba + 3 * MATB);
            }
            #pragma unroll
            for (int mt = 0; mt < 4; mt++) {
                const uint32_t aa = st + aRowOff + (uint32_t)mt * 16 * RS + kk * 32;
                uint32_t ah[4], al[4];
                ldsm_x4(ah, aa);
                ldsm_x4(al, aa + MATB);
                // term-major: 4 independent accs between same-acc MMAs
                #pragma unroll
                for (int nt = 0; nt < 4; nt++)
                    mma16816(acc[mt][nt], ah, &bh[nt >> 1][(nt & 1) * 2]);
                #pragma unroll
                for (int nt = 0; nt < 4; nt++)
                    mma16816(acc[mt][nt], ah, &bl[nt >> 1][(nt & 1) * 2]);
                #pragma unroll
                for (int nt = 0; nt < 4; nt++)
                    mma16816(acc[mt][nt], al, &bh[nt >> 1][(nt & 1) * 2]);
            }
        }
        __syncthreads();
        if (c + 2 < nk) { load_stage(c & 1, (c + 2) * 32); cp_commit(); }
    }

    const int mBase = bm * 128 + warp_m * 64;
    const int nBase = warp_n * 32;
    const int gn0 = bn * 128;

    if (part) {
        // fused argmax partials (gate GEMM): smem two-level reduce, no atomics
        unsigned long long* psm = (unsigned long long*)(smem + 512);  // [128][4]
        #pragma unroll
        for (int mt = 0; mt < 4; mt++) {
            #pragma unroll
            for (int hh = 0; hh < 2; hh++) {
                const int rloc = warp_m * 64 + mt * 16 + (lane >> 2) + hh * 8;
                float bestv = -3.4e38f; int bestc = 0;
                #pragma unroll
                for (int nt = 0; nt < 4; nt++) {
                    const int lc = nBase + nt * 8 + (lane & 3) * 2;
                    const float vx = acc[mt][nt][hh * 2 + 0] + bsm[lc];
                    const float vy = acc[mt][nt][hh * 2 + 1] + bsm[lc + 1];
                    if (vx > bestv) { bestv = vx; bestc = gn0 + lc; }
                    if (vy > bestv) { bestv = vy; bestc = gn0 + lc + 1; }
                }
                unsigned long long key = enc_argmax(bestv, bestc);
                unsigned long long o1 = __shfl_xor_sync(0xffffffffu, key, 1);
                if (o1 > key) key = o1;
                unsigned long long o2 = __shfl_xor_sync(0xffffffffu, key, 2);
                if (o2 > key) key = o2;
                if ((lane & 3) == 0) psm[rloc * 4 + warp_n] = key;
            }
        }
        __syncthreads();
        if (tid < 128) {
            unsigned long long k = psm[tid * 4 + 0];
            unsigned long long t1 = psm[tid * 4 + 1]; if (t1 > k) k = t1;
            unsigned long long t2 = psm[tid * 4 + 2]; if (t2 > k) k = t2;
            unsigned long long t3 = psm[tid * 4 + 3]; if (t3 > k) k = t3;
            part[(size_t)(bm * 128 + tid) * 16 + bn] = k;
        }
        return;
    }

    #pragma unroll
    for (int mt = 0; mt < 4; mt++) {
        #pragma unroll
        for (int nt = 0; nt < 4; nt++) {
            const int row = mBase + mt * 16 + (lane >> 2);
            const int col = nBase + nt * 8 + (lane & 3) * 2;
            #pragma unroll
            for (int hh = 0; hh < 2; hh++) {
                const int m = row + hh * 8;
                float vx = acc[mt][nt][hh * 2 + 0] + bsm[col];
                float vy = acc[mt][nt][hh * 2 + 1] + bsm[col + 1];
                if (outHi) {
                    uint32_t lo;
                    const uint32_t hi = packsplit(vx, vy, lo);
                    *(uint32_t*)(outHi + (size_t)m * N + gn0 + col) = hi;
                    *(uint32_t*)(outLo + (size_t)m * N + gn0 + col) = lo;
                } else {
                    if (res) {
                        const float2 rv = *(const float2*)(res + (size_t)m * N + gn0 + col);
                        vx += rv.x; vy += rv.y;
                    }
                    float2 v; v.x = vx; v.y = vy;
                    *(float2*)(Cf + (size_t)m * N + gn0 + col) = v;
                }
            }
        }
    }
}

// =====================================================================
// HMMA flash attention (causal, split-bf16, unnormalized exp softmax)
// Grid (T/128, NH, B), 256 threads = 8 warps, warp owns 16 q rows.
// Q 128x64 hi/lo; K/V 64-key tiles, 2-stage cp.async; 2 CTAs/SM.
// =====================================================================
#define SRS 144                     // smem row stride (64 bf16 + 16B pad)
#define ATT_MAT (64*SRS)            // 9216 per matrix (64 rows)
#define ATT_STG (4*ATT_MAT)         // Khi,Klo,Vhi,Vlo = 36864
#define ATT_Q   (128*SRS)           // 18432
#define ATT_SMEM (2*ATT_Q + 2*ATT_STG)   // 110592 -> 2 CTAs/SM

__global__ __launch_bounds__(256, 2)
void flash_mma_kernel(const __nv_bfloat16* __restrict__ QKVhi,
                      const __nv_bfloat16* __restrict__ QKVlo,
                      __nv_bfloat16* __restrict__ Ohi,
                      __nv_bfloat16* __restrict__ Olo)
{
    extern __shared__ __align__(128) char smem[];
    const int tid = threadIdx.x, lane = tid & 31, wid = tid >> 5;
    const int qt = (int)gridDim.x - 1 - (int)blockIdx.x;   // heavy blocks first
    const int q0 = qt * 128;
    const int h = blockIdx.y, b = blockIdx.z;

    const uint32_t sQhi = smem_u32(smem);
    const uint32_t sQlo = sQhi + ATT_Q;
    const uint32_t sKV0 = sQlo + ATT_Q;

    const size_t rowStride = 3 * EE;
    const size_t base = ((size_t)b * TT) * rowStride + (size_t)h * DHH;
    const __nv_bfloat16* Qh = QKVhi + base;
    const __nv_bfloat16* Ql = QKVlo + base;
    const __nv_bfloat16* Kh = Qh + EE;
    const __nv_bfloat16* Kl = Ql + EE;
    const __nv_bfloat16* Vh = Qh + 2 * EE;
    const __nv_bfloat16* Vl = Ql + 2 * EE;

    // ---- Q tile load (128 rows x 8 16B chunks, hi+lo) ----
    for (int i = tid; i < 1024; i += 256) {
        const int row = i >> 3, c = i & 7;
        const size_t g = (size_t)(q0 + row) * rowStride + c * 8;
        cp_async16(sQhi + row * SRS + c * 16, Qh + g);
        cp_async16(sQlo + row * SRS + c * 16, Ql + g);
    }

    auto load_kv = [&](int s, int k0){
        const uint32_t st = sKV0 + s * ATT_STG;
        for (int i = tid; i < 512; i += 256) {
            const int row = i >> 3, c = i & 7;
            const size_t g = (size_t)(k0 + row) * rowStride + c * 8;
            const uint32_t d = st + row * SRS + c * 16;
            cp_async16(d + 0 * ATT_MAT, Kh + g);
            cp_async16(d + 1 * ATT_MAT, Kl + g);
            cp_async16(d + 2 * ATT_MAT, Vh + g);
            cp_async16(d + 3 * ATT_MAT, Vl + g);
        }
    };

    const int nk = 2 * qt + 2;      // 64-key tiles
    load_kv(0, 0);  cp_commit();    // group 0 carries Q too

    float acc_o[8][4];
    #pragma unroll
    for (int i = 0; i < 8; i++)
        #pragma unroll
        for (int j = 0; j < 4; j++) acc_o[i][j] = 0.f;
    float l0 = 0.f, l1 = 0.f;

    const int l15 = lane & 15;
    const uint32_t qOff = (uint32_t)(wid * 16 + l15) * SRS + (uint32_t)(lane >> 4) * 16;
    const uint32_t kRowOff = (uint32_t)((lane & 7) + ((lane >> 4) << 3)) * SRS
                           + (uint32_t)((lane >> 3) & 1) * 16;
    const uint32_t vRowOff = (uint32_t)((lane & 7) + (((lane >> 3) & 1) << 3)) * SRS
                           + (uint32_t)((lane >> 4) & 1) * 16;

    const int limit = q0 + wid * 16 + 15;   // warp's max row

    for (int c = 0; c < nk; c++) {
        cp_wait<0>();
        __syncthreads();
        if (c + 1 < nk) { load_kv((c + 1) & 1, (c + 1) * 64); cp_commit(); }

        const uint32_t Khi_ = sKV0 + (c & 1) * ATT_STG;
        const uint32_t Klo_ = Khi_ + ATT_MAT;
        const uint32_t Vhi_ = Khi_ + 2 * ATT_MAT;
        const uint32_t Vlo_ = Khi_ + 3 * ATT_MAT;
        const int k0 = c * 64;
        const bool needmask = (k0 + 63) > (q0 + wid * 16);

        // ---- S = Q K^T (split bf16) ----
        float sacc[8][4];
        #pragma unroll
        for (int i = 0; i < 8; i++)
            #pragma unroll
            for (int j = 0; j < 4; j++) sacc[i][j] = 0.f;

        #pragma unroll
        for (int kk = 0; kk < 4; kk++) {
            uint32_t qh[4], ql[4];
            ldsm_x4(qh, sQhi + qOff + kk * 32);
            ldsm_x4(ql, sQlo + qOff + kk * 32);
            #pragma unroll
            for (int np = 0; np < 4; np++) {
                if (k0 + np * 16 > limit) break;   // fully masked 16-col tile
                const uint32_t ba = kRowOff + (uint32_t)np * 16 * SRS + kk * 32;
                uint32_t bh[4], bl[4];
                ldsm_x4(bh, Khi_ + ba);
                ldsm_x4(bl, Klo_ + ba);
                #pragma unroll
                for (int t = 0; t < 2; t++) {
                    mma16816(sacc[2 * np + t], qh, &bh[2 * t]);
                    mma16816(sacc[2 * np + t], qh, &bl[2 * t]);
                    mma16816(sacc[2 * np + t], ql, &bh[2 * t]);
                }
            }
        }

        // ---- unnormalized softmax: p = exp(s/8), masked -> 0 ----
        const int rbase = q0 + wid * 16 + (lane >> 2);
        float s0 = 0.f, s1 = 0.f;
        #pragma unroll
        for (int nt = 0; nt < 8; nt++) {
            const int col = k0 + nt * 8 + 2 * (lane & 3);
            if (k0 + (nt >> 1) * 16 > limit) {
                sacc[nt][0] = sacc[nt][1] = sacc[nt][2] = sacc[nt][3] = 0.f;
                continue;
            }
            #pragma unroll
            for (int j = 0; j < 4; j++) {
                float v = sacc[nt][j] * 0.125f;
                bool dead = false;
                if (needmask) {
                    const int cc = col + (j & 1);
                    const int rr = rbase + (j >> 1) * 8;
                    dead = (cc > rr);
                }
                v = dead ? 0.f : __expf(v);
                sacc[nt][j] = v;
            }
            s0 += sacc[nt][0] + sacc[nt][1];
            s1 += sacc[nt][2] + sacc[nt][3];
        }
        s0 += __shfl_xor_sync(0xffffffffu, s0, 1);
        s0 += __shfl_xor_sync(0xffffffffu, s0, 2);
        s1 += __shfl_xor_sync(0xffffffffu, s1, 1);
        s1 += __shfl_xor_sync(0xffffffffu, s1, 2);
        l0 += s0; l1 += s1;

        // ---- O += P V (split P, split V) ----
        #pragma unroll
        for (int kkp = 0; kkp < 4; kkp++) {
            if (k0 + kkp * 16 > limit) break;      // P == 0 for these keys
            uint32_t phi[4], plo[4];
            phi[0] = packsplit(sacc[2*kkp][0],   sacc[2*kkp][1],   plo[0]);
            phi[1] = packsplit(sacc[2*kkp][2],   sacc[2*kkp][3],   plo[1]);
            phi[2] = packsplit(sacc[2*kkp+1][0], sacc[2*kkp+1][1], plo[2]);
            phi[3] = packsplit(sacc[2*kkp+1][2], sacc[2*kkp+1][3], plo[3]);
            #pragma unroll
            for (int np = 0; np < 4; np++) {
                const uint32_t va = (uint32_t)(kkp * 16) * SRS + vRowOff + np * 32;
                uint32_t vh[4], vl[4];
                ldsm_x4_t(vh, Vhi_ + va);
                ldsm_x4_t(vl, Vlo_ + va);
                #pragma unroll
                for (int t = 0; t < 2; t++) {
                    mma16816(acc_o[2 * np + t], phi, &vh[2 * t]);
                    mma16816(acc_o[2 * np + t], phi, &vl[2 * t]);
                    mma16816(acc_o[2 * np + t], plo, &vh[2 * t]);
                }
            }
        }
    }

    // ---- epilogue: O / l, write bf16 hi/lo into GEMM A buffers ----
    const float inv0 = 1.f / l0, inv1 = 1.f / l1;
    const int row0 = b * TT + q0 + wid * 16 + (lane >> 2);
    const int colb = h * DHH + 2 * (lane & 3);
    #pragma unroll
    for (int nt = 0; nt < 8; nt++) {
        const int col = colb + nt * 8;
        uint32_t lo;
        uint32_t hi = packsplit(acc_o[nt][0] * inv0, acc_o[nt][1] * inv0, lo);
        *(uint32_t*)(Ohi + (size_t)row0 * EE + col) = hi;
        *(uint32_t*)(Olo + (size_t)row0 * EE + col) = lo;
        hi = packsplit(acc_o[nt][2] * inv1, acc_o[nt][3] * inv1, lo);
        *(uint32_t*)(Ohi + (size_t)(row0 + 8) * EE + col) = hi;
        *(uint32_t*)(Olo + (size_t)(row0 + 8) * EE + col) = lo;
    }
}

// =====================================================================
// LayerNorm: block per row, 256 threads; optional fp32 + bf16 hi/lo out
// =====================================================================
__global__ __launch_bounds__(256) void layernorm_kernel(
    const float* __restrict__ x, const float* __restrict__ gam,
    const float* __restrict__ bet, float* __restrict__ outF,
    __nv_bfloat16* __restrict__ outHi, __nv_bfloat16* __restrict__ outLo)
{
    const int row = blockIdx.x;
    const int tid = threadIdx.x;
    const float4 xv = *(const float4*)(x + (size_t)row * EE + tid * 4);

    __shared__ float red[8];

    float s = xv.x + xv.y + xv.z + xv.w;
    #pragma unroll
    for (int o = 16; o; o >>= 1) s += __shfl_xor_sync(0xffffffffu, s, o);
    if ((tid & 31) == 0) red[tid >> 5] = s;
    __syncthreads();
    float tot = 0.f;
    #pragma unroll
    for (int i = 0; i < 8; i++) tot += red[i];
    const float mu = tot * (1.0f / (float)EE);
    __syncthreads();

    const float dx = xv.x - mu, dy = xv.y - mu, dz = xv.z - mu, dw = xv.w - mu;
    float ss = dx*dx + dy*dy + dz*dz + dw*dw;
    #pragma unroll
    for (int o = 16; o; o >>= 1) ss += __shfl_xor_sync(0xffffffffu, ss, o);
    if ((tid & 31) == 0) red[tid >> 5] = ss;
    __syncthreads();
    float sst = 0.f;
    #pragma unroll
    for (int i = 0; i < 8; i++) sst += red[i];
    const float inv = rsqrtf(sst * (1.0f / (float)EE) + LN_EPS);

    const float4 gv = *(const float4*)(gam + tid * 4);
    const float4 bv = *(const float4*)(bet + tid * 4);
    float4 ov;
    ov.x = dx * inv * gv.x + bv.x;
    ov.y = dy * inv * gv.y + bv.y;
    ov.z = dz * inv * gv.z + bv.z;
    ov.w = dw * inv * gv.w + bv.w;
    if (outF) *(float4*)(outF + (size_t)row * EE + tid * 4) = ov;
    uint32_t lo0, lo1;
    const uint32_t hi0 = packsplit(ov.x, ov.y, lo0);
    const uint32_t hi1 = packsplit(ov.z, ov.w, lo1);
    uint2 hv; hv.x = hi0; hv.y = hi1;
    uint2 lv; lv.x = lo0; lv.y = lo1;
    *(uint2*)(outHi + (size_t)row * EE + tid * 4) = hv;
    *(uint2*)(outLo + (size_t)row * EE + tid * 4) = lv;
}

// =====================================================================
// Argmax reduce over 16 partials per row + expert histogram (fused)
// =====================================================================
__global__ __launch_bounds__(256) void argmax_reduce_kernel(
    const unsigned long long* __restrict__ part, int* __restrict__ idx,
    int* __restrict__ hist)
{
    const int m = blockIdx.x * 256 + threadIdx.x;
    const unsigned long long* p = part + (size_t)m * 16;
    unsigned long long k = p[0];
    #pragma unroll
    for (int i = 1; i < 16; i++) {
        const unsigned long long v = p[i];
        if (v > k) k = v;
    }
    const int e = dec_argmax(k);
    idx[m] = e;
    atomicAdd(&hist[e], 1);
}

// =====================================================================
// MoE routing: clear-hist / scan (hist -> cursor + offsets) / scatter
// =====================================================================
__global__ __launch_bounds__(256) void hist_clear_kernel(int* __restrict__ hist)
{
    hist[blockIdx.x * 256 + threadIdx.x] = 0;
}

__global__ __launch_bounds__(1024) void scan_kernel(
    const int* __restrict__ hist, int* __restrict__ cursor,
    int* __restrict__ offsets)
{
    __shared__ int warpsum[32];
    const int tid = threadIdx.x;
    const int lane = tid & 31, wid = tid >> 5;
    const int v0 = hist[2 * tid], v1 = hist[2 * tid + 1];
    const int tsum = v0 + v1;
    int x = tsum;
    #pragma unroll
    for (int o = 1; o < 32; o <<= 1) {
        const int y = __shfl_up_sync(0xffffffffu, x, o);
        if (lane >= o) x += y;
    }
    if (lane == 31) warpsum[wid] = x;
    __syncthreads();
    if (wid == 0) {
        int w = warpsum[lane];
        #pragma unroll
        for (int o = 1; o < 32; o <<= 1) {
            const int y = __shfl_up_sync(0xffffffffu, w, o);
            if (lane >= o) w += y;
        }
        warpsum[lane] = w;
    }
    __syncthreads();
    const int base = (wid > 0 ? warpsum[wid - 1] : 0) + (x - tsum);
    cursor[2 * tid] = base;
    cursor[2 * tid + 1] = base + v0;
    offsets[2 * tid] = base;
    offsets[2 * tid + 1] = base + v0;
}

__global__ __launch_bounds__(256) void scatter_kernel(
    const int* __restrict__ idx, int* __restrict__ cursor,
    int* __restrict__ perm)
{
    const int t = blockIdx.x * 256 + threadIdx.x;
    const int pos = atomicAdd(&cursor[idx[t]], 1);
    perm[pos] = t;
}

// =====================================================================
// MoE: one block per EXPERT; loops over its tokens (w1/w2 stay in L1)
// =====================================================================
__global__ __launch_bounds__(256) void moe_kernel(
    const float* __restrict__ h,
    const int* __restrict__ perm, const int* __restrict__ offsets,
    const int* __restrict__ hist,
    const float* __restrict__ w1, const float* __restrict__ b1,
    const float* __restrict__ w2, const float* __restrict__ b2,
    float* __restrict__ out)
{
    const int e = blockIdx.x;
    const int count = hist[e];
    if (count == 0) return;
    const int start = offsets[e];
    const int tid = threadIdx.x;

    __shared__ float xs[EE];
    __shared__ float partial[HIDD][17];
    __shared__ float hm[HIDD];

    const int hcol = tid & 15;
    const int grp  = tid >> 4;
    const float* w1p = w1 + (size_t)e * EE * HIDD;
    const float* w2p = w2 + (size_t)e * HIDD * EE;
    const float* b2p = b2 + (size_t)e * EE;
    const float  b1v = (tid < HIDD) ? b1[(size_t)e * HIDD + tid] : 0.f;

    for (int ti = 0; ti < count; ti++) {
        const int token = perm[start + ti];

        const float* hrow = h + (size_t)token * EE;
        for (int i = tid; i < EE; i += 256) xs[i] = hrow[i];
        __syncthreads();

        float acc = 0.f;
        for (int i = grp; i < EE; i += 16)
            acc += xs[i] * w1p[(size_t)i * HIDD + hcol];
        partial[hcol][grp] = acc;
        __syncthreads();

        if (tid < HIDD) {
            float s = b1v;
            #pragma unroll
            for (int g2 = 0; g2 < 16; g2++) s += partial[tid][g2];
            hm[tid] = 0.5f * s * (1.0f + erff(s * 0.70710678118654752f));
        }
        __syncthreads();

        float hreg[HIDD];
        #pragma unroll
        for (int k = 0; k < HIDD; k++) hreg[k] = hm[k];

        float* orow = out + (size_t)token * EE;
        for (int j = tid; j < EE; j += 256) {
            float s = b2p[j];
            #pragma unroll
            for (int k = 0; k < HIDD; k++) s += hreg[k] * w2p[(size_t)k * EE + j];
            orow[j] += s;
        }
        __syncthreads();
    }
}

// =====================================================================
// launch
// =====================================================================
extern "C" void kernel_launch(void* const* d_in, const int* in_sizes, int n_in,
                              void* d_out, int out_size)
{
    const float* x      = (const float*)d_in[0];
    const float* ln1_g  = (const float*)d_in[1];
    const float* ln1_b  = (const float*)d_in[2];
    const float* ln2_g  = (const float*)d_in[3];
    const float* ln2_b  = (const float*)d_in[4];
    const float* qkv_w  = (const float*)d_in[5];
    const float* qkv_b  = (const float*)d_in[6];
    const float* proj_w = (const float*)d_in[7];
    const float* proj_b = (const float*)d_in[8];
    const float* gate_w = (const float*)d_in[9];
    const float* gate_b = (const float*)d_in[10];
    const float* w1     = (const float*)d_in[11];
    const float* b1     = (const float*)d_in[12];
    const float* w2     = (const float*)d_in[13];
    const float* w2b    = (const float*)d_in[14];
    float* out = (float*)d_out;

    void *p_h, *p_part, *p_idx, *p_hist, *p_cur, *p_off, *p_perm,
         *p_ah, *p_al, *p_bh, *p_bl, *p_qh, *p_ql;
    cudaGetSymbolAddress(&p_h, g_h);
    cudaGetSymbolAddress(&p_part, g_part);
    cudaGetSymbolAddress(&p_idx, g_idx);
    cudaGetSymbolAddress(&p_hist, g_hist);
    cudaGetSymbolAddress(&p_cur, g_cursor);
    cudaGetSymbolAddress(&p_off, g_offsets);
    cudaGetSymbolAddress(&p_perm, g_perm);
    cudaGetSymbolAddress(&p_ah, g_Ahi);
    cudaGetSymbolAddress(&p_al, g_Alo);
    cudaGetSymbolAddress(&p_bh, g_Bhi);
    cudaGetSymbolAddress(&p_bl, g_Blo);
    cudaGetSymbolAddress(&p_qh, g_QKVhi);
    cudaGetSymbolAddress(&p_ql, g_QKVlo);
    float* bh      = (float*)p_h;
    unsigned long long* bpart = (unsigned long long*)p_part;
    int*   bidx    = (int*)p_idx;
    int*   hist    = (int*)p_hist;
    int*   cursor  = (int*)p_cur;
    int*   offsets = (int*)p_off;
    int*   perm    = (int*)p_perm;
    __nv_bfloat16* Ahi = (__nv_bfloat16*)p_ah;
    __nv_bfloat16* Alo = (__nv_bfloat16*)p_al;
    __nv_bfloat16* Bhi = (__nv_bfloat16*)p_bh;
    __nv_bfloat16* Blo = (__nv_bfloat16*)p_bl;
    __nv_bfloat16* QKVhi = (__nv_bfloat16*)p_qh;
    __nv_bfloat16* QKVlo = (__nv_bfloat16*)p_ql;

    cudaFuncSetAttribute(gemm_tc, cudaFuncAttributeMaxDynamicSharedMemorySize, GEMM_SMEM);
    cudaFuncSetAttribute(flash_mma_kernel, cudaFuncAttributeMaxDynamicSharedMemorySize, ATT_SMEM);

    // 1) LN1(x) -> bf16 hi/lo A operand
    layernorm_kernel<<<MTOK, 256>>>(x, ln1_g, ln1_b, nullptr, Ahi, Alo);

    // 2) qkv = h @ qkv_w + qkv_b -> bf16 hi/lo qkv buffers
    convW_kernel<<<dim3(3*EE/64, EE/64), 256>>>(qkv_w, Bhi, Blo, 3*EE, EE);
    gemm_tc<<<dim3(3*EE/128, MTOK/128), 256, GEMM_SMEM>>>(
        Ahi, Alo, Bhi, Blo, qkv_b, nullptr, nullptr, QKVhi, QKVlo, nullptr, 3*EE, EE);

    // 3) attention -> bf16 hi/lo into A operand buffers
    flash_mma_kernel<<<dim3(TT/128, NHH, BB), 256, ATT_SMEM>>>(QKVhi, QKVlo, Ahi, Alo);

    // 4) xmid = x + attn @ proj_w + proj_b -> d_out (fp32)
    convW_kernel<<<dim3(EE/64, EE/64), 256>>>(proj_w, Bhi, Blo, EE, EE);
    gemm_tc<<<dim3(EE/128, MTOK/128), 256, GEMM_SMEM>>>(
        Ahi, Alo, Bhi, Blo, proj_b, x, out, nullptr, nullptr, nullptr, EE, EE);

    // 5) LN2 -> fp32 (MoE) + bf16 hi/lo (gate GEMM)
    layernorm_kernel<<<MTOK, 256>>>(out, ln2_g, ln2_b, bh, Ahi, Alo);

    // 6) gate GEMM with fused argmax partials (no logits materialization)
    hist_clear_kernel<<<NEE/256, 256>>>(hist);
    convW_kernel<<<dim3(NEE/64, EE/64), 256>>>(gate_w, Bhi, Blo, NEE, EE);
    gemm_tc<<<dim3(NEE/128, MTOK/128), 256, GEMM_SMEM>>>(
        Ahi, Alo, Bhi, Blo, gate_b, nullptr, nullptr, nullptr, nullptr, bpart, NEE, EE);

    // 7) idx + hist (fused); scan -> cursor/offsets; scatter -> perm
    argmax_reduce_kernel<<<MTOK/256, 256>>>(bpart, bidx, hist);
    scan_kernel<<<1, 1024>>>(hist, cursor, offsets);
    scatter_kernel<<<MTOK/256, 256>>>(bidx, cursor, perm);

    // 8) d_out += moe over experts (block per expert, token loop)
    moe_kernel<<<NEE, 256>>>(bh, perm, offsets, hist, w1, b1, w2, w2b, out);
}

// round 12
// speedup vs baseline: 1.0327x; 1.0327x over previous
#include <cuda_runtime.h>
#include <cuda_bf16.h>
#include <math.h>
#include <stdint.h>

// ---------------- problem constants ----------------
#define BB 4
#define TT 2048
#define EE 1024
#define NHH 16
#define DHH 64
#define NEE 2048
#define HIDD 16
#define MTOK (BB*TT)          // 8192 tokens
#define LN_EPS 1e-5f

// ---------------- scratch (device globals; no runtime allocation) ----------
__device__ float g_h[MTOK * EE];          // LN2 output fp32 (for MoE)
__device__ unsigned long long g_part[MTOK * 16];  // per-(row, bn-tile) argmax partials
__device__ int   g_idx[MTOK];             // argmax expert per token
__device__ int   g_hist[NEE];
__device__ int   g_cursor[NEE];
__device__ int   g_perm[MTOK];
__device__ __nv_bfloat16 g_Ahi[MTOK * EE];       // GEMM A operand hi [M,K]
__device__ __nv_bfloat16 g_Alo[MTOK * EE];
__device__ __nv_bfloat16 g_Bhi[3 * EE * EE];     // weights transposed [N,K]
__device__ __nv_bfloat16 g_Blo[3 * EE * EE];
__device__ __nv_bfloat16 g_QKVhi[MTOK * 3 * EE]; // qkv bf16 hi/lo
__device__ __nv_bfloat16 g_QKVlo[MTOK * 3 * EE];

// =====================================================================
// PTX helpers (family-portable: cp.async / ldmatrix / mma.sync only)
// =====================================================================
__device__ __forceinline__ uint32_t smem_u32(const void* p){
    uint32_t a;
    asm("{ .reg .u64 t; cvta.to.shared.u64 t, %1; cvt.u32.u64 %0, t; }"
        : "=r"(a) : "l"(p));
    return a;
}
__device__ __forceinline__ void cp_async16(uint32_t dst, const void* src){
    asm volatile("cp.async.cg.shared.global [%0], [%1], 16;"
        :: "r"(dst), "l"(src));
}
__device__ __forceinline__ void cp_commit(){
    asm volatile("cp.async.commit_group;");
}
template<int N> __device__ __forceinline__ void cp_wait(){
    asm volatile("cp.async.wait_group %0;" :: "n"(N));
}
__device__ __forceinline__ void ldsm_x4(uint32_t* r, uint32_t a){
    asm volatile("ldmatrix.sync.aligned.m8n8.x4.shared.b16 {%0,%1,%2,%3}, [%4];"
        : "=r"(r[0]), "=r"(r[1]), "=r"(r[2]), "=r"(r[3]) : "r"(a));
}
__device__ __forceinline__ void ldsm_x4_t(uint32_t* r, uint32_t a){
    asm volatile("ldmatrix.sync.aligned.m8n8.x4.trans.shared.b16 {%0,%1,%2,%3}, [%4];"
        : "=r"(r[0]), "=r"(r[1]), "=r"(r[2]), "=r"(r[3]) : "r"(a));
}
__device__ __forceinline__ void mma16816(float* d, const uint32_t* a, const uint32_t* b){
    asm volatile(
        "mma.sync.aligned.m16n8k16.row.col.f32.bf16.bf16.f32 "
        "{%0,%1,%2,%3}, {%4,%5,%6,%7}, {%8,%9}, {%0,%1,%2,%3};"
        : "+f"(d[0]), "+f"(d[1]), "+f"(d[2]), "+f"(d[3])
        : "r"(a[0]), "r"(a[1]), "r"(a[2]), "r"(a[3]), "r"(b[0]), "r"(b[1]));
}
__device__ __forceinline__ uint32_t packsplit(float x, float y, uint32_t& lo){
    __nv_bfloat162 h = __floats2bfloat162_rn(x, y);
    __nv_bfloat162 l = __floats2bfloat162_rn(x - __bfloat162float(h.x),
                                             y - __bfloat162float(h.y));
    lo = *(uint32_t*)&l;
    return *(uint32_t*)&h;
}
// monotone encoding of (float value, col) for argmax-with-first-tiebreak
__device__ __forceinline__ unsigned long long enc_argmax(float v, int col){
    uint32_t u = __float_as_uint(v);
    u = (u & 0x80000000u) ? ~u : (u | 0x80000000u);
    return ((unsigned long long)u << 32) | (uint32_t)(~col);
}
__device__ __forceinline__ int dec_argmax(unsigned long long k){
    return (int)(~(uint32_t)k);
}

// =====================================================================
// Weights: fp32 W[K,N] -> transposed bf16 hi/lo [N,K]
// =====================================================================
__global__ __launch_bounds__(256) void convW_kernel(
    const float* __restrict__ W, __nv_bfloat16* __restrict__ hi,
    __nv_bfloat16* __restrict__ lo, int N, int K)
{
    __shared__ float tile[64][65];
    const int k0 = blockIdx.y * 64;
    const int n0 = blockIdx.x * 64;
    for (int i = threadIdx.x; i < 4096; i += 256) {
        const int r = i >> 6, c = i & 63;
        tile[r][c] = W[(size_t)(k0 + r) * N + n0 + c];
    }
    __syncthreads();
    for (int i = threadIdx.x; i < 4096; i += 256) {
        const int r = i >> 6, c = i & 63;
        const float v = tile[c][r];
        const __nv_bfloat16 h = __float2bfloat16(v);
        const __nv_bfloat16 l = __float2bfloat16(v - __bfloat162float(h));
        const size_t o = (size_t)(n0 + r) * K + k0 + c;
        hi[o] = h;
        lo[o] = l;
    }
}

// =====================================================================
// split-bf16 HMMA GEMM: C[M,N] = A[M,K] @ W[K,N] + bias (+ res)
// CTA 128x128, BK=32, 2-stage cp.async, 2 CTAs/SM, 8 warps (2x4),
// warp tile 64x32, term-major MMA ordering (RAW chains broken).
// Epilogue: fp32 (Cf) / bf16 hi-lo (outHi/outLo) / argmax partials (part)
// =====================================================================
#define RS 80                      // smem row stride bytes (40 bf16)
#define MATB (128*RS)              // 10240 B per matrix tile
#define STGB (4*MATB)              // 40960 B per stage
#define GEMM_SMEM (512 + 2*STGB)   // bias + 2 stages = 82432 -> 2 CTAs/SM

__global__ __launch_bounds__(256, 2)
void gemm_tc(const __nv_bfloat16* __restrict__ Ahi, const __nv_bfloat16* __restrict__ Alo,
             const __nv_bfloat16* __restrict__ Bhi, const __nv_bfloat16* __restrict__ Blo,
             const float* __restrict__ bias, const float* __restrict__ res,
             float* __restrict__ Cf,
             __nv_bfloat16* __restrict__ outHi, __nv_bfloat16* __restrict__ outLo,
             unsigned long long* __restrict__ part,
             int N, int K)
{
    extern __shared__ __align__(128) char smem[];
    const int tid = threadIdx.x;
    const int lane = tid & 31, wid = tid >> 5;
    const int warp_m = wid & 1, warp_n = wid >> 1;     // 2 x 4
    const int bn = blockIdx.x, bm = blockIdx.y;
    const uint32_t sb = smem_u32(smem);
    float* bsm = (float*)smem;

    if (tid < 128) bsm[tid] = bias[bn * 128 + tid];

    const __nv_bfloat16* gA[2] = { Ahi + (size_t)bm * 128 * K,
                                   Alo + (size_t)bm * 128 * K };
    const __nv_bfloat16* gB[2] = { Bhi + (size_t)bn * 128 * K,
                                   Blo + (size_t)bn * 128 * K };

    const int r0 = tid >> 2, c0 = tid & 3;
    const int r1 = r0 + 64;

    auto load_stage = [&](int s, int k0){
        const uint32_t st = sb + 512 + s * STGB;
        #pragma unroll
        for (int m = 0; m < 2; m++) {
            const __nv_bfloat16* src = gA[m] + k0;
            const uint32_t d = st + m * MATB;
            cp_async16(d + r0 * RS + c0 * 16, src + (size_t)r0 * K + c0 * 8);
            cp_async16(d + r1 * RS + c0 * 16, src + (size_t)r1 * K + c0 * 8);
        }
        #pragma unroll
        for (int m = 0; m < 2; m++) {
            const __nv_bfloat16* src = gB[m] + k0;
            const uint32_t d = st + (2 + m) * MATB;
            cp_async16(d + r0 * RS + c0 * 16, src + (size_t)r0 * K + c0 * 8);
            cp_async16(d + r1 * RS + c0 * 16, src + (size_t)r1 * K + c0 * 8);
        }
    };

    float acc[4][4][4];
    #pragma unroll
    for (int i = 0; i < 4; i++)
        #pragma unroll
        for (int j = 0; j < 4; j++)
            #pragma unroll
            for (int t = 0; t < 4; t++) acc[i][j][t] = 0.f;

    const int nk = K >> 5;
    load_stage(0, 0);  cp_commit();
    load_stage(1, 32); cp_commit();

    const int l15 = lane & 15;
    const uint32_t aRowOff = (uint32_t)(warp_m * 64 + l15) * RS + (uint32_t)(lane >> 4) * 16;
    const uint32_t bRowOff = (uint32_t)(warp_n * 32 + (lane & 7) + ((lane >> 4) << 3)) * RS
                           + (uint32_t)((lane >> 3) & 1) * 16;

    for (int c = 0; c < nk; c++) {
        if (c == nk - 1) cp_wait<0>(); else cp_wait<1>();
        __syncthreads();

        const uint32_t st = sb + 512 + (c & 1) * STGB;
        #pragma unroll
        for (int kk = 0; kk < 2; kk++) {
            uint32_t bh[2][4], bl[2][4];
            #pragma unroll
            for (int np = 0; np < 2; np++) {
                const uint32_t ba = st + bRowOff + (uint32_t)np * 16 * RS + kk * 32;
                ldsm_x4(bh[np], ba + 2 * MATB);
                ldsm_x4(bl[np], ba + 3 * MATB);
            }
            #pragma unroll
            for (int mt = 0; mt < 4; mt++) {
                const uint32_t aa = st + aRowOff + (uint32_t)mt * 16 * RS + kk * 32;
                uint32_t ah[4], al[4];
                ldsm_x4(ah, aa);
                ldsm_x4(al, aa + MATB);
                // term-major: 4 independent accs between same-acc MMAs
                #pragma unroll
                for (int nt = 0; nt < 4; nt++)
                    mma16816(acc[mt][nt], ah, &bh[nt >> 1][(nt & 1) * 2]);
                #pragma unroll
                for (int nt = 0; nt < 4; nt++)
                    mma16816(acc[mt][nt], ah, &bl[nt >> 1][(nt & 1) * 2]);
                #pragma unroll
                for (int nt = 0; nt < 4; nt++)
                    mma16816(acc[mt][nt], al, &bh[nt >> 1][(nt & 1) * 2]);
            }
        }
        __syncthreads();
        if (c + 2 < nk) { load_stage(c & 1, (c + 2) * 32); cp_commit(); }
    }

    const int mBase = bm * 128 + warp_m * 64;
    const int nBase = warp_n * 32;
    const int gn0 = bn * 128;

    if (part) {
        // fused argmax partials (gate GEMM): smem two-level reduce, no atomics
        unsigned long long* psm = (unsigned long long*)(smem + 512);  // [128][4]
        #pragma unroll
        for (int mt = 0; mt < 4; mt++) {
            #pragma unroll
            for (int hh = 0; hh < 2; hh++) {
                const int rloc = warp_m * 64 + mt * 16 + (lane >> 2) + hh * 8;
                float bestv = -3.4e38f; int bestc = 0;
                #pragma unroll
                for (int nt = 0; nt < 4; nt++) {
                    const int lc = nBase + nt * 8 + (lane & 3) * 2;
                    const float vx = acc[mt][nt][hh * 2 + 0] + bsm[lc];
                    const float vy = acc[mt][nt][hh * 2 + 1] + bsm[lc + 1];
                    if (vx > bestv) { bestv = vx; bestc = gn0 + lc; }
                    if (vy > bestv) { bestv = vy; bestc = gn0 + lc + 1; }
                }
                unsigned long long key = enc_argmax(bestv, bestc);
                unsigned long long o1 = __shfl_xor_sync(0xffffffffu, key, 1);
                if (o1 > key) key = o1;
                unsigned long long o2 = __shfl_xor_sync(0xffffffffu, key, 2);
                if (o2 > key) key = o2;
                if ((lane & 3) == 0) psm[rloc * 4 + warp_n] = key;
            }
        }
        __syncthreads();
        if (tid < 128) {
            unsigned long long k = psm[tid * 4 + 0];
            unsigned long long t1 = psm[tid * 4 + 1]; if (t1 > k) k = t1;
            unsigned long long t2 = psm[tid * 4 + 2]; if (t2 > k) k = t2;
            unsigned long long t3 = psm[tid * 4 + 3]; if (t3 > k) k = t3;
            part[(size_t)(bm * 128 + tid) * 16 + bn] = k;
        }
        return;
    }

    #pragma unroll
    for (int mt = 0; mt < 4; mt++) {
        #pragma unroll
        for (int nt = 0; nt < 4; nt++) {
            const int row = mBase + mt * 16 + (lane >> 2);
            const int col = nBase + nt * 8 + (lane & 3) * 2;
            #pragma unroll
            for (int hh = 0; hh < 2; hh++) {
                const int m = row + hh * 8;
                float vx = acc[mt][nt][hh * 2 + 0] + bsm[col];
                float vy = acc[mt][nt][hh * 2 + 1] + bsm[col + 1];
                if (outHi) {
                    uint32_t lo;
                    const uint32_t hi = packsplit(vx, vy, lo);
                    *(uint32_t*)(outHi + (size_t)m * N + gn0 + col) = hi;
                    *(uint32_t*)(outLo + (size_t)m * N + gn0 + col) = lo;
                } else {
                    if (res) {
                        const float2 rv = *(const float2*)(res + (size_t)m * N + gn0 + col);
                        vx += rv.x; vy += rv.y;
                    }
                    float2 v; v.x = vx; v.y = vy;
                    *(float2*)(Cf + (size_t)m * N + gn0 + col) = v;
                }
            }
        }
    }
}

// =====================================================================
// HMMA flash attention (causal, split-bf16, unnormalized exp softmax)
// Grid (T/128, NH, B), 256 threads = 8 warps, warp owns 16 q rows.
// Q 128x64 hi/lo; K/V 64-key tiles, 2-stage cp.async; 2 CTAs/SM.
// =====================================================================
#define SRS 144                     // smem row stride (64 bf16 + 16B pad)
#define ATT_MAT (64*SRS)            // 9216 per matrix (64 rows)
#define ATT_STG (4*ATT_MAT)         // Khi,Klo,Vhi,Vlo = 36864
#define ATT_Q   (128*SRS)           // 18432
#define ATT_SMEM (2*ATT_Q + 2*ATT_STG)   // 110592 -> 2 CTAs/SM

__global__ __launch_bounds__(256, 2)
void flash_mma_kernel(const __nv_bfloat16* __restrict__ QKVhi,
                      const __nv_bfloat16* __restrict__ QKVlo,
                      __nv_bfloat16* __restrict__ Ohi,
                      __nv_bfloat16* __restrict__ Olo)
{
    extern __shared__ __align__(128) char smem[];
    const int tid = threadIdx.x, lane = tid & 31, wid = tid >> 5;
    const int qt = (int)gridDim.x - 1 - (int)blockIdx.x;   // heavy blocks first
    const int q0 = qt * 128;
    const int h = blockIdx.y, b = blockIdx.z;

    const uint32_t sQhi = smem_u32(smem);
    const uint32_t sQlo = sQhi + ATT_Q;
    const uint32_t sKV0 = sQlo + ATT_Q;

    const size_t rowStride = 3 * EE;
    const size_t base = ((size_t)b * TT) * rowStride + (size_t)h * DHH;
    const __nv_bfloat16* Qh = QKVhi + base;
    const __nv_bfloat16* Ql = QKVlo + base;
    const __nv_bfloat16* Kh = Qh + EE;
    const __nv_bfloat16* Kl = Ql + EE;
    const __nv_bfloat16* Vh = Qh + 2 * EE;
    const __nv_bfloat16* Vl = Ql + 2 * EE;

    // ---- Q tile load (128 rows x 8 16B chunks, hi+lo) ----
    for (int i = tid; i < 1024; i += 256) {
        const int row = i >> 3, c = i & 7;
        const size_t g = (size_t)(q0 + row) * rowStride + c * 8;
        cp_async16(sQhi + row * SRS + c * 16, Qh + g);
        cp_async16(sQlo + row * SRS + c * 16, Ql + g);
    }

    auto load_kv = [&](int s, int k0){
        const uint32_t st = sKV0 + s * ATT_STG;
        for (int i = tid; i < 512; i += 256) {
            const int row = i >> 3, c = i & 7;
            const size_t g = (size_t)(k0 + row) * rowStride + c * 8;
            const uint32_t d = st + row * SRS + c * 16;
            cp_async16(d + 0 * ATT_MAT, Kh + g);
            cp_async16(d + 1 * ATT_MAT, Kl + g);
            cp_async16(d + 2 * ATT_MAT, Vh + g);
            cp_async16(d + 3 * ATT_MAT, Vl + g);
        }
    };

    const int nk = 2 * qt + 2;      // 64-key tiles
    load_kv(0, 0);  cp_commit();    // group 0 carries Q too

    float acc_o[8][4];
    #pragma unroll
    for (int i = 0; i < 8; i++)
        #pragma unroll
        for (int j = 0; j < 4; j++) acc_o[i][j] = 0.f;
    float l0 = 0.f, l1 = 0.f;

    const int l15 = lane & 15;
    const uint32_t qOff = (uint32_t)(wid * 16 + l15) * SRS + (uint32_t)(lane >> 4) * 16;
    const uint32_t kRowOff = (uint32_t)((lane & 7) + ((lane >> 4) << 3)) * SRS
                           + (uint32_t)((lane >> 3) & 1) * 16;
    const uint32_t vRowOff = (uint32_t)((lane & 7) + (((lane >> 3) & 1) << 3)) * SRS
                           + (uint32_t)((lane >> 4) & 1) * 16;

    const int limit = q0 + wid * 16 + 15;   // warp's max row

    for (int c = 0; c < nk; c++) {
        cp_wait<0>();
        __syncthreads();
        if (c + 1 < nk) { load_kv((c + 1) & 1, (c + 1) * 64); cp_commit(); }

        const uint32_t Khi_ = sKV0 + (c & 1) * ATT_STG;
        const uint32_t Klo_ = Khi_ + ATT_MAT;
        const uint32_t Vhi_ = Khi_ + 2 * ATT_MAT;
        const uint32_t Vlo_ = Khi_ + 3 * ATT_MAT;
        const int k0 = c * 64;
        const bool needmask = (k0 + 63) > (q0 + wid * 16);

        // ---- S = Q K^T (split bf16) ----
        float sacc[8][4];
        #pragma unroll
        for (int i = 0; i < 8; i++)
            #pragma unroll
            for (int j = 0; j < 4; j++) sacc[i][j] = 0.f;

        #pragma unroll
        for (int kk = 0; kk < 4; kk++) {
            uint32_t qh[4], ql[4];
            ldsm_x4(qh, sQhi + qOff + kk * 32);
            ldsm_x4(ql, sQlo + qOff + kk * 32);
            #pragma unroll
            for (int np = 0; np < 4; np++) {
                if (k0 + np * 16 > limit) break;   // fully masked 16-col tile
                const uint32_t ba = kRowOff + (uint32_t)np * 16 * SRS + kk * 32;
                uint32_t bh[4], bl[4];
                ldsm_x4(bh, Khi_ + ba);
                ldsm_x4(bl, Klo_ + ba);
                #pragma unroll
                for (int t = 0; t < 2; t++) {
                    mma16816(sacc[2 * np + t], qh, &bh[2 * t]);
                    mma16816(sacc[2 * np + t], qh, &bl[2 * t]);
                    mma16816(sacc[2 * np + t], ql, &bh[2 * t]);
                }
            }
        }

        // ---- unnormalized softmax: p = exp(s/8), masked -> 0 ----
        const int rbase = q0 + wid * 16 + (lane >> 2);
        float s0 = 0.f, s1 = 0.f;
        #pragma unroll
        for (int nt = 0; nt < 8; nt++) {
            const int col = k0 + nt * 8 + 2 * (lane & 3);
            if (k0 + (nt >> 1) * 16 > limit) {
                sacc[nt][0] = sacc[nt][1] = sacc[nt][2] = sacc[nt][3] = 0.f;
                continue;
            }
            #pragma unroll
            for (int j = 0; j < 4; j++) {
                float v = sacc[nt][j] * 0.125f;
                bool dead = false;
                if (needmask) {
                    const int cc = col + (j & 1);
                    const int rr = rbase + (j >> 1) * 8;
                    dead = (cc > rr);
                }
                v = dead ? 0.f : __expf(v);
                sacc[nt][j] = v;
            }
            s0 += sacc[nt][0] + sacc[nt][1];
            s1 += sacc[nt][2] + sacc[nt][3];
        }
        s0 += __shfl_xor_sync(0xffffffffu, s0, 1);
        s0 += __shfl_xor_sync(0xffffffffu, s0, 2);
        s1 += __shfl_xor_sync(0xffffffffu, s1, 1);
        s1 += __shfl_xor_sync(0xffffffffu, s1, 2);
        l0 += s0; l1 += s1;

        // ---- O += P V (split P, split V) ----
        #pragma unroll
        for (int kkp = 0; kkp < 4; kkp++) {
            if (k0 + kkp * 16 > limit) break;      // P == 0 for these keys
            uint32_t phi[4], plo[4];
            phi[0] = packsplit(sacc[2*kkp][0],   sacc[2*kkp][1],   plo[0]);
            phi[1] = packsplit(sacc[2*kkp][2],   sacc[2*kkp][3],   plo[1]);
            phi[2] = packsplit(sacc[2*kkp+1][0], sacc[2*kkp+1][1], plo[2]);
            phi[3] = packsplit(sacc[2*kkp+1][2], sacc[2*kkp+1][3], plo[3]);
            #pragma unroll
            for (int np = 0; np < 4; np++) {
                const uint32_t va = (uint32_t)(kkp * 16) * SRS + vRowOff + np * 32;
                uint32_t vh[4], vl[4];
                ldsm_x4_t(vh, Vhi_ + va);
                ldsm_x4_t(vl, Vlo_ + va);
                #pragma unroll
                for (int t = 0; t < 2; t++) {
                    mma16816(acc_o[2 * np + t], phi, &vh[2 * t]);
                    mma16816(acc_o[2 * np + t], phi, &vl[2 * t]);
                    mma16816(acc_o[2 * np + t], plo, &vh[2 * t]);
                }
            }
        }
    }

    // ---- epilogue: O / l, write bf16 hi/lo into GEMM A buffers ----
    const float inv0 = 1.f / l0, inv1 = 1.f / l1;
    const int row0 = b * TT + q0 + wid * 16 + (lane >> 2);
    const int colb = h * DHH + 2 * (lane & 3);
    #pragma unroll
    for (int nt = 0; nt < 8; nt++) {
        const int col = colb + nt * 8;
        uint32_t lo;
        uint32_t hi = packsplit(acc_o[nt][0] * inv0, acc_o[nt][1] * inv0, lo);
        *(uint32_t*)(Ohi + (size_t)row0 * EE + col) = hi;
        *(uint32_t*)(Olo + (size_t)row0 * EE + col) = lo;
        hi = packsplit(acc_o[nt][2] * inv1, acc_o[nt][3] * inv1, lo);
        *(uint32_t*)(Ohi + (size_t)(row0 + 8) * EE + col) = hi;
        *(uint32_t*)(Olo + (size_t)(row0 + 8) * EE + col) = lo;
    }
}

// =====================================================================
// LayerNorm: block per row, 256 threads; optional fp32 + bf16 hi/lo out
// =====================================================================
__global__ __launch_bounds__(256) void layernorm_kernel(
    const float* __restrict__ x, const float* __restrict__ gam,
    const float* __restrict__ bet, float* __restrict__ outF,
    __nv_bfloat16* __restrict__ outHi, __nv_bfloat16* __restrict__ outLo)
{
    const int row = blockIdx.x;
    const int tid = threadIdx.x;
    const float4 xv = *(const float4*)(x + (size_t)row * EE + tid * 4);

    __shared__ float red[8];

    float s = xv.x + xv.y + xv.z + xv.w;
    #pragma unroll
    for (int o = 16; o; o >>= 1) s += __shfl_xor_sync(0xffffffffu, s, o);
    if ((tid & 31) == 0) red[tid >> 5] = s;
    __syncthreads();
    float tot = 0.f;
    #pragma unroll
    for (int i = 0; i < 8; i++) tot += red[i];
    const float mu = tot * (1.0f / (float)EE);
    __syncthreads();

    const float dx = xv.x - mu, dy = xv.y - mu, dz = xv.z - mu, dw = xv.w - mu;
    float ss = dx*dx + dy*dy + dz*dz + dw*dw;
    #pragma unroll
    for (int o = 16; o; o >>= 1) ss += __shfl_xor_sync(0xffffffffu, ss, o);
    if ((tid & 31) == 0) red[tid >> 5] = ss;
    __syncthreads();
    float sst = 0.f;
    #pragma unroll
    for (int i = 0; i < 8; i++) sst += red[i];
    const float inv = rsqrtf(sst * (1.0f / (float)EE) + LN_EPS);

    const float4 gv = *(const float4*)(gam + tid * 4);
    const float4 bv = *(const float4*)(bet + tid * 4);
    float4 ov;
    ov.x = dx * inv * gv.x + bv.x;
    ov.y = dy * inv * gv.y + bv.y;
    ov.z = dz * inv * gv.z + bv.z;
    ov.w = dw * inv * gv.w + bv.w;
    if (outF) *(float4*)(outF + (size_t)row * EE + tid * 4) = ov;
    uint32_t lo0, lo1;
    const uint32_t hi0 = packsplit(ov.x, ov.y, lo0);
    const uint32_t hi1 = packsplit(ov.z, ov.w, lo1);
    uint2 hv; hv.x = hi0; hv.y = hi1;
    uint2 lv; lv.x = lo0; lv.y = lo1;
    *(uint2*)(outHi + (size_t)row * EE + tid * 4) = hv;
    *(uint2*)(outLo + (size_t)row * EE + tid * 4) = lv;
}

// =====================================================================
// Argmax reduce over 16 partials per row + expert histogram (fused)
// =====================================================================
__global__ __launch_bounds__(256) void argmax_reduce_kernel(
    const unsigned long long* __restrict__ part, int* __restrict__ idx,
    int* __restrict__ hist)
{
    const int m = blockIdx.x * 256 + threadIdx.x;
    const unsigned long long* p = part + (size_t)m * 16;
    unsigned long long k = p[0];
    #pragma unroll
    for (int i = 1; i < 16; i++) {
        const unsigned long long v = p[i];
        if (v > k) k = v;
    }
    const int e = dec_argmax(k);
    idx[m] = e;
    atomicAdd(&hist[e], 1);
}

// =====================================================================
// MoE routing: clear-hist / scan / scatter
// =====================================================================
__global__ __launch_bounds__(256) void hist_clear_kernel(int* __restrict__ hist)
{
    hist[blockIdx.x * 256 + threadIdx.x] = 0;
}

__global__ __launch_bounds__(1024) void scan_kernel(
    const int* __restrict__ hist, int* __restrict__ cursor)
{
    __shared__ int warpsum[32];
    const int tid = threadIdx.x;
    const int lane = tid & 31, wid = tid >> 5;
    const int v0 = hist[2 * tid], v1 = hist[2 * tid + 1];
    const int tsum = v0 + v1;
    int x = tsum;
    #pragma unroll
    for (int o = 1; o < 32; o <<= 1) {
        const int y = __shfl_up_sync(0xffffffffu, x, o);
        if (lane >= o) x += y;
    }
    if (lane == 31) warpsum[wid] = x;
    __syncthreads();
    if (wid == 0) {
        int w = warpsum[lane];
        #pragma unroll
        for (int o = 1; o < 32; o <<= 1) {
            const int y = __shfl_up_sync(0xffffffffu, w, o);
            if (lane >= o) w += y;
        }
        warpsum[lane] = w;
    }
    __syncthreads();
    const int base = (wid > 0 ? warpsum[wid - 1] : 0) + (x - tsum);
    cursor[2 * tid] = base;
    cursor[2 * tid + 1] = base + v0;
}

__global__ __launch_bounds__(256) void scatter_kernel(
    const int* __restrict__ idx, int* __restrict__ cursor,
    int* __restrict__ perm)
{
    const int t = blockIdx.x * 256 + threadIdx.x;
    const int pos = atomicAdd(&cursor[idx[t]], 1);
    perm[pos] = t;
}

// =====================================================================
// MoE: one block per (expert-sorted) token, float4-vectorized
// =====================================================================
__global__ __launch_bounds__(256) void moe_kernel(
    const float* __restrict__ h, const int* __restrict__ idx,
    const int* __restrict__ perm,
    const float* __restrict__ w1, const float* __restrict__ b1,
    const float* __restrict__ w2, const float* __restrict__ b2,
    float* __restrict__ out)
{
    const int token = perm[blockIdx.x];
    const int tid = threadIdx.x;
    const int e = idx[token];

    __shared__ float xs[EE];
    __shared__ float partial[HIDD][17];
    __shared__ float hm[HIDD];

    // xs load: one float4 per thread (EE/4 == 256)
    const float* hrow = h + (size_t)token * EE;
    ((float4*)xs)[tid] = ((const float4*)hrow)[tid];
    __syncthreads();

    const int hcol = tid & 15;
    const int grp  = tid >> 4;
    const float* w1p = w1 + (size_t)e * EE * HIDD;
    float acc = 0.f;
    for (int i = grp; i < EE; i += 16)
        acc += xs[i] * w1p[(size_t)i * HIDD + hcol];
    partial[hcol][grp] = acc;
    __syncthreads();

    if (tid < HIDD) {
        float s = b1[(size_t)e * HIDD + tid];
        #pragma unroll
        for (int g2 = 0; g2 < 16; g2++) s += partial[tid][g2];
        hm[tid] = 0.5f * s * (1.0f + erff(s * 0.70710678118654752f));
    }
    __syncthreads();

    float hreg[HIDD];
    #pragma unroll
    for (int k = 0; k < HIDD; k++) hreg[k] = hm[k];

    // w2 pass: each thread owns 4 contiguous columns (float4 everywhere)
    const float* w2p = w2 + (size_t)e * HIDD * EE;
    const float* b2p = b2 + (size_t)e * EE;
    float* orow = out + (size_t)token * EE;
    const int j4 = tid * 4;
    float4 s4 = *(const float4*)(b2p + j4);
    #pragma unroll
    for (int k = 0; k < HIDD; k++) {
        const float4 wv = *(const float4*)(w2p + (size_t)k * EE + j4);
        s4.x += hreg[k] * wv.x;
        s4.y += hreg[k] * wv.y;
        s4.z += hreg[k] * wv.z;
        s4.w += hreg[k] * wv.w;
    }
    float4 ov = *(const float4*)(orow + j4);
    ov.x += s4.x; ov.y += s4.y; ov.z += s4.z; ov.w += s4.w;
    *(float4*)(orow + j4) = ov;
}

// =====================================================================
// launch
// =====================================================================
extern "C" void kernel_launch(void* const* d_in, const int* in_sizes, int n_in,
                              void* d_out, int out_size)
{
    const float* x      = (const float*)d_in[0];
    const float* ln1_g  = (const float*)d_in[1];
    const float* ln1_b  = (const float*)d_in[2];
    const float* ln2_g  = (const float*)d_in[3];
    const float* ln2_b  = (const float*)d_in[4];
    const float* qkv_w  = (const float*)d_in[5];
    const float* qkv_b  = (const float*)d_in[6];
    const float* proj_w = (const float*)d_in[7];
    const float* proj_b = (const float*)d_in[8];
    const float* gate_w = (const float*)d_in[9];
    const float* gate_b = (const float*)d_in[10];
    const float* w1     = (const float*)d_in[11];
    const float* b1     = (const float*)d_in[12];
    const float* w2     = (const float*)d_in[13];
    const float* w2b    = (const float*)d_in[14];
    float* out = (float*)d_out;

    void *p_h, *p_part, *p_idx, *p_hist, *p_cur, *p_perm,
         *p_ah, *p_al, *p_bh, *p_bl, *p_qh, *p_ql;
    cudaGetSymbolAddress(&p_h, g_h);
    cudaGetSymbolAddress(&p_part, g_part);
    cudaGetSymbolAddress(&p_idx, g_idx);
    cudaGetSymbolAddress(&p_hist, g_hist);
    cudaGetSymbolAddress(&p_cur, g_cursor);
    cudaGetSymbolAddress(&p_perm, g_perm);
    cudaGetSymbolAddress(&p_ah, g_Ahi);
    cudaGetSymbolAddress(&p_al, g_Alo);
    cudaGetSymbolAddress(&p_bh, g_Bhi);
    cudaGetSymbolAddress(&p_bl, g_Blo);
    cudaGetSymbolAddress(&p_qh, g_QKVhi);
    cudaGetSymbolAddress(&p_ql, g_QKVlo);
    float* bh      = (float*)p_h;
    unsigned long long* bpart = (unsigned long long*)p_part;
    int*   bidx    = (int*)p_idx;
    int*   hist    = (int*)p_hist;
    int*   cursor  = (int*)p_cur;
    int*   perm    = (int*)p_perm;
    __nv_bfloat16* Ahi = (__nv_bfloat16*)p_ah;
    __nv_bfloat16* Alo = (__nv_bfloat16*)p_al;
    __nv_bfloat16* Bhi = (__nv_bfloat16*)p_bh;
    __nv_bfloat16* Blo = (__nv_bfloat16*)p_bl;
    __nv_bfloat16* QKVhi = (__nv_bfloat16*)p_qh;
    __nv_bfloat16* QKVlo = (__nv_bfloat16*)p_ql;

    cudaFuncSetAttribute(gemm_tc, cudaFuncAttributeMaxDynamicSharedMemorySize, GEMM_SMEM);
    cudaFuncSetAttribute(flash_mma_kernel, cudaFuncAttributeMaxDynamicSharedMemorySize, ATT_SMEM);

    // 1) LN1(x) -> bf16 hi/lo A operand
    layernorm_kernel<<<MTOK, 256>>>(x, ln1_g, ln1_b, nullptr, Ahi, Alo);

    // 2) qkv = h @ qkv_w + qkv_b -> bf16 hi/lo qkv buffers
    convW_kernel<<<dim3(3*EE/64, EE/64), 256>>>(qkv_w, Bhi, Blo, 3*EE, EE);
    gemm_tc<<<dim3(3*EE/128, MTOK/128), 256, GEMM_SMEM>>>(
        Ahi, Alo, Bhi, Blo, qkv_b, nullptr, nullptr, QKVhi, QKVlo, nullptr, 3*EE, EE);

    // 3) attention -> bf16 hi/lo into A operand buffers
    flash_mma_kernel<<<dim3(TT/128, NHH, BB), 256, ATT_SMEM>>>(QKVhi, QKVlo, Ahi, Alo);

    // 4) xmid = x + attn @ proj_w + proj_b -> d_out (fp32)
    convW_kernel<<<dim3(EE/64, EE/64), 256>>>(proj_w, Bhi, Blo, EE, EE);
    gemm_tc<<<dim3(EE/128, MTOK/128), 256, GEMM_SMEM>>>(
        Ahi, Alo, Bhi, Blo, proj_b, x, out, nullptr, nullptr, nullptr, EE, EE);

    // 5) LN2 -> fp32 (MoE) + bf16 hi/lo (gate GEMM)
    layernorm_kernel<<<MTOK, 256>>>(out, ln2_g, ln2_b, bh, Ahi, Alo);

    // 6) gate GEMM with fused argmax partials (no logits materialization)
    hist_clear_kernel<<<NEE/256, 256>>>(hist);
    convW_kernel<<<dim3(NEE/64, EE/64), 256>>>(gate_w, Bhi, Blo, NEE, EE);
    gemm_tc<<<dim3(NEE/128, MTOK/128), 256, GEMM_SMEM>>>(
        Ahi, Alo, Bhi, Blo, gate_b, nullptr, nullptr, nullptr, nullptr, bpart, NEE, EE);

    // 7) idx + hist (fused); scan -> cursor; scatter -> perm
    argmax_reduce_kernel<<<MTOK/256, 256>>>(bpart, bidx, hist);
    scan_kernel<<<1, 1024>>>(hist, cursor);
    scatter_kernel<<<MTOK/256, 256>>>(bidx, cursor, perm);

    // 8) d_out += moe(h, idx) over expert-sorted tokens (block per token)
    moe_kernel<<<MTOK, 256>>>(bh, bidx, perm, w1, b1, w2, w2b, out);
}

// round 13
// speedup vs baseline: 1.0845x; 1.0502x over previous
#include <cuda_runtime.h>
#include <cuda_bf16.h>
#include <math.h>
#include <stdint.h>

// ---------------- problem constants ----------------
#define BB 4
#define TT 2048
#define EE 1024
#define NHH 16
#define DHH 64
#define NEE 2048
#define HIDD 16
#define MTOK (BB*TT)          // 8192 tokens
#define LN_EPS 1e-5f

// ---------------- scratch (device globals; no runtime allocation) ----------
__device__ float g_h[MTOK * EE];          // LN2 output fp32 (for MoE)
__device__ unsigned long long g_part[MTOK * 16];  // per-(row, bn-tile) argmax partials
__device__ int   g_idx[MTOK];             // argmax expert per token
__device__ int   g_hist[NEE];
__device__ int   g_cursor[NEE];
__device__ int   g_perm[MTOK];
__device__ __nv_bfloat16 g_Ahi[MTOK * EE];       // GEMM A operand hi [M,K]
__device__ __nv_bfloat16 g_Alo[MTOK * EE];
__device__ __nv_bfloat16 g_Bhi[3 * EE * EE];     // weights transposed [N,K]
__device__ __nv_bfloat16 g_Blo[3 * EE * EE];
__device__ __nv_bfloat16 g_QKVhi[MTOK * 3 * EE]; // qkv bf16 hi/lo
__device__ __nv_bfloat16 g_QKVlo[MTOK * 3 * EE];

// =====================================================================
// PTX helpers (family-portable: cp.async / ldmatrix / mma.sync only)
// =====================================================================
__device__ __forceinline__ uint32_t smem_u32(const void* p){
    uint32_t a;
    asm("{ .reg .u64 t; cvta.to.shared.u64 t, %1; cvt.u32.u64 %0, t; }"
        : "=r"(a) : "l"(p));
    return a;
}
__device__ __forceinline__ void cp_async16(uint32_t dst, const void* src){
    asm volatile("cp.async.cg.shared.global [%0], [%1], 16;"
        :: "r"(dst), "l"(src));
}
__device__ __forceinline__ void cp_commit(){
    asm volatile("cp.async.commit_group;");
}
template<int N> __device__ __forceinline__ void cp_wait(){
    asm volatile("cp.async.wait_group %0;" :: "n"(N));
}
__device__ __forceinline__ void ldsm_x4(uint32_t* r, uint32_t a){
    asm volatile("ldmatrix.sync.aligned.m8n8.x4.shared.b16 {%0,%1,%2,%3}, [%4];"
        : "=r"(r[0]), "=r"(r[1]), "=r"(r[2]), "=r"(r[3]) : "r"(a));
}
__device__ __forceinline__ void ldsm_x4_t(uint32_t* r, uint32_t a){
    asm volatile("ldmatrix.sync.aligned.m8n8.x4.trans.shared.b16 {%0,%1,%2,%3}, [%4];"
        : "=r"(r[0]), "=r"(r[1]), "=r"(r[2]), "=r"(r[3]) : "r"(a));
}
__device__ __forceinline__ void mma16816(float* d, const uint32_t* a, const uint32_t* b){
    asm volatile(
        "mma.sync.aligned.m16n8k16.row.col.f32.bf16.bf16.f32 "
        "{%0,%1,%2,%3}, {%4,%5,%6,%7}, {%8,%9}, {%0,%1,%2,%3};"
        : "+f"(d[0]), "+f"(d[1]), "+f"(d[2]), "+f"(d[3])
        : "r"(a[0]), "r"(a[1]), "r"(a[2]), "r"(a[3]), "r"(b[0]), "r"(b[1]));
}
__device__ __forceinline__ uint32_t packsplit(float x, float y, uint32_t& lo){
    __nv_bfloat162 h = __floats2bfloat162_rn(x, y);
    __nv_bfloat162 l = __floats2bfloat162_rn(x - __bfloat162float(h.x),
                                             y - __bfloat162float(h.y));
    lo = *(uint32_t*)&l;
    return *(uint32_t*)&h;
}
// monotone encoding of (float value, col) for argmax-with-first-tiebreak
__device__ __forceinline__ unsigned long long enc_argmax(float v, int col){
    uint32_t u = __float_as_uint(v);
    u = (u & 0x80000000u) ? ~u : (u | 0x80000000u);
    return ((unsigned long long)u << 32) | (uint32_t)(~col);
}
__device__ __forceinline__ int dec_argmax(unsigned long long k){
    return (int)(~(uint32_t)k);
}

// =====================================================================
// Weights: fp32 W[K,N] -> transposed bf16 hi/lo [N,K]
// =====================================================================
__global__ __launch_bounds__(256) void convW_kernel(
    const float* __restrict__ W, __nv_bfloat16* __restrict__ hi,
    __nv_bfloat16* __restrict__ lo, int N, int K)
{
    __shared__ float tile[64][65];
    const int k0 = blockIdx.y * 64;
    const int n0 = blockIdx.x * 64;
    for (int i = threadIdx.x; i < 4096; i += 256) {
        const int r = i >> 6, c = i & 63;
        tile[r][c] = W[(size_t)(k0 + r) * N + n0 + c];
    }
    __syncthreads();
    for (int i = threadIdx.x; i < 4096; i += 256) {
        const int r = i >> 6, c = i & 63;
        const float v = tile[c][r];
        const __nv_bfloat16 h = __float2bfloat16(v);
        const __nv_bfloat16 l = __float2bfloat16(v - __bfloat162float(h));
        const size_t o = (size_t)(n0 + r) * K + k0 + c;
        hi[o] = h;
        lo[o] = l;
    }
}

// =====================================================================
// split-bf16 HMMA GEMM: C[M,N] = A[M,K] @ W[K,N] + bias (+ res)
// CTA 128x128, BK=32, 2-stage cp.async, 2 CTAs/SM, 8 warps (2x4),
// warp tile 64x32, term-major MMA ordering, A-fragment double buffer.
// Epilogue: fp32 (Cf) / bf16 hi-lo (outHi/outLo) / argmax partials (part)
// =====================================================================
#define RS 80                      // smem row stride bytes (40 bf16)
#define MATB (128*RS)              // 10240 B per matrix tile
#define STGB (4*MATB)              // 40960 B per stage
#define GEMM_SMEM (512 + 2*STGB)   // bias + 2 stages = 82432 -> 2 CTAs/SM

__global__ __launch_bounds__(256, 2)
void gemm_tc(const __nv_bfloat16* __restrict__ Ahi, const __nv_bfloat16* __restrict__ Alo,
             const __nv_bfloat16* __restrict__ Bhi, const __nv_bfloat16* __restrict__ Blo,
             const float* __restrict__ bias, const float* __restrict__ res,
             float* __restrict__ Cf,
             __nv_bfloat16* __restrict__ outHi, __nv_bfloat16* __restrict__ outLo,
             unsigned long long* __restrict__ part,
             int N, int K)
{
    extern __shared__ __align__(128) char smem[];
    const int tid = threadIdx.x;
    const int lane = tid & 31, wid = tid >> 5;
    const int warp_m = wid & 1, warp_n = wid >> 1;     // 2 x 4
    const int bn = blockIdx.x, bm = blockIdx.y;
    const uint32_t sb = smem_u32(smem);
    float* bsm = (float*)smem;

    if (tid < 128) bsm[tid] = bias[bn * 128 + tid];

    const __nv_bfloat16* gA[2] = { Ahi + (size_t)bm * 128 * K,
                                   Alo + (size_t)bm * 128 * K };
    const __nv_bfloat16* gB[2] = { Bhi + (size_t)bn * 128 * K,
                                   Blo + (size_t)bn * 128 * K };

    const int r0 = tid >> 2, c0 = tid & 3;
    const int r1 = r0 + 64;

    auto load_stage = [&](int s, int k0){
        const uint32_t st = sb + 512 + s * STGB;
        #pragma unroll
        for (int m = 0; m < 2; m++) {
            const __nv_bfloat16* src = gA[m] + k0;
            const uint32_t d = st + m * MATB;
            cp_async16(d + r0 * RS + c0 * 16, src + (size_t)r0 * K + c0 * 8);
            cp_async16(d + r1 * RS + c0 * 16, src + (size_t)r1 * K + c0 * 8);
        }
        #pragma unroll
        for (int m = 0; m < 2; m++) {
            const __nv_bfloat16* src = gB[m] + k0;
            const uint32_t d = st + (2 + m) * MATB;
            cp_async16(d + r0 * RS + c0 * 16, src + (size_t)r0 * K + c0 * 8);
            cp_async16(d + r1 * RS + c0 * 16, src + (size_t)r1 * K + c0 * 8);
        }
    };

    float acc[4][4][4];
    #pragma unroll
    for (int i = 0; i < 4; i++)
        #pragma unroll
        for (int j = 0; j < 4; j++)
            #pragma unroll
            for (int t = 0; t < 4; t++) acc[i][j][t] = 0.f;

    const int nk = K >> 5;
    load_stage(0, 0);  cp_commit();
    load_stage(1, 32); cp_commit();

    const int l15 = lane & 15;
    const uint32_t aRowOff = (uint32_t)(warp_m * 64 + l15) * RS + (uint32_t)(lane >> 4) * 16;
    const uint32_t bRowOff = (uint32_t)(warp_n * 32 + (lane & 7) + ((lane >> 4) << 3)) * RS
                           + (uint32_t)((lane >> 3) & 1) * 16;

    for (int c = 0; c < nk; c++) {
        if (c == nk - 1) cp_wait<0>(); else cp_wait<1>();
        __syncthreads();

        const uint32_t st = sb + 512 + (c & 1) * STGB;
        #pragma unroll
        for (int kk = 0; kk < 2; kk++) {
            uint32_t bh[2][4], bl[2][4];
            #pragma unroll
            for (int np = 0; np < 2; np++) {
                const uint32_t ba = st + bRowOff + (uint32_t)np * 16 * RS + kk * 32;
                ldsm_x4(bh[np], ba + 2 * MATB);
                ldsm_x4(bl[np], ba + 3 * MATB);
            }
            // A-fragment double buffer: prefetch mt+1 while issuing mt's MMAs
            uint32_t ah[2][4], al[2][4];
            {
                const uint32_t aa0 = st + aRowOff + kk * 32;
                ldsm_x4(ah[0], aa0);
                ldsm_x4(al[0], aa0 + MATB);
            }
            #pragma unroll
            for (int mt = 0; mt < 4; mt++) {
                const int cur = mt & 1, nxt = cur ^ 1;
                if (mt < 3) {
                    const uint32_t aa = st + aRowOff + (uint32_t)(mt + 1) * 16 * RS + kk * 32;
                    ldsm_x4(ah[nxt], aa);
                    ldsm_x4(al[nxt], aa + MATB);
                }
                // term-major: 4 independent accs between same-acc MMAs
                #pragma unroll
                for (int nt = 0; nt < 4; nt++)
                    mma16816(acc[mt][nt], ah[cur], &bh[nt >> 1][(nt & 1) * 2]);
                #pragma unroll
                for (int nt = 0; nt < 4; nt++)
                    mma16816(acc[mt][nt], ah[cur], &bl[nt >> 1][(nt & 1) * 2]);
                #pragma unroll
                for (int nt = 0; nt < 4; nt++)
                    mma16816(acc[mt][nt], al[cur], &bh[nt >> 1][(nt & 1) * 2]);
            }
        }
        __syncthreads();
        if (c + 2 < nk) { load_stage(c & 1, (c + 2) * 32); cp_commit(); }
    }

    const int mBase = bm * 128 + warp_m * 64;
    const int nBase = warp_n * 32;
    const int gn0 = bn * 128;

    if (part) {
        // fused argmax partials (gate GEMM): smem two-level reduce, no atomics
        unsigned long long* psm = (unsigned long long*)(smem + 512);  // [128][4]
        #pragma unroll
        for (int mt = 0; mt < 4; mt++) {
            #pragma unroll
            for (int hh = 0; hh < 2; hh++) {
                const int rloc = warp_m * 64 + mt * 16 + (lane >> 2) + hh * 8;
                float bestv = -3.4e38f; int bestc = 0;
                #pragma unroll
                for (int nt = 0; nt < 4; nt++) {
                    const int lc = nBase + nt * 8 + (lane & 3) * 2;
                    const float vx = acc[mt][nt][hh * 2 + 0] + bsm[lc];
                    const float vy = acc[mt][nt][hh * 2 + 1] + bsm[lc + 1];
                    if (vx > bestv) { bestv = vx; bestc = gn0 + lc; }
                    if (vy > bestv) { bestv = vy; bestc = gn0 + lc + 1; }
                }
                unsigned long long key = enc_argmax(bestv, bestc);
                unsigned long long o1 = __shfl_xor_sync(0xffffffffu, key, 1);
                if (o1 > key) key = o1;
                unsigned long long o2 = __shfl_xor_sync(0xffffffffu, key, 2);
                if (o2 > key) key = o2;
                if ((lane & 3) == 0) psm[rloc * 4 + warp_n] = key;
            }
        }
        __syncthreads();
        if (tid < 128) {
            unsigned long long k = psm[tid * 4 + 0];
            unsigned long long t1 = psm[tid * 4 + 1]; if (t1 > k) k = t1;
            unsigned long long t2 = psm[tid * 4 + 2]; if (t2 > k) k = t2;
            unsigned long long t3 = psm[tid * 4 + 3]; if (t3 > k) k = t3;
            part[(size_t)(bm * 128 + tid) * 16 + bn] = k;
        }
        return;
    }

    #pragma unroll
    for (int mt = 0; mt < 4; mt++) {
        #pragma unroll
        for (int nt = 0; nt < 4; nt++) {
            const int row = mBase + mt * 16 + (lane >> 2);
            const int col = nBase + nt * 8 + (lane & 3) * 2;
            #pragma unroll
            for (int hh = 0; hh < 2; hh++) {
                const int m = row + hh * 8;
                float vx = acc[mt][nt][hh * 2 + 0] + bsm[col];
                float vy = acc[mt][nt][hh * 2 + 1] + bsm[col + 1];
                if (outHi) {
                    uint32_t lo;
                    const uint32_t hi = packsplit(vx, vy, lo);
                    *(uint32_t*)(outHi + (size_t)m * N + gn0 + col) = hi;
                    *(uint32_t*)(outLo + (size_t)m * N + gn0 + col) = lo;
                } else {
                    if (res) {
                        const float2 rv = *(const float2*)(res + (size_t)m * N + gn0 + col);
                        vx += rv.x; vy += rv.y;
                    }
                    float2 v; v.x = vx; v.y = vy;
                    *(float2*)(Cf + (size_t)m * N + gn0 + col) = v;
                }
            }
        }
    }
}

// =====================================================================
// HMMA flash attention (causal, split-bf16, unnormalized exp softmax)
// Grid (T/128, NH, B), 256 threads = 8 warps, warp owns 16 q rows.
// Q 128x64 hi/lo; K/V 64-key tiles, 2-stage cp.async; 2 CTAs/SM.
// =====================================================================
#define SRS 144                     // smem row stride (64 bf16 + 16B pad)
#define ATT_MAT (64*SRS)            // 9216 per matrix (64 rows)
#define ATT_STG (4*ATT_MAT)         // Khi,Klo,Vhi,Vlo = 36864
#define ATT_Q   (128*SRS)           // 18432
#define ATT_SMEM (2*ATT_Q + 2*ATT_STG)   // 110592 -> 2 CTAs/SM

__global__ __launch_bounds__(256, 2)
void flash_mma_kernel(const __nv_bfloat16* __restrict__ QKVhi,
                      const __nv_bfloat16* __restrict__ QKVlo,
                      __nv_bfloat16* __restrict__ Ohi,
                      __nv_bfloat16* __restrict__ Olo)
{
    extern __shared__ __align__(128) char smem[];
    const int tid = threadIdx.x, lane = tid & 31, wid = tid >> 5;
    const int qt = (int)gridDim.x - 1 - (int)blockIdx.x;   // heavy blocks first
    const int q0 = qt * 128;
    const int h = blockIdx.y, b = blockIdx.z;

    const uint32_t sQhi = smem_u32(smem);
    const uint32_t sQlo = sQhi + ATT_Q;
    const uint32_t sKV0 = sQlo + ATT_Q;

    const size_t rowStride = 3 * EE;
    const size_t base = ((size_t)b * TT) * rowStride + (size_t)h * DHH;
    const __nv_bfloat16* Qh = QKVhi + base;
    const __nv_bfloat16* Ql = QKVlo + base;
    const __nv_bfloat16* Kh = Qh + EE;
    const __nv_bfloat16* Kl = Ql + EE;
    const __nv_bfloat16* Vh = Qh + 2 * EE;
    const __nv_bfloat16* Vl = Ql + 2 * EE;

    // ---- Q tile load (128 rows x 8 16B chunks, hi+lo) ----
    for (int i = tid; i < 1024; i += 256) {
        const int row = i >> 3, c = i & 7;
        const size_t g = (size_t)(q0 + row) * rowStride + c * 8;
        cp_async16(sQhi + row * SRS + c * 16, Qh + g);
        cp_async16(sQlo + row * SRS + c * 16, Ql + g);
    }

    auto load_kv = [&](int s, int k0){
        const uint32_t st = sKV0 + s * ATT_STG;
        for (int i = tid; i < 512; i += 256) {
            const int row = i >> 3, c = i & 7;
            const size_t g = (size_t)(k0 + row) * rowStride + c * 8;
            const uint32_t d = st + row * SRS + c * 16;
            cp_async16(d + 0 * ATT_MAT, Kh + g);
            cp_async16(d + 1 * ATT_MAT, Kl + g);
            cp_async16(d + 2 * ATT_MAT, Vh + g);
            cp_async16(d + 3 * ATT_MAT, Vl + g);
        }
    };

    const int nk = 2 * qt + 2;      // 64-key tiles
    load_kv(0, 0);  cp_commit();    // group 0 carries Q too

    float acc_o[8][4];
    #pragma unroll
    for (int i = 0; i < 8; i++)
        #pragma unroll
        for (int j = 0; j < 4; j++) acc_o[i][j] = 0.f;
    float l0 = 0.f, l1 = 0.f;

    const int l15 = lane & 15;
    const uint32_t qOff = (uint32_t)(wid * 16 + l15) * SRS + (uint32_t)(lane >> 4) * 16;
    const uint32_t kRowOff = (uint32_t)((lane & 7) + ((lane >> 4) << 3)) * SRS
                           + (uint32_t)((lane >> 3) & 1) * 16;
    const uint32_t vRowOff = (uint32_t)((lane & 7) + (((lane >> 3) & 1) << 3)) * SRS
                           + (uint32_t)((lane >> 4) & 1) * 16;

    const int limit = q0 + wid * 16 + 15;   // warp's max row

    for (int c = 0; c < nk; c++) {
        cp_wait<0>();
        __syncthreads();
        if (c + 1 < nk) { load_kv((c + 1) & 1, (c + 1) * 64); cp_commit(); }

        const uint32_t Khi_ = sKV0 + (c & 1) * ATT_STG;
        const uint32_t Klo_ = Khi_ + ATT_MAT;
        const uint32_t Vhi_ = Khi_ + 2 * ATT_MAT;
        const uint32_t Vlo_ = Khi_ + 3 * ATT_MAT;
        const int k0 = c * 64;
        const bool needmask = (k0 + 63) > (q0 + wid * 16);

        // ---- S = Q K^T (split bf16) ----
        float sacc[8][4];
        #pragma unroll
        for (int i = 0; i < 8; i++)
            #pragma unroll
            for (int j = 0; j < 4; j++) sacc[i][j] = 0.f;

        #pragma unroll
        for (int kk = 0; kk < 4; kk++) {
            uint32_t qh[4], ql[4];
            ldsm_x4(qh, sQhi + qOff + kk * 32);
            ldsm_x4(ql, sQlo + qOff + kk * 32);
            #pragma unroll
            for (int np = 0; np < 4; np++) {
                if (k0 + np * 16 > limit) break;   // fully masked 16-col tile
                const uint32_t ba = kRowOff + (uint32_t)np * 16 * SRS + kk * 32;
                uint32_t bh[4], bl[4];
                ldsm_x4(bh, Khi_ + ba);
                ldsm_x4(bl, Klo_ + ba);
                #pragma unroll
                for (int t = 0; t < 2; t++) {
                    mma16816(sacc[2 * np + t], qh, &bh[2 * t]);
                    mma16816(sacc[2 * np + t], qh, &bl[2 * t]);
                    mma16816(sacc[2 * np + t], ql, &bh[2 * t]);
                }
            }
        }

        // ---- unnormalized softmax: p = exp(s/8), masked -> 0 ----
        const int rbase = q0 + wid * 16 + (lane >> 2);
        float s0 = 0.f, s1 = 0.f;
        #pragma unroll
        for (int nt = 0; nt < 8; nt++) {
            const int col = k0 + nt * 8 + 2 * (lane & 3);
            if (k0 + (nt >> 1) * 16 > limit) {
                sacc[nt][0] = sacc[nt][1] = sacc[nt][2] = sacc[nt][3] = 0.f;
                continue;
            }
            #pragma unroll
            for (int j = 0; j < 4; j++) {
                float v = sacc[nt][j] * 0.125f;
                bool dead = false;
                if (needmask) {
                    const int cc = col + (j & 1);
                    const int rr = rbase + (j >> 1) * 8;
                    dead = (cc > rr);
                }
                v = dead ? 0.f : __expf(v);
                sacc[nt][j] = v;
            }
            s0 += sacc[nt][0] + sacc[nt][1];
            s1 += sacc[nt][2] + sacc[nt][3];
        }
        s0 += __shfl_xor_sync(0xffffffffu, s0, 1);
        s0 += __shfl_xor_sync(0xffffffffu, s0, 2);
        s1 += __shfl_xor_sync(0xffffffffu, s1, 1);
        s1 += __shfl_xor_sync(0xffffffffu, s1, 2);
        l0 += s0; l1 += s1;

        // ---- O += P V (split P, split V) ----
        #pragma unroll
        for (int kkp = 0; kkp < 4; kkp++) {
            if (k0 + kkp * 16 > limit) break;      // P == 0 for these keys
            uint32_t phi[4], plo[4];
            phi[0] = packsplit(sacc[2*kkp][0],   sacc[2*kkp][1],   plo[0]);
            phi[1] = packsplit(sacc[2*kkp][2],   sacc[2*kkp][3],   plo[1]);
            phi[2] = packsplit(sacc[2*kkp+1][0], sacc[2*kkp+1][1], plo[2]);
            phi[3] = packsplit(sacc[2*kkp+1][2], sacc[2*kkp+1][3], plo[3]);
            #pragma unroll
            for (int np = 0; np < 4; np++) {
                const uint32_t va = (uint32_t)(kkp * 16) * SRS + vRowOff + np * 32;
                uint32_t vh[4], vl[4];
                ldsm_x4_t(vh, Vhi_ + va);
                ldsm_x4_t(vl, Vlo_ + va);
                #pragma unroll
                for (int t = 0; t < 2; t++) {
                    mma16816(acc_o[2 * np + t], phi, &vh[2 * t]);
                    mma16816(acc_o[2 * np + t], phi, &vl[2 * t]);
                    mma16816(acc_o[2 * np + t], plo, &vh[2 * t]);
                }
            }
        }
    }

    // ---- epilogue: O / l, write bf16 hi/lo into GEMM A buffers ----
    const float inv0 = 1.f / l0, inv1 = 1.f / l1;
    const int row0 = b * TT + q0 + wid * 16 + (lane >> 2);
    const int colb = h * DHH + 2 * (lane & 3);
    #pragma unroll
    for (int nt = 0; nt < 8; nt++) {
        const int col = colb + nt * 8;
        uint32_t lo;
        uint32_t hi = packsplit(acc_o[nt][0] * inv0, acc_o[nt][1] * inv0, lo);
        *(uint32_t*)(Ohi + (size_t)row0 * EE + col) = hi;
        *(uint32_t*)(Olo + (size_t)row0 * EE + col) = lo;
        hi = packsplit(acc_o[nt][2] * inv1, acc_o[nt][3] * inv1, lo);
        *(uint32_t*)(Ohi + (size_t)(row0 + 8) * EE + col) = hi;
        *(uint32_t*)(Olo + (size_t)(row0 + 8) * EE + col) = lo;
    }
}

// =====================================================================
// LayerNorm: block per row, 256 threads; optional fp32 + bf16 hi/lo out
// =====================================================================
__global__ __launch_bounds__(256) void layernorm_kernel(
    const float* __restrict__ x, const float* __restrict__ gam,
    const float* __restrict__ bet, float* __restrict__ outF,
    __nv_bfloat16* __restrict__ outHi, __nv_bfloat16* __restrict__ outLo)
{
    const int row = blockIdx.x;
    const int tid = threadIdx.x;
    const float4 xv = *(const float4*)(x + (size_t)row * EE + tid * 4);

    __shared__ float red[8];

    float s = xv.x + xv.y + xv.z + xv.w;
    #pragma unroll
    for (int o = 16; o; o >>= 1) s += __shfl_xor_sync(0xffffffffu, s, o);
    if ((tid & 31) == 0) red[tid >> 5] = s;
    __syncthreads();
    float tot = 0.f;
    #pragma unroll
    for (int i = 0; i < 8; i++) tot += red[i];
    const float mu = tot * (1.0f / (float)EE);
    __syncthreads();

    const float dx = xv.x - mu, dy = xv.y - mu, dz = xv.z - mu, dw = xv.w - mu;
    float ss = dx*dx + dy*dy + dz*dz + dw*dw;
    #pragma unroll
    for (int o = 16; o; o >>= 1) ss += __shfl_xor_sync(0xffffffffu, ss, o);
    if ((tid & 31) == 0) red[tid >> 5] = ss;
    __syncthreads();
    float sst = 0.f;
    #pragma unroll
    for (int i = 0; i < 8; i++) sst += red[i];
    const float inv = rsqrtf(sst * (1.0f / (float)EE) + LN_EPS);

    const float4 gv = *(const float4*)(gam + tid * 4);
    const float4 bv = *(const float4*)(bet + tid * 4);
    float4 ov;
    ov.x = dx * inv * gv.x + bv.x;
    ov.y = dy * inv * gv.y + bv.y;
    ov.z = dz * inv * gv.z + bv.z;
    ov.w = dw * inv * gv.w + bv.w;
    if (outF) *(float4*)(outF + (size_t)row * EE + tid * 4) = ov;
    uint32_t lo0, lo1;
    const uint32_t hi0 = packsplit(ov.x, ov.y, lo0);
    const uint32_t hi1 = packsplit(ov.z, ov.w, lo1);
    uint2 hv; hv.x = hi0; hv.y = hi1;
    uint2 lv; lv.x = lo0; lv.y = lo1;
    *(uint2*)(outHi + (size_t)row * EE + tid * 4) = hv;
    *(uint2*)(outLo + (size_t)row * EE + tid * 4) = lv;
}

// =====================================================================
// Argmax reduce over 16 partials per row
// =====================================================================
__global__ __launch_bounds__(256) void argmax_reduce_kernel(
    const unsigned long long* __restrict__ part, int* __restrict__ idx)
{
    const int m = blockIdx.x * 256 + threadIdx.x;
    const unsigned long long* p = part + (size_t)m * 16;
    unsigned long long k = p[0];
    #pragma unroll
    for (int i = 1; i < 16; i++) {
        const unsigned long long v = p[i];
        if (v > k) k = v;
    }
    idx[m] = dec_argmax(k);
}

// =====================================================================
// MoE routing: clear-hist / hist / scan / scatter (from g_idx)
// =====================================================================
__global__ __launch_bounds__(256) void hist_clear_kernel(int* __restrict__ hist)
{
    hist[blockIdx.x * 256 + threadIdx.x] = 0;
}

__global__ __launch_bounds__(256) void hist_kernel(
    const int* __restrict__ idx, int* __restrict__ hist)
{
    const int t = blockIdx.x * 256 + threadIdx.x;
    atomicAdd(&hist[idx[t]], 1);
}

__global__ __launch_bounds__(1024) void scan_kernel(
    const int* __restrict__ hist, int* __restrict__ cursor)
{
    __shared__ int warpsum[32];
    const int tid = threadIdx.x;
    const int lane = tid & 31, wid = tid >> 5;
    const int v0 = hist[2 * tid], v1 = hist[2 * tid + 1];
    const int tsum = v0 + v1;
    int x = tsum;
    #pragma unroll
    for (int o = 1; o < 32; o <<= 1) {
        const int y = __shfl_up_sync(0xffffffffu, x, o);
        if (lane >= o) x += y;
    }
    if (lane == 31) warpsum[wid] = x;
    __syncthreads();
    if (wid == 0) {
        int w = warpsum[lane];
        #pragma unroll
        for (int o = 1; o < 32; o <<= 1) {
            const int y = __shfl_up_sync(0xffffffffu, w, o);
            if (lane >= o) w += y;
        }
        warpsum[lane] = w;
    }
    __syncthreads();
    const int base = (wid > 0 ? warpsum[wid - 1] : 0) + (x - tsum);
    cursor[2 * tid] = base;
    cursor[2 * tid + 1] = base + v0;
}

__global__ __launch_bounds__(256) void scatter_kernel(
    const int* __restrict__ idx, int* __restrict__ cursor,
    int* __restrict__ perm)
{
    const int t = blockIdx.x * 256 + threadIdx.x;
    const int pos = atomicAdd(&cursor[idx[t]], 1);
    perm[pos] = t;
}

// =====================================================================
// MoE: one block per (expert-sorted) token
// =====================================================================
__global__ __launch_bounds__(256) void moe_kernel(
    const float* __restrict__ h, const int* __restrict__ idx,
    const int* __restrict__ perm,
    const float* __restrict__ w1, const float* __restrict__ b1,
    const float* __restrict__ w2, const float* __restrict__ b2,
    float* __restrict__ out)
{
    const int token = perm[blockIdx.x];
    const int tid = threadIdx.x;
    const int e = idx[token];

    __shared__ float xs[EE];
    __shared__ float partial[HIDD][17];
    __shared__ float hm[HIDD];

    const float* hrow = h + (size_t)token * EE;
    for (int i = tid; i < EE; i += 256) xs[i] = hrow[i];
    __syncthreads();

    const int hcol = tid & 15;
    const int grp  = tid >> 4;
    const float* w1p = w1 + (size_t)e * EE * HIDD;
    float acc = 0.f;
    for (int i = grp; i < EE; i += 16)
        acc += xs[i] * w1p[(size_t)i * HIDD + hcol];
    partial[hcol][grp] = acc;
    __syncthreads();

    if (tid < HIDD) {
        float s = b1[(size_t)e * HIDD + tid];
        #pragma unroll
        for (int g2 = 0; g2 < 16; g2++) s += partial[tid][g2];
        hm[tid] = 0.5f * s * (1.0f + erff(s * 0.70710678118654752f));
    }
    __syncthreads();

    float hreg[HIDD];
    #pragma unroll
    for (int k = 0; k < HIDD; k++) hreg[k] = hm[k];

    const float* w2p = w2 + (size_t)e * HIDD * EE;
    const float* b2p = b2 + (size_t)e * EE;
    float* orow = out + (size_t)token * EE;
    for (int j = tid; j < EE; j += 256) {
        float s = b2p[j];
        #pragma unroll
        for (int k = 0; k < HIDD; k++) s += hreg[k] * w2p[(size_t)k * EE + j];
        orow[j] += s;
    }
}

// =====================================================================
// launch
// =====================================================================
extern "C" void kernel_launch(void* const* d_in, const int* in_sizes, int n_in,
                              void* d_out, int out_size)
{
    const float* x      = (const float*)d_in[0];
    const float* ln1_g  = (const float*)d_in[1];
    const float* ln1_b  = (const float*)d_in[2];
    const float* ln2_g  = (const float*)d_in[3];
    const float* ln2_b  = (const float*)d_in[4];
    const float* qkv_w  = (const float*)d_in[5];
    const float* qkv_b  = (const float*)d_in[6];
    const float* proj_w = (const float*)d_in[7];
    const float* proj_b = (const float*)d_in[8];
    const float* gate_w = (const float*)d_in[9];
    const float* gate_b = (const float*)d_in[10];
    const float* w1     = (const float*)d_in[11];
    const float* b1     = (const float*)d_in[12];
    const float* w2     = (const float*)d_in[13];
    const float* w2b    = (const float*)d_in[14];
    float* out = (float*)d_out;

    void *p_h, *p_part, *p_idx, *p_hist, *p_cur, *p_perm,
         *p_ah, *p_al, *p_bh, *p_bl, *p_qh, *p_ql;
    cudaGetSymbolAddress(&p_h, g_h);
    cudaGetSymbolAddress(&p_part, g_part);
    cudaGetSymbolAddress(&p_idx, g_idx);
    cudaGetSymbolAddress(&p_hist, g_hist);
    cudaGetSymbolAddress(&p_cur, g_cursor);
    cudaGetSymbolAddress(&p_perm, g_perm);
    cudaGetSymbolAddress(&p_ah, g_Ahi);
    cudaGetSymbolAddress(&p_al, g_Alo);
    cudaGetSymbolAddress(&p_bh, g_Bhi);
    cudaGetSymbolAddress(&p_bl, g_Blo);
    cudaGetSymbolAddress(&p_qh, g_QKVhi);
    cudaGetSymbolAddress(&p_ql, g_QKVlo);
    float* bh      = (float*)p_h;
    unsigned long long* bpart = (unsigned long long*)p_part;
    int*   bidx    = (int*)p_idx;
    int*   hist    = (int*)p_hist;
    int*   cursor  = (int*)p_cur;
    int*   perm    = (int*)p_perm;
    __nv_bfloat16* Ahi = (__nv_bfloat16*)p_ah;
    __nv_bfloat16* Alo = (__nv_bfloat16*)p_al;
    __nv_bfloat16* Bhi = (__nv_bfloat16*)p_bh;
    __nv_bfloat16* Blo = (__nv_bfloat16*)p_bl;
    __nv_bfloat16* QKVhi = (__nv_bfloat16*)p_qh;
    __nv_bfloat16* QKVlo = (__nv_bfloat16*)p_ql;

    cudaFuncSetAttribute(gemm_tc, cudaFuncAttributeMaxDynamicSharedMemorySize, GEMM_SMEM);
    cudaFuncSetAttribute(flash_mma_kernel, cudaFuncAttributeMaxDynamicSharedMemorySize, ATT_SMEM);

    // 1) LN1(x) -> bf16 hi/lo A operand
    layernorm_kernel<<<MTOK, 256>>>(x, ln1_g, ln1_b, nullptr, Ahi, Alo);

    // 2) qkv = h @ qkv_w + qkv_b -> bf16 hi/lo qkv buffers
    convW_kernel<<<dim3(3*EE/64, EE/64), 256>>>(qkv_w, Bhi, Blo, 3*EE, EE);
    gemm_tc<<<dim3(3*EE/128, MTOK/128), 256, GEMM_SMEM>>>(
        Ahi, Alo, Bhi, Blo, qkv_b, nullptr, nullptr, QKVhi, QKVlo, nullptr, 3*EE, EE);

    // 3) attention -> bf16 hi/lo into A operand buffers
    flash_mma_kernel<<<dim3(TT/128, NHH, BB), 256, ATT_SMEM>>>(QKVhi, QKVlo, Ahi, Alo);

    // 4) xmid = x + attn @ proj_w + proj_b -> d_out (fp32)
    convW_kernel<<<dim3(EE/64, EE/64), 256>>>(proj_w, Bhi, Blo, EE, EE);
    gemm_tc<<<dim3(EE/128, MTOK/128), 256, GEMM_SMEM>>>(
        Ahi, Alo, Bhi, Blo, proj_b, x, out, nullptr, nullptr, nullptr, EE, EE);

    // 5) LN2 -> fp32 (MoE) + bf16 hi/lo (gate GEMM)
    layernorm_kernel<<<MTOK, 256>>>(out, ln2_g, ln2_b, bh, Ahi, Alo);

    // 6) gate GEMM with fused argmax partials (no logits materialization)
    convW_kernel<<<dim3(NEE/64, EE/64), 256>>>(gate_w, Bhi, Blo, NEE, EE);
    gemm_tc<<<dim3(NEE/128, MTOK/128), 256, GEMM_SMEM>>>(
        Ahi, Alo, Bhi, Blo, gate_b, nullptr, nullptr, nullptr, nullptr, bpart, NEE, EE);

    // 7) idx = reduce(partials); expert-locality sort
    argmax_reduce_kernel<<<MTOK/256, 256>>>(bpart, bidx);
    hist_clear_kernel<<<NEE/256, 256>>>(hist);
    hist_kernel<<<MTOK/256, 256>>>(bidx, hist);
    scan_kernel<<<1, 1024>>>(hist, cursor);
    scatter_kernel<<<MTOK/256, 256>>>(bidx, cursor, perm);

    // 8) d_out += moe(h, idx) over expert-sorted tokens (block per token)
    moe_kernel<<<MTOK, 256>>>(bh, bidx, perm, w1, b1, w2, w2b, out);
}

// round 14
// speedup vs baseline: 1.1181x; 1.0310x over previous
#include <cuda_runtime.h>
#include <cuda_bf16.h>
#include <math.h>
#include <stdint.h>

// ---------------- problem constants ----------------
#define BB 4
#define TT 2048
#define EE 1024
#define NHH 16
#define DHH 64
#define NEE 2048
#define HIDD 16
#define MTOK (BB*TT)          // 8192 tokens
#define LN_EPS 1e-5f

// ---------------- scratch (device globals; no runtime allocation) ----------
__device__ float g_h[MTOK * EE];          // LN2 output fp32 (for MoE)
__device__ unsigned long long g_part[MTOK * 16];  // per-(row, bn-tile) argmax partials
__device__ int   g_idx[MTOK];             // argmax expert per token
__device__ int   g_hist[NEE];
__device__ int   g_cursor[NEE];
__device__ int   g_perm[MTOK];
__device__ __nv_bfloat16 g_Ahi[MTOK * EE];       // GEMM A operand hi [M,K]
__device__ __nv_bfloat16 g_Alo[MTOK * EE];
__device__ __nv_bfloat16 g_Bhi[3 * EE * EE];     // weights transposed [N,K]
__device__ __nv_bfloat16 g_Blo[3 * EE * EE];
__device__ __nv_bfloat16 g_QKVhi[MTOK * 3 * EE]; // qkv bf16 hi/lo
__device__ __nv_bfloat16 g_QKVlo[MTOK * 3 * EE];

// =====================================================================
// PTX helpers (family-portable: cp.async / ldmatrix / mma.sync only)
// =====================================================================
__device__ __forceinline__ uint32_t smem_u32(const void* p){
    uint32_t a;
    asm("{ .reg .u64 t; cvta.to.shared.u64 t, %1; cvt.u32.u64 %0, t; }"
        : "=r"(a) : "l"(p));
    return a;
}
__device__ __forceinline__ void cp_async16(uint32_t dst, const void* src){
    asm volatile("cp.async.cg.shared.global [%0], [%1], 16;"
        :: "r"(dst), "l"(src));
}
__device__ __forceinline__ void cp_commit(){
    asm volatile("cp.async.commit_group;");
}
template<int N> __device__ __forceinline__ void cp_wait(){
    asm volatile("cp.async.wait_group %0;" :: "n"(N));
}
__device__ __forceinline__ void ldsm_x4(uint32_t* r, uint32_t a){
    asm volatile("ldmatrix.sync.aligned.m8n8.x4.shared.b16 {%0,%1,%2,%3}, [%4];"
        : "=r"(r[0]), "=r"(r[1]), "=r"(r[2]), "=r"(r[3]) : "r"(a));
}
__device__ __forceinline__ void ldsm_x4_t(uint32_t* r, uint32_t a){
    asm volatile("ldmatrix.sync.aligned.m8n8.x4.trans.shared.b16 {%0,%1,%2,%3}, [%4];"
        : "=r"(r[0]), "=r"(r[1]), "=r"(r[2]), "=r"(r[3]) : "r"(a));
}
__device__ __forceinline__ void mma16816(float* d, const uint32_t* a, const uint32_t* b){
    asm volatile(
        "mma.sync.aligned.m16n8k16.row.col.f32.bf16.bf16.f32 "
        "{%0,%1,%2,%3}, {%4,%5,%6,%7}, {%8,%9}, {%0,%1,%2,%3};"
        : "+f"(d[0]), "+f"(d[1]), "+f"(d[2]), "+f"(d[3])
        : "r"(a[0]), "r"(a[1]), "r"(a[2]), "r"(a[3]), "r"(b[0]), "r"(b[1]));
}
__device__ __forceinline__ uint32_t packsplit(float x, float y, uint32_t& lo){
    __nv_bfloat162 h = __floats2bfloat162_rn(x, y);
    __nv_bfloat162 l = __floats2bfloat162_rn(x - __bfloat162float(h.x),
                                             y - __bfloat162float(h.y));
    lo = *(uint32_t*)&l;
    return *(uint32_t*)&h;
}
// monotone encoding of (float value, col) for argmax-with-first-tiebreak
__device__ __forceinline__ unsigned long long enc_argmax(float v, int col){
    uint32_t u = __float_as_uint(v);
    u = (u & 0x80000000u) ? ~u : (u | 0x80000000u);
    return ((unsigned long long)u << 32) | (uint32_t)(~col);
}
__device__ __forceinline__ int dec_argmax(unsigned long long k){
    return (int)(~(uint32_t)k);
}

// =====================================================================
// Weights: fp32 W[K,N] -> transposed bf16 hi/lo [N,K]
// =====================================================================
__global__ __launch_bounds__(256) void convW_kernel(
    const float* __restrict__ W, __nv_bfloat16* __restrict__ hi,
    __nv_bfloat16* __restrict__ lo, int N, int K)
{
    __shared__ float tile[64][65];
    const int k0 = blockIdx.y * 64;
    const int n0 = blockIdx.x * 64;
    for (int i = threadIdx.x; i < 4096; i += 256) {
        const int r = i >> 6, c = i & 63;
        tile[r][c] = W[(size_t)(k0 + r) * N + n0 + c];
    }
    __syncthreads();
    for (int i = threadIdx.x; i < 4096; i += 256) {
        const int r = i >> 6, c = i & 63;
        const float v = tile[c][r];
        const __nv_bfloat16 h = __float2bfloat16(v);
        const __nv_bfloat16 l = __float2bfloat16(v - __bfloat162float(h));
        const size_t o = (size_t)(n0 + r) * K + k0 + c;
        hi[o] = h;
        lo[o] = l;
    }
}

// =====================================================================
// split-bf16 HMMA GEMM: C[M,N] = A[M,K] @ W[K,N] + bias (+ res)
// CTA 128x128, BK=32, 2-stage cp.async, 2 CTAs/SM, 8 warps (2x4),
// warp tile 64x32, term-major MMA ordering, A-fragment double buffer.
// Epilogue: fp32 (Cf) / bf16 hi-lo (outHi/outLo) / argmax partials (part)
// =====================================================================
#define RS 80                      // smem row stride bytes (40 bf16)
#define MATB (128*RS)              // 10240 B per matrix tile
#define STGB (4*MATB)              // 40960 B per stage
#define GEMM_SMEM (512 + 2*STGB)   // bias + 2 stages = 82432 -> 2 CTAs/SM

__global__ __launch_bounds__(256, 2)
void gemm_tc(const __nv_bfloat16* __restrict__ Ahi, const __nv_bfloat16* __restrict__ Alo,
             const __nv_bfloat16* __restrict__ Bhi, const __nv_bfloat16* __restrict__ Blo,
             const float* __restrict__ bias, const float* __restrict__ res,
             float* __restrict__ Cf,
             __nv_bfloat16* __restrict__ outHi, __nv_bfloat16* __restrict__ outLo,
             unsigned long long* __restrict__ part,
             int N, int K)
{
    extern __shared__ __align__(128) char smem[];
    const int tid = threadIdx.x;
    const int lane = tid & 31, wid = tid >> 5;
    const int warp_m = wid & 1, warp_n = wid >> 1;     // 2 x 4
    const int bn = blockIdx.x, bm = blockIdx.y;
    const uint32_t sb = smem_u32(smem);
    float* bsm = (float*)smem;

    if (tid < 128) bsm[tid] = bias[bn * 128 + tid];

    const __nv_bfloat16* gA[2] = { Ahi + (size_t)bm * 128 * K,
                                   Alo + (size_t)bm * 128 * K };
    const __nv_bfloat16* gB[2] = { Bhi + (size_t)bn * 128 * K,
                                   Blo + (size_t)bn * 128 * K };

    const int r0 = tid >> 2, c0 = tid & 3;
    const int r1 = r0 + 64;

    auto load_stage = [&](int s, int k0){
        const uint32_t st = sb + 512 + s * STGB;
        #pragma unroll
        for (int m = 0; m < 2; m++) {
            const __nv_bfloat16* src = gA[m] + k0;
            const uint32_t d = st + m * MATB;
            cp_async16(d + r0 * RS + c0 * 16, src + (size_t)r0 * K + c0 * 8);
            cp_async16(d + r1 * RS + c0 * 16, src + (size_t)r1 * K + c0 * 8);
        }
        #pragma unroll
        for (int m = 0; m < 2; m++) {
            const __nv_bfloat16* src = gB[m] + k0;
            const uint32_t d = st + (2 + m) * MATB;
            cp_async16(d + r0 * RS + c0 * 16, src + (size_t)r0 * K + c0 * 8);
            cp_async16(d + r1 * RS + c0 * 16, src + (size_t)r1 * K + c0 * 8);
        }
    };

    float acc[4][4][4];
    #pragma unroll
    for (int i = 0; i < 4; i++)
        #pragma unroll
        for (int j = 0; j < 4; j++)
            #pragma unroll
            for (int t = 0; t < 4; t++) acc[i][j][t] = 0.f;

    const int nk = K >> 5;
    load_stage(0, 0);  cp_commit();
    load_stage(1, 32); cp_commit();

    const int l15 = lane & 15;
    const uint32_t aRowOff = (uint32_t)(warp_m * 64 + l15) * RS + (uint32_t)(lane >> 4) * 16;
    const uint32_t bRowOff = (uint32_t)(warp_n * 32 + (lane & 7) + ((lane >> 4) << 3)) * RS
                           + (uint32_t)((lane >> 3) & 1) * 16;

    for (int c = 0; c < nk; c++) {
        if (c == nk - 1) cp_wait<0>(); else cp_wait<1>();
        __syncthreads();

        const uint32_t st = sb + 512 + (c & 1) * STGB;
        #pragma unroll
        for (int kk = 0; kk < 2; kk++) {
            uint32_t bh[2][4], bl[2][4];
            #pragma unroll
            for (int np = 0; np < 2; np++) {
                const uint32_t ba = st + bRowOff + (uint32_t)np * 16 * RS + kk * 32;
                ldsm_x4(bh[np], ba + 2 * MATB);
                ldsm_x4(bl[np], ba + 3 * MATB);
            }
            // A-fragment double buffer: prefetch mt+1 while issuing mt's MMAs
            uint32_t ah[2][4], al[2][4];
            {
                const uint32_t aa0 = st + aRowOff + kk * 32;
                ldsm_x4(ah[0], aa0);
                ldsm_x4(al[0], aa0 + MATB);
            }
            #pragma unroll
            for (int mt = 0; mt < 4; mt++) {
                const int cur = mt & 1, nxt = cur ^ 1;
                if (mt < 3) {
                    const uint32_t aa = st + aRowOff + (uint32_t)(mt + 1) * 16 * RS + kk * 32;
                    ldsm_x4(ah[nxt], aa);
                    ldsm_x4(al[nxt], aa + MATB);
                }
                // term-major: 4 independent accs between same-acc MMAs
                #pragma unroll
                for (int nt = 0; nt < 4; nt++)
                    mma16816(acc[mt][nt], ah[cur], &bh[nt >> 1][(nt & 1) * 2]);
                #pragma unroll
                for (int nt = 0; nt < 4; nt++)
                    mma16816(acc[mt][nt], ah[cur], &bl[nt >> 1][(nt & 1) * 2]);
                #pragma unroll
                for (int nt = 0; nt < 4; nt++)
                    mma16816(acc[mt][nt], al[cur], &bh[nt >> 1][(nt & 1) * 2]);
            }
        }
        __syncthreads();
        if (c + 2 < nk) { load_stage(c & 1, (c + 2) * 32); cp_commit(); }
    }

    const int mBase = bm * 128 + warp_m * 64;
    const int nBase = warp_n * 32;
    const int gn0 = bn * 128;

    if (part) {
        // fused argmax partials (gate GEMM): smem two-level reduce, no atomics
        unsigned long long* psm = (unsigned long long*)(smem + 512);  // [128][4]
        #pragma unroll
        for (int mt = 0; mt < 4; mt++) {
            #pragma unroll
            for (int hh = 0; hh < 2; hh++) {
                const int rloc = warp_m * 64 + mt * 16 + (lane >> 2) + hh * 8;
                float bestv = -3.4e38f; int bestc = 0;
                #pragma unroll
                for (int nt = 0; nt < 4; nt++) {
                    const int lc = nBase + nt * 8 + (lane & 3) * 2;
                    const float vx = acc[mt][nt][hh * 2 + 0] + bsm[lc];
                    const float vy = acc[mt][nt][hh * 2 + 1] + bsm[lc + 1];
                    if (vx > bestv) { bestv = vx; bestc = gn0 + lc; }
                    if (vy > bestv) { bestv = vy; bestc = gn0 + lc + 1; }
                }
                unsigned long long key = enc_argmax(bestv, bestc);
                unsigned long long o1 = __shfl_xor_sync(0xffffffffu, key, 1);
                if (o1 > key) key = o1;
                unsigned long long o2 = __shfl_xor_sync(0xffffffffu, key, 2);
                if (o2 > key) key = o2;
                if ((lane & 3) == 0) psm[rloc * 4 + warp_n] = key;
            }
        }
        __syncthreads();
        if (tid < 128) {
            unsigned long long k = psm[tid * 4 + 0];
            unsigned long long t1 = psm[tid * 4 + 1]; if (t1 > k) k = t1;
            unsigned long long t2 = psm[tid * 4 + 2]; if (t2 > k) k = t2;
            unsigned long long t3 = psm[tid * 4 + 3]; if (t3 > k) k = t3;
            part[(size_t)(bm * 128 + tid) * 16 + bn] = k;
        }
        return;
    }

    #pragma unroll
    for (int mt = 0; mt < 4; mt++) {
        #pragma unroll
        for (int nt = 0; nt < 4; nt++) {
            const int row = mBase + mt * 16 + (lane >> 2);
            const int col = nBase + nt * 8 + (lane & 3) * 2;
            #pragma unroll
            for (int hh = 0; hh < 2; hh++) {
                const int m = row + hh * 8;
                float vx = acc[mt][nt][hh * 2 + 0] + bsm[col];
                float vy = acc[mt][nt][hh * 2 + 1] + bsm[col + 1];
                if (outHi) {
                    uint32_t lo;
                    const uint32_t hi = packsplit(vx, vy, lo);
                    *(uint32_t*)(outHi + (size_t)m * N + gn0 + col) = hi;
                    *(uint32_t*)(outLo + (size_t)m * N + gn0 + col) = lo;
                } else {
                    if (res) {
                        const float2 rv = *(const float2*)(res + (size_t)m * N + gn0 + col);
                        vx += rv.x; vy += rv.y;
                    }
                    float2 v; v.x = vx; v.y = vy;
                    *(float2*)(Cf + (size_t)m * N + gn0 + col) = v;
                }
            }
        }
    }
}

// =====================================================================
// HMMA flash attention (causal, unnormalized exp softmax)
// Q: bf16 hi only (2-term QK split; Q-lo term dropped, err ~4e-4 on p).
// P V: full 3-term split. Grid (T/128, NH, B), 256 thr, 2 CTAs/SM.
// =====================================================================
#define SRS 144                     // smem row stride (64 bf16 + 16B pad)
#define ATT_MAT (64*SRS)            // 9216 per matrix (64 rows)
#define ATT_STG (4*ATT_MAT)         // Khi,Klo,Vhi,Vlo = 36864
#define ATT_Q   (128*SRS)           // 18432 (Q hi only)
#define ATT_SMEM (ATT_Q + 2*ATT_STG)   // 92160 -> 2 CTAs/SM

__global__ __launch_bounds__(256, 2)
void flash_mma_kernel(const __nv_bfloat16* __restrict__ QKVhi,
                      const __nv_bfloat16* __restrict__ QKVlo,
                      __nv_bfloat16* __restrict__ Ohi,
                      __nv_bfloat16* __restrict__ Olo)
{
    extern __shared__ __align__(128) char smem[];
    const int tid = threadIdx.x, lane = tid & 31, wid = tid >> 5;
    const int qt = (int)gridDim.x - 1 - (int)blockIdx.x;   // heavy blocks first
    const int q0 = qt * 128;
    const int h = blockIdx.y, b = blockIdx.z;

    const uint32_t sQhi = smem_u32(smem);
    const uint32_t sKV0 = sQhi + ATT_Q;

    const size_t rowStride = 3 * EE;
    const size_t base = ((size_t)b * TT) * rowStride + (size_t)h * DHH;
    const __nv_bfloat16* Qh = QKVhi + base;
    const __nv_bfloat16* Kh = Qh + EE;
    const __nv_bfloat16* Kl = QKVlo + base + EE;
    const __nv_bfloat16* Vh = Qh + 2 * EE;
    const __nv_bfloat16* Vl = QKVlo + base + 2 * EE;

    // ---- Q tile load (128 rows x 8 16B chunks, hi only) ----
    for (int i = tid; i < 1024; i += 256) {
        const int row = i >> 3, c = i & 7;
        const size_t g = (size_t)(q0 + row) * rowStride + c * 8;
        cp_async16(sQhi + row * SRS + c * 16, Qh + g);
    }

    auto load_kv = [&](int s, int k0){
        const uint32_t st = sKV0 + s * ATT_STG;
        for (int i = tid; i < 512; i += 256) {
            const int row = i >> 3, c = i & 7;
            const size_t g = (size_t)(k0 + row) * rowStride + c * 8;
            const uint32_t d = st + row * SRS + c * 16;
            cp_async16(d + 0 * ATT_MAT, Kh + g);
            cp_async16(d + 1 * ATT_MAT, Kl + g);
            cp_async16(d + 2 * ATT_MAT, Vh + g);
            cp_async16(d + 3 * ATT_MAT, Vl + g);
        }
    };

    const int nk = 2 * qt + 2;      // 64-key tiles
    load_kv(0, 0);  cp_commit();    // group 0 carries Q too

    float acc_o[8][4];
    #pragma unroll
    for (int i = 0; i < 8; i++)
        #pragma unroll
        for (int j = 0; j < 4; j++) acc_o[i][j] = 0.f;
    float l0 = 0.f, l1 = 0.f;

    const int l15 = lane & 15;
    const uint32_t qOff = (uint32_t)(wid * 16 + l15) * SRS + (uint32_t)(lane >> 4) * 16;
    const uint32_t kRowOff = (uint32_t)((lane & 7) + ((lane >> 4) << 3)) * SRS
                           + (uint32_t)((lane >> 3) & 1) * 16;
    const uint32_t vRowOff = (uint32_t)((lane & 7) + (((lane >> 3) & 1) << 3)) * SRS
                           + (uint32_t)((lane >> 4) & 1) * 16;

    const int limit = q0 + wid * 16 + 15;   // warp's max row

    for (int c = 0; c < nk; c++) {
        cp_wait<0>();
        __syncthreads();
        if (c + 1 < nk) { load_kv((c + 1) & 1, (c + 1) * 64); cp_commit(); }

        const uint32_t Khi_ = sKV0 + (c & 1) * ATT_STG;
        const uint32_t Klo_ = Khi_ + ATT_MAT;
        const uint32_t Vhi_ = Khi_ + 2 * ATT_MAT;
        const uint32_t Vlo_ = Khi_ + 3 * ATT_MAT;
        const int k0 = c * 64;
        const bool needmask = (k0 + 63) > (q0 + wid * 16);

        // ---- S = Q K^T (Q hi only; 2-term split on K) ----
        float sacc[8][4];
        #pragma unroll
        for (int i = 0; i < 8; i++)
            #pragma unroll
            for (int j = 0; j < 4; j++) sacc[i][j] = 0.f;

        #pragma unroll
        for (int kk = 0; kk < 4; kk++) {
            uint32_t qh[4];
            ldsm_x4(qh, sQhi + qOff + kk * 32);
            #pragma unroll
            for (int np = 0; np < 4; np++) {
                if (k0 + np * 16 > limit) break;   // fully masked 16-col tile
                const uint32_t ba = kRowOff + (uint32_t)np * 16 * SRS + kk * 32;
                uint32_t bh[4], bl[4];
                ldsm_x4(bh, Khi_ + ba);
                ldsm_x4(bl, Klo_ + ba);
                #pragma unroll
                for (int t = 0; t < 2; t++) {
                    mma16816(sacc[2 * np + t], qh, &bh[2 * t]);
                    mma16816(sacc[2 * np + t], qh, &bl[2 * t]);
                }
            }
        }

        // ---- unnormalized softmax: p = exp2(s * 0.125/ln2), masked -> 0 ----
        const int rbase = q0 + wid * 16 + (lane >> 2);
        float s0 = 0.f, s1 = 0.f;
        #pragma unroll
        for (int nt = 0; nt < 8; nt++) {
            const int col = k0 + nt * 8 + 2 * (lane & 3);
            if (k0 + (nt >> 1) * 16 > limit) {
                sacc[nt][0] = sacc[nt][1] = sacc[nt][2] = sacc[nt][3] = 0.f;
                continue;
            }
            #pragma unroll
            for (int j = 0; j < 4; j++) {
                bool dead = false;
                if (needmask) {
                    const int cc = col + (j & 1);
                    const int rr = rbase + (j >> 1) * 8;
                    dead = (cc > rr);
                }
                const float v = dead ? 0.f
                    : exp2f(sacc[nt][j] * 0.18033688011112042f);
                sacc[nt][j] = v;
            }
            s0 += sacc[nt][0] + sacc[nt][1];
            s1 += sacc[nt][2] + sacc[nt][3];
        }
        s0 += __shfl_xor_sync(0xffffffffu, s0, 1);
        s0 += __shfl_xor_sync(0xffffffffu, s0, 2);
        s1 += __shfl_xor_sync(0xffffffffu, s1, 1);
        s1 += __shfl_xor_sync(0xffffffffu, s1, 2);
        l0 += s0; l1 += s1;

        // ---- O += P V (split P, split V) ----
        #pragma unroll
        for (int kkp = 0; kkp < 4; kkp++) {
            if (k0 + kkp * 16 > limit) break;      // P == 0 for these keys
            uint32_t phi[4], plo[4];
            phi[0] = packsplit(sacc[2*kkp][0],   sacc[2*kkp][1],   plo[0]);
            phi[1] = packsplit(sacc[2*kkp][2],   sacc[2*kkp][3],   plo[1]);
            phi[2] = packsplit(sacc[2*kkp+1][0], sacc[2*kkp+1][1], plo[2]);
            phi[3] = packsplit(sacc[2*kkp+1][2], sacc[2*kkp+1][3], plo[3]);
            #pragma unroll
            for (int np = 0; np < 4; np++) {
                const uint32_t va = (uint32_t)(kkp * 16) * SRS + vRowOff + np * 32;
                uint32_t vh[4], vl[4];
                ldsm_x4_t(vh, Vhi_ + va);
                ldsm_x4_t(vl, Vlo_ + va);
                #pragma unroll
                for (int t = 0; t < 2; t++) {
                    mma16816(acc_o[2 * np + t], phi, &vh[2 * t]);
                    mma16816(acc_o[2 * np + t], phi, &vl[2 * t]);
                    mma16816(acc_o[2 * np + t], plo, &vh[2 * t]);
                }
            }
        }
    }

    // ---- epilogue: O / l, write bf16 hi/lo into GEMM A buffers ----
    const float inv0 = 1.f / l0, inv1 = 1.f / l1;
    const int row0 = b * TT + q0 + wid * 16 + (lane >> 2);
    const int colb = h * DHH + 2 * (lane & 3);
    #pragma unroll
    for (int nt = 0; nt < 8; nt++) {
        const int col = colb + nt * 8;
        uint32_t lo;
        uint32_t hi = packsplit(acc_o[nt][0] * inv0, acc_o[nt][1] * inv0, lo);
        *(uint32_t*)(Ohi + (size_t)row0 * EE + col) = hi;
        *(uint32_t*)(Olo + (size_t)row0 * EE + col) = lo;
        hi = packsplit(acc_o[nt][2] * inv1, acc_o[nt][3] * inv1, lo);
        *(uint32_t*)(Ohi + (size_t)(row0 + 8) * EE + col) = hi;
        *(uint32_t*)(Olo + (size_t)(row0 + 8) * EE + col) = lo;
    }
}

// =====================================================================
// LayerNorm: block per row, 256 threads; optional fp32 + bf16 hi/lo out
// =====================================================================
__global__ __launch_bounds__(256) void layernorm_kernel(
    const float* __restrict__ x, const float* __restrict__ gam,
    const float* __restrict__ bet, float* __restrict__ outF,
    __nv_bfloat16* __restrict__ outHi, __nv_bfloat16* __restrict__ outLo)
{
    const int row = blockIdx.x;
    const int tid = threadIdx.x;
    const float4 xv = *(const float4*)(x + (size_t)row * EE + tid * 4);

    __shared__ float red[8];

    float s = xv.x + xv.y + xv.z + xv.w;
    #pragma unroll
    for (int o = 16; o; o >>= 1) s += __shfl_xor_sync(0xffffffffu, s, o);
    if ((tid & 31) == 0) red[tid >> 5] = s;
    __syncthreads();
    float tot = 0.f;
    #pragma unroll
    for (int i = 0; i < 8; i++) tot += red[i];
    const float mu = tot * (1.0f / (float)EE);
    __syncthreads();

    const float dx = xv.x - mu, dy = xv.y - mu, dz = xv.z - mu, dw = xv.w - mu;
    float ss = dx*dx + dy*dy + dz*dz + dw*dw;
    #pragma unroll
    for (int o = 16; o; o >>= 1) ss += __shfl_xor_sync(0xffffffffu, ss, o);
    if ((tid & 31) == 0) red[tid >> 5] = ss;
    __syncthreads();
    float sst = 0.f;
    #pragma unroll
    for (int i = 0; i < 8; i++) sst += red[i];
    const float inv = rsqrtf(sst * (1.0f / (float)EE) + LN_EPS);

    const float4 gv = *(const float4*)(gam + tid * 4);
    const float4 bv = *(const float4*)(bet + tid * 4);
    float4 ov;
    ov.x = dx * inv * gv.x + bv.x;
    ov.y = dy * inv * gv.y + bv.y;
    ov.z = dz * inv * gv.z + bv.z;
    ov.w = dw * inv * gv.w + bv.w;
    if (outF) *(float4*)(outF + (size_t)row * EE + tid * 4) = ov;
    uint32_t lo0, lo1;
    const uint32_t hi0 = packsplit(ov.x, ov.y, lo0);
    const uint32_t hi1 = packsplit(ov.z, ov.w, lo1);
    uint2 hv; hv.x = hi0; hv.y = hi1;
    uint2 lv; lv.x = lo0; lv.y = lo1;
    *(uint2*)(outHi + (size_t)row * EE + tid * 4) = hv;
    *(uint2*)(outLo + (size_t)row * EE + tid * 4) = lv;
}

// =====================================================================
// Argmax reduce over 16 partials per row
// =====================================================================
__global__ __launch_bounds__(256) void argmax_reduce_kernel(
    const unsigned long long* __restrict__ part, int* __restrict__ idx)
{
    const int m = blockIdx.x * 256 + threadIdx.x;
    const unsigned long long* p = part + (size_t)m * 16;
    unsigned long long k = p[0];
    #pragma unroll
    for (int i = 1; i < 16; i++) {
        const unsigned long long v = p[i];
        if (v > k) k = v;
    }
    idx[m] = dec_argmax(k);
}

// =====================================================================
// MoE routing: clear-hist / hist / scan / scatter (from g_idx)
// =====================================================================
__global__ __launch_bounds__(256) void hist_clear_kernel(int* __restrict__ hist)
{
    hist[blockIdx.x * 256 + threadIdx.x] = 0;
}

__global__ __launch_bounds__(256) void hist_kernel(
    const int* __restrict__ idx, int* __restrict__ hist)
{
    const int t = blockIdx.x * 256 + threadIdx.x;
    atomicAdd(&hist[idx[t]], 1);
}

__global__ __launch_bounds__(1024) void scan_kernel(
    const int* __restrict__ hist, int* __restrict__ cursor)
{
    __shared__ int warpsum[32];
    const int tid = threadIdx.x;
    const int lane = tid & 31, wid = tid >> 5;
    const int v0 = hist[2 * tid], v1 = hist[2 * tid + 1];
    const int tsum = v0 + v1;
    int x = tsum;
    #pragma unroll
    for (int o = 1; o < 32; o <<= 1) {
        const int y = __shfl_up_sync(0xffffffffu, x, o);
        if (lane >= o) x += y;
    }
    if (lane == 31) warpsum[wid] = x;
    __syncthreads();
    if (wid == 0) {
        int w = warpsum[lane];
        #pragma unroll
        for (int o = 1; o < 32; o <<= 1) {
            const int y = __shfl_up_sync(0xffffffffu, w, o);
            if (lane >= o) w += y;
        }
        warpsum[lane] = w;
    }
    __syncthreads();
    const int base = (wid > 0 ? warpsum[wid - 1] : 0) + (x - tsum);
    cursor[2 * tid] = base;
    cursor[2 * tid + 1] = base + v0;
}

__global__ __launch_bounds__(256) void scatter_kernel(
    const int* __restrict__ idx, int* __restrict__ cursor,
    int* __restrict__ perm)
{
    const int t = blockIdx.x * 256 + threadIdx.x;
    const int pos = atomicAdd(&cursor[idx[t]], 1);
    perm[pos] = t;
}

// =====================================================================
// MoE: one block per (expert-sorted) token
// =====================================================================
__global__ __launch_bounds__(256) void moe_kernel(
    const float* __restrict__ h, const int* __restrict__ idx,
    const int* __restrict__ perm,
    const float* __restrict__ w1, const float* __restrict__ b1,
    const float* __restrict__ w2, const float* __restrict__ b2,
    float* __restrict__ out)
{
    const int token = perm[blockIdx.x];
    const int tid = threadIdx.x;
    const int e = idx[token];

    __shared__ float xs[EE];
    __shared__ float partial[HIDD][17];
    __shared__ float hm[HIDD];

    const float* hrow = h + (size_t)token * EE;
    for (int i = tid; i < EE; i += 256) xs[i] = hrow[i];
    __syncthreads();

    const int hcol = tid & 15;
    const int grp  = tid >> 4;
    const float* w1p = w1 + (size_t)e * EE * HIDD;
    float acc = 0.f;
    for (int i = grp; i < EE; i += 16)
        acc += xs[i] * w1p[(size_t)i * HIDD + hcol];
    partial[hcol][grp] = acc;
    __syncthreads();

    if (tid < HIDD) {
        float s = b1[(size_t)e * HIDD + tid];
        #pragma unroll
        for (int g2 = 0; g2 < 16; g2++) s += partial[tid][g2];
        hm[tid] = 0.5f * s * (1.0f + erff(s * 0.70710678118654752f));
    }
    __syncthreads();

    float hreg[HIDD];
    #pragma unroll
    for (int k = 0; k < HIDD; k++) hreg[k] = hm[k];

    const float* w2p = w2 + (size_t)e * HIDD * EE;
    const float* b2p = b2 + (size_t)e * EE;
    float* orow = out + (size_t)token * EE;
    for (int j = tid; j < EE; j += 256) {
        float s = b2p[j];
        #pragma unroll
        for (int k = 0; k < HIDD; k++) s += hreg[k] * w2p[(size_t)k * EE + j];
        orow[j] += s;
    }
}

// =====================================================================
// launch
// =====================================================================
extern "C" void kernel_launch(void* const* d_in, const int* in_sizes, int n_in,
                              void* d_out, int out_size)
{
    const float* x      = (const float*)d_in[0];
    const float* ln1_g  = (const float*)d_in[1];
    const float* ln1_b  = (const float*)d_in[2];
    const float* ln2_g  = (const float*)d_in[3];
    const float* ln2_b  = (const float*)d_in[4];
    const float* qkv_w  = (const float*)d_in[5];
    const float* qkv_b  = (const float*)d_in[6];
    const float* proj_w = (const float*)d_in[7];
    const float* proj_b = (const float*)d_in[8];
    const float* gate_w = (const float*)d_in[9];
    const float* gate_b = (const float*)d_in[10];
    const float* w1     = (const float*)d_in[11];
    const float* b1     = (const float*)d_in[12];
    const float* w2     = (const float*)d_in[13];
    const float* w2b    = (const float*)d_in[14];
    float* out = (float*)d_out;

    void *p_h, *p_part, *p_idx, *p_hist, *p_cur, *p_perm,
         *p_ah, *p_al, *p_bh, *p_bl, *p_qh, *p_ql;
    cudaGetSymbolAddress(&p_h, g_h);
    cudaGetSymbolAddress(&p_part, g_part);
    cudaGetSymbolAddress(&p_idx, g_idx);
    cudaGetSymbolAddress(&p_hist, g_hist);
    cudaGetSymbolAddress(&p_cur, g_cursor);
    cudaGetSymbolAddress(&p_perm, g_perm);
    cudaGetSymbolAddress(&p_ah, g_Ahi);
    cudaGetSymbolAddress(&p_al, g_Alo);
    cudaGetSymbolAddress(&p_bh, g_Bhi);
    cudaGetSymbolAddress(&p_bl, g_Blo);
    cudaGetSymbolAddress(&p_qh, g_QKVhi);
    cudaGetSymbolAddress(&p_ql, g_QKVlo);
    float* bh      = (float*)p_h;
    unsigned long long* bpart = (unsigned long long*)p_part;
    int*   bidx    = (int*)p_idx;
    int*   hist    = (int*)p_hist;
    int*   cursor  = (int*)p_cur;
    int*   perm    = (int*)p_perm;
    __nv_bfloat16* Ahi = (__nv_bfloat16*)p_ah;
    __nv_bfloat16* Alo = (__nv_bfloat16*)p_al;
    __nv_bfloat16* Bhi = (__nv_bfloat16*)p_bh;
    __nv_bfloat16* Blo = (__nv_bfloat16*)p_bl;
    __nv_bfloat16* QKVhi = (__nv_bfloat16*)p_qh;
    __nv_bfloat16* QKVlo = (__nv_bfloat16*)p_ql;

    cudaFuncSetAttribute(gemm_tc, cudaFuncAttributeMaxDynamicSharedMemorySize, GEMM_SMEM);
    cudaFuncSetAttribute(flash_mma_kernel, cudaFuncAttributeMaxDynamicSharedMemorySize, ATT_SMEM);

    // 1) LN1(x) -> bf16 hi/lo A operand
    layernorm_kernel<<<MTOK, 256>>>(x, ln1_g, ln1_b, nullptr, Ahi, Alo);

    // 2) qkv = h @ qkv_w + qkv_b -> bf16 hi/lo qkv buffers
    convW_kernel<<<dim3(3*EE/64, EE/64), 256>>>(qkv_w, Bhi, Blo, 3*EE, EE);
    gemm_tc<<<dim3(3*EE/128, MTOK/128), 256, GEMM_SMEM>>>(
        Ahi, Alo, Bhi, Blo, qkv_b, nullptr, nullptr, QKVhi, QKVlo, nullptr, 3*EE, EE);

    // 3) attention -> bf16 hi/lo into A operand buffers
    flash_mma_kernel<<<dim3(TT/128, NHH, BB), 256, ATT_SMEM>>>(QKVhi, QKVlo, Ahi, Alo);

    // 4) xmid = x + attn @ proj_w + proj_b -> d_out (fp32)
    convW_kernel<<<dim3(EE/64, EE/64), 256>>>(proj_w, Bhi, Blo, EE, EE);
    gemm_tc<<<dim3(EE/128, MTOK/128), 256, GEMM_SMEM>>>(
        Ahi, Alo, Bhi, Blo, proj_b, x, out, nullptr, nullptr, nullptr, EE, EE);

    // 5) LN2 -> fp32 (MoE) + bf16 hi/lo (gate GEMM)
    layernorm_kernel<<<MTOK, 256>>>(out, ln2_g, ln2_b, bh, Ahi, Alo);

    // 6) gate GEMM with fused argmax partials (no logits materialization)
    convW_kernel<<<dim3(NEE/64, EE/64), 256>>>(gate_w, Bhi, Blo, NEE, EE);
    gemm_tc<<<dim3(NEE/128, MTOK/128), 256, GEMM_SMEM>>>(
        Ahi, Alo, Bhi, Blo, gate_b, nullptr, nullptr, nullptr, nullptr, bpart, NEE, EE);

    // 7) idx = reduce(partials); expert-locality sort
    argmax_reduce_kernel<<<MTOK/256, 256>>>(bpart, bidx);
    hist_clear_kernel<<<NEE/256, 256>>>(hist);
    hist_kernel<<<MTOK/256, 256>>>(bidx, hist);
    scan_kernel<<<1, 1024>>>(hist, cursor);
    scatter_kernel<<<MTOK/256, 256>>>(bidx, cursor, perm);

    // 8) d_out += moe(h, idx) over expert-sorted tokens (block per token)
    moe_kernel<<<MTOK, 256>>>(bh, bidx, perm, w1, b1, w2, w2b, out);
}

// round 15
// speedup vs baseline: 1.2134x; 1.0853x over previous
#include <cuda_runtime.h>
#include <cuda_bf16.h>
#include <math.h>
#include <stdint.h>

// ---------------- problem constants ----------------
#define BB 4
#define TT 2048
#define EE 1024
#define NHH 16
#define DHH 64
#define NEE 2048
#define HIDD 16
#define MTOK (BB*TT)          // 8192 tokens
#define LN_EPS 1e-5f

// ---------------- scratch (device globals; no runtime allocation) ----------
__device__ float g_h[MTOK * EE];          // LN2 output fp32 (for MoE)
__device__ unsigned long long g_part[MTOK * 16];  // per-(row, bn-tile) argmax partials
__device__ int   g_idx[MTOK];             // argmax expert per token
__device__ int   g_hist[NEE];
__device__ int   g_cursor[NEE];
__device__ int   g_perm[MTOK];
__device__ __nv_bfloat16 g_Ahi[MTOK * EE];       // GEMM A operand hi [M,K]
__device__ __nv_bfloat16 g_Alo[MTOK * EE];
__device__ __nv_bfloat16 g_Bhi[3 * EE * EE];     // weights transposed [N,K]
__device__ __nv_bfloat16 g_Blo[3 * EE * EE];
__device__ __nv_bfloat16 g_QKVhi[MTOK * 3 * EE]; // qkv bf16 hi/lo
__device__ __nv_bfloat16 g_QKVlo[MTOK * 3 * EE];

// =====================================================================
// PTX helpers (family-portable: cp.async / ldmatrix / mma.sync only)
// =====================================================================
__device__ __forceinline__ uint32_t smem_u32(const void* p){
    uint32_t a;
    asm("{ .reg .u64 t; cvta.to.shared.u64 t, %1; cvt.u32.u64 %0, t; }"
        : "=r"(a) : "l"(p));
    return a;
}
__device__ __forceinline__ void cp_async16(uint32_t dst, const void* src){
    asm volatile("cp.async.cg.shared.global [%0], [%1], 16;"
        :: "r"(dst), "l"(src));
}
__device__ __forceinline__ void cp_commit(){
    asm volatile("cp.async.commit_group;");
}
template<int N> __device__ __forceinline__ void cp_wait(){
    asm volatile("cp.async.wait_group %0;" :: "n"(N));
}
__device__ __forceinline__ void ldsm_x4(uint32_t* r, uint32_t a){
    asm volatile("ldmatrix.sync.aligned.m8n8.x4.shared.b16 {%0,%1,%2,%3}, [%4];"
        : "=r"(r[0]), "=r"(r[1]), "=r"(r[2]), "=r"(r[3]) : "r"(a));
}
__device__ __forceinline__ void ldsm_x4_t(uint32_t* r, uint32_t a){
    asm volatile("ldmatrix.sync.aligned.m8n8.x4.trans.shared.b16 {%0,%1,%2,%3}, [%4];"
        : "=r"(r[0]), "=r"(r[1]), "=r"(r[2]), "=r"(r[3]) : "r"(a));
}
__device__ __forceinline__ void mma16816(float* d, const uint32_t* a, const uint32_t* b){
    asm volatile(
        "mma.sync.aligned.m16n8k16.row.col.f32.bf16.bf16.f32 "
        "{%0,%1,%2,%3}, {%4,%5,%6,%7}, {%8,%9}, {%0,%1,%2,%3};"
        : "+f"(d[0]), "+f"(d[1]), "+f"(d[2]), "+f"(d[3])
        : "r"(a[0]), "r"(a[1]), "r"(a[2]), "r"(a[3]), "r"(b[0]), "r"(b[1]));
}
__device__ __forceinline__ uint32_t packsplit(float x, float y, uint32_t& lo){
    __nv_bfloat162 h = __floats2bfloat162_rn(x, y);
    __nv_bfloat162 l = __floats2bfloat162_rn(x - __bfloat162float(h.x),
                                             y - __bfloat162float(h.y));
    lo = *(uint32_t*)&l;
    return *(uint32_t*)&h;
}
// monotone encoding of (float value, col) for argmax-with-first-tiebreak
__device__ __forceinline__ unsigned long long enc_argmax(float v, int col){
    uint32_t u = __float_as_uint(v);
    u = (u & 0x80000000u) ? ~u : (u | 0x80000000u);
    return ((unsigned long long)u << 32) | (uint32_t)(~col);
}
__device__ __forceinline__ int dec_argmax(unsigned long long k){
    return (int)(~(uint32_t)k);
}

// =====================================================================
// Weights: fp32 W[K,N] -> transposed bf16 hi/lo [N,K]
// =====================================================================
__global__ __launch_bounds__(256) void convW_kernel(
    const float* __restrict__ W, __nv_bfloat16* __restrict__ hi,
    __nv_bfloat16* __restrict__ lo, int N, int K)
{
    __shared__ float tile[64][65];
    const int k0 = blockIdx.y * 64;
    const int n0 = blockIdx.x * 64;
    for (int i = threadIdx.x; i < 4096; i += 256) {
        const int r = i >> 6, c = i & 63;
        tile[r][c] = W[(size_t)(k0 + r) * N + n0 + c];
    }
    __syncthreads();
    for (int i = threadIdx.x; i < 4096; i += 256) {
        const int r = i >> 6, c = i & 63;
        const float v = tile[c][r];
        const __nv_bfloat16 h = __float2bfloat16(v);
        const __nv_bfloat16 l = __float2bfloat16(v - __bfloat162float(h));
        const size_t o = (size_t)(n0 + r) * K + k0 + c;
        hi[o] = h;
        lo[o] = l;
    }
}

// =====================================================================
// split-bf16 HMMA GEMM: C[M,N] = A[M,K] @ W[K,N] + bias (+ res)
// CTA 128x128, BK=32, 2-stage cp.async, 2 CTAs/SM, 8 warps (2x4),
// warp tile 64x32, term-major MMA ordering, A-fragment double buffer.
// TERMS=3: hi·hi + hi·lo + lo·hi.  TERMS=2: hi·hi + hi·lo (A-lo unused,
// not even loaded; adds ~1.1e-3 rel err — used only for the QKV GEMM).
// Epilogue: fp32 (Cf) / bf16 hi-lo (outHi/outLo) / argmax partials (part)
// =====================================================================
#define RS 80                      // smem row stride bytes (40 bf16)
#define MATB (128*RS)              // 10240 B per matrix tile
#define STGB (4*MATB)              // 40960 B per stage
#define GEMM_SMEM (512 + 2*STGB)   // bias + 2 stages = 82432 -> 2 CTAs/SM

template<int TERMS>
__global__ __launch_bounds__(256, 2)
void gemm_tc(const __nv_bfloat16* __restrict__ Ahi, const __nv_bfloat16* __restrict__ Alo,
             const __nv_bfloat16* __restrict__ Bhi, const __nv_bfloat16* __restrict__ Blo,
             const float* __restrict__ bias, const float* __restrict__ res,
             float* __restrict__ Cf,
             __nv_bfloat16* __restrict__ outHi, __nv_bfloat16* __restrict__ outLo,
             unsigned long long* __restrict__ part,
             int N, int K)
{
    extern __shared__ __align__(128) char smem[];
    const int tid = threadIdx.x;
    const int lane = tid & 31, wid = tid >> 5;
    const int warp_m = wid & 1, warp_n = wid >> 1;     // 2 x 4
    const int bn = blockIdx.x, bm = blockIdx.y;
    const uint32_t sb = smem_u32(smem);
    float* bsm = (float*)smem;

    if (tid < 128) bsm[tid] = bias[bn * 128 + tid];

    const __nv_bfloat16* gA[2] = { Ahi + (size_t)bm * 128 * K,
                                   Alo + (size_t)bm * 128 * K };
    const __nv_bfloat16* gB[2] = { Bhi + (size_t)bn * 128 * K,
                                   Blo + (size_t)bn * 128 * K };

    const int r0 = tid >> 2, c0 = tid & 3;
    const int r1 = r0 + 64;

    auto load_stage = [&](int s, int k0){
        const uint32_t st = sb + 512 + s * STGB;
        #pragma unroll
        for (int m = 0; m < 2; m++) {
            if (TERMS == 2 && m == 1) break;       // A-lo never used
            const __nv_bfloat16* src = gA[m] + k0;
            const uint32_t d = st + m * MATB;
            cp_async16(d + r0 * RS + c0 * 16, src + (size_t)r0 * K + c0 * 8);
            cp_async16(d + r1 * RS + c0 * 16, src + (size_t)r1 * K + c0 * 8);
        }
        #pragma unroll
        for (int m = 0; m < 2; m++) {
            const __nv_bfloat16* src = gB[m] + k0;
            const uint32_t d = st + (2 + m) * MATB;
            cp_async16(d + r0 * RS + c0 * 16, src + (size_t)r0 * K + c0 * 8);
            cp_async16(d + r1 * RS + c0 * 16, src + (size_t)r1 * K + c0 * 8);
        }
    };

    float acc[4][4][4];
    #pragma unroll
    for (int i = 0; i < 4; i++)
        #pragma unroll
        for (int j = 0; j < 4; j++)
            #pragma unroll
            for (int t = 0; t < 4; t++) acc[i][j][t] = 0.f;

    const int nk = K >> 5;
    load_stage(0, 0);  cp_commit();
    load_stage(1, 32); cp_commit();

    const int l15 = lane & 15;
    const uint32_t aRowOff = (uint32_t)(warp_m * 64 + l15) * RS + (uint32_t)(lane >> 4) * 16;
    const uint32_t bRowOff = (uint32_t)(warp_n * 32 + (lane & 7) + ((lane >> 4) << 3)) * RS
                           + (uint32_t)((lane >> 3) & 1) * 16;

    for (int c = 0; c < nk; c++) {
        if (c == nk - 1) cp_wait<0>(); else cp_wait<1>();
        __syncthreads();

        const uint32_t st = sb + 512 + (c & 1) * STGB;
        #pragma unroll
        for (int kk = 0; kk < 2; kk++) {
            uint32_t bh[2][4], bl[2][4];
            #pragma unroll
            for (int np = 0; np < 2; np++) {
                const uint32_t ba = st + bRowOff + (uint32_t)np * 16 * RS + kk * 32;
                ldsm_x4(bh[np], ba + 2 * MATB);
                ldsm_x4(bl[np], ba + 3 * MATB);
            }
            // A-fragment double buffer: prefetch mt+1 while issuing mt's MMAs
            uint32_t ah[2][4], al[2][4];
            {
                const uint32_t aa0 = st + aRowOff + kk * 32;
                ldsm_x4(ah[0], aa0);
                if (TERMS == 3) ldsm_x4(al[0], aa0 + MATB);
            }
            #pragma unroll
            for (int mt = 0; mt < 4; mt++) {
                const int cur = mt & 1, nxt = cur ^ 1;
                if (mt < 3) {
                    const uint32_t aa = st + aRowOff + (uint32_t)(mt + 1) * 16 * RS + kk * 32;
                    ldsm_x4(ah[nxt], aa);
                    if (TERMS == 3) ldsm_x4(al[nxt], aa + MATB);
                }
                // term-major: 4 independent accs between same-acc MMAs
                #pragma unroll
                for (int nt = 0; nt < 4; nt++)
                    mma16816(acc[mt][nt], ah[cur], &bh[nt >> 1][(nt & 1) * 2]);
                #pragma unroll
                for (int nt = 0; nt < 4; nt++)
                    mma16816(acc[mt][nt], ah[cur], &bl[nt >> 1][(nt & 1) * 2]);
                if (TERMS == 3) {
                    #pragma unroll
                    for (int nt = 0; nt < 4; nt++)
                        mma16816(acc[mt][nt], al[cur], &bh[nt >> 1][(nt & 1) * 2]);
                }
            }
        }
        __syncthreads();
        if (c + 2 < nk) { load_stage(c & 1, (c + 2) * 32); cp_commit(); }
    }

    const int mBase = bm * 128 + warp_m * 64;
    const int nBase = warp_n * 32;
    const int gn0 = bn * 128;

    if (part) {
        // fused argmax partials (gate GEMM): smem two-level reduce, no atomics
        unsigned long long* psm = (unsigned long long*)(smem + 512);  // [128][4]
        #pragma unroll
        for (int mt = 0; mt < 4; mt++) {
            #pragma unroll
            for (int hh = 0; hh < 2; hh++) {
                const int rloc = warp_m * 64 + mt * 16 + (lane >> 2) + hh * 8;
                float bestv = -3.4e38f; int bestc = 0;
                #pragma unroll
                for (int nt = 0; nt < 4; nt++) {
                    const int lc = nBase + nt * 8 + (lane & 3) * 2;
                    const float vx = acc[mt][nt][hh * 2 + 0] + bsm[lc];
                    const float vy = acc[mt][nt][hh * 2 + 1] + bsm[lc + 1];
                    if (vx > bestv) { bestv = vx; bestc = gn0 + lc; }
                    if (vy > bestv) { bestv = vy; bestc = gn0 + lc + 1; }
                }
                unsigned long long key = enc_argmax(bestv, bestc);
                unsigned long long o1 = __shfl_xor_sync(0xffffffffu, key, 1);
                if (o1 > key) key = o1;
                unsigned long long o2 = __shfl_xor_sync(0xffffffffu, key, 2);
                if (o2 > key) key = o2;
                if ((lane & 3) == 0) psm[rloc * 4 + warp_n] = key;
            }
        }
        __syncthreads();
        if (tid < 128) {
            unsigned long long k = psm[tid * 4 + 0];
            unsigned long long t1 = psm[tid * 4 + 1]; if (t1 > k) k = t1;
            unsigned long long t2 = psm[tid * 4 + 2]; if (t2 > k) k = t2;
            unsigned long long t3 = psm[tid * 4 + 3]; if (t3 > k) k = t3;
            part[(size_t)(bm * 128 + tid) * 16 + bn] = k;
        }
        return;
    }

    #pragma unroll
    for (int mt = 0; mt < 4; mt++) {
        #pragma unroll
        for (int nt = 0; nt < 4; nt++) {
            const int row = mBase + mt * 16 + (lane >> 2);
            const int col = nBase + nt * 8 + (lane & 3) * 2;
            #pragma unroll
            for (int hh = 0; hh < 2; hh++) {
                const int m = row + hh * 8;
                float vx = acc[mt][nt][hh * 2 + 0] + bsm[col];
                float vy = acc[mt][nt][hh * 2 + 1] + bsm[col + 1];
                if (outHi) {
                    uint32_t lo;
                    const uint32_t hi = packsplit(vx, vy, lo);
                    *(uint32_t*)(outHi + (size_t)m * N + gn0 + col) = hi;
                    *(uint32_t*)(outLo + (size_t)m * N + gn0 + col) = lo;
                } else {
                    if (res) {
                        const float2 rv = *(const float2*)(res + (size_t)m * N + gn0 + col);
                        vx += rv.x; vy += rv.y;
                    }
                    float2 v; v.x = vx; v.y = vy;
                    *(float2*)(Cf + (size_t)m * N + gn0 + col) = v;
                }
            }
        }
    }
}

// =====================================================================
// HMMA flash attention (causal, unnormalized exp softmax)
// Q: bf16 hi only (2-term QK split). P V: full 3-term split.
// Grid (T/128, NH, B), 256 thr, 2 CTAs/SM.
// =====================================================================
#define SRS 144                     // smem row stride (64 bf16 + 16B pad)
#define ATT_MAT (64*SRS)            // 9216 per matrix (64 rows)
#define ATT_STG (4*ATT_MAT)         // Khi,Klo,Vhi,Vlo = 36864
#define ATT_Q   (128*SRS)           // 18432 (Q hi only)
#define ATT_SMEM (ATT_Q + 2*ATT_STG)   // 92160 -> 2 CTAs/SM

__global__ __launch_bounds__(256, 2)
void flash_mma_kernel(const __nv_bfloat16* __restrict__ QKVhi,
                      const __nv_bfloat16* __restrict__ QKVlo,
                      __nv_bfloat16* __restrict__ Ohi,
                      __nv_bfloat16* __restrict__ Olo)
{
    extern __shared__ __align__(128) char smem[];
    const int tid = threadIdx.x, lane = tid & 31, wid = tid >> 5;
    const int qt = (int)gridDim.x - 1 - (int)blockIdx.x;   // heavy blocks first
    const int q0 = qt * 128;
    const int h = blockIdx.y, b = blockIdx.z;

    const uint32_t sQhi = smem_u32(smem);
    const uint32_t sKV0 = sQhi + ATT_Q;

    const size_t rowStride = 3 * EE;
    const size_t base = ((size_t)b * TT) * rowStride + (size_t)h * DHH;
    const __nv_bfloat16* Qh = QKVhi + base;
    const __nv_bfloat16* Kh = Qh + EE;
    const __nv_bfloat16* Kl = QKVlo + base + EE;
    const __nv_bfloat16* Vh = Qh + 2 * EE;
    const __nv_bfloat16* Vl = QKVlo + base + 2 * EE;

    // ---- Q tile load (128 rows x 8 16B chunks, hi only) ----
    for (int i = tid; i < 1024; i += 256) {
        const int row = i >> 3, c = i & 7;
        const size_t g = (size_t)(q0 + row) * rowStride + c * 8;
        cp_async16(sQhi + row * SRS + c * 16, Qh + g);
    }

    auto load_kv = [&](int s, int k0){
        const uint32_t st = sKV0 + s * ATT_STG;
        for (int i = tid; i < 512; i += 256) {
            const int row = i >> 3, c = i & 7;
            const size_t g = (size_t)(k0 + row) * rowStride + c * 8;
            const uint32_t d = st + row * SRS + c * 16;
            cp_async16(d + 0 * ATT_MAT, Kh + g);
            cp_async16(d + 1 * ATT_MAT, Kl + g);
            cp_async16(d + 2 * ATT_MAT, Vh + g);
            cp_async16(d + 3 * ATT_MAT, Vl + g);
        }
    };

    const int nk = 2 * qt + 2;      // 64-key tiles
    load_kv(0, 0);  cp_commit();    // group 0 carries Q too

    float acc_o[8][4];
    #pragma unroll
    for (int i = 0; i < 8; i++)
        #pragma unroll
        for (int j = 0; j < 4; j++) acc_o[i][j] = 0.f;
    float l0 = 0.f, l1 = 0.f;

    const int l15 = lane & 15;
    const uint32_t qOff = (uint32_t)(wid * 16 + l15) * SRS + (uint32_t)(lane >> 4) * 16;
    const uint32_t kRowOff = (uint32_t)((lane & 7) + ((lane >> 4) << 3)) * SRS
                           + (uint32_t)((lane >> 3) & 1) * 16;
    const uint32_t vRowOff = (uint32_t)((lane & 7) + (((lane >> 3) & 1) << 3)) * SRS
                           + (uint32_t)((lane >> 4) & 1) * 16;

    const int limit = q0 + wid * 16 + 15;   // warp's max row

    for (int c = 0; c < nk; c++) {
        cp_wait<0>();
        __syncthreads();
        if (c + 1 < nk) { load_kv((c + 1) & 1, (c + 1) * 64); cp_commit(); }

        const uint32_t Khi_ = sKV0 + (c & 1) * ATT_STG;
        const uint32_t Klo_ = Khi_ + ATT_MAT;
        const uint32_t Vhi_ = Khi_ + 2 * ATT_MAT;
        const uint32_t Vlo_ = Khi_ + 3 * ATT_MAT;
        const int k0 = c * 64;
        const bool needmask = (k0 + 63) > (q0 + wid * 16);

        // ---- S = Q K^T (Q hi only; 2-term split on K) ----
        float sacc[8][4];
        #pragma unroll
        for (int i = 0; i < 8; i++)
            #pragma unroll
            for (int j = 0; j < 4; j++) sacc[i][j] = 0.f;

        #pragma unroll
        for (int kk = 0; kk < 4; kk++) {
            uint32_t qh[4];
            ldsm_x4(qh, sQhi + qOff + kk * 32);
            #pragma unroll
            for (int np = 0; np < 4; np++) {
                if (k0 + np * 16 > limit) break;   // fully masked 16-col tile
                const uint32_t ba = kRowOff + (uint32_t)np * 16 * SRS + kk * 32;
                uint32_t bh[4], bl[4];
                ldsm_x4(bh, Khi_ + ba);
                ldsm_x4(bl, Klo_ + ba);
                #pragma unroll
                for (int t = 0; t < 2; t++) {
                    mma16816(sacc[2 * np + t], qh, &bh[2 * t]);
                    mma16816(sacc[2 * np + t], qh, &bl[2 * t]);
                }
            }
        }

        // ---- unnormalized softmax: p = exp2(s * 0.125/ln2), masked -> 0 ----
        const int rbase = q0 + wid * 16 + (lane >> 2);
        float s0 = 0.f, s1 = 0.f;
        #pragma unroll
        for (int nt = 0; nt < 8; nt++) {
            const int col = k0 + nt * 8 + 2 * (lane & 3);
            if (k0 + (nt >> 1) * 16 > limit) {
                sacc[nt][0] = sacc[nt][1] = sacc[nt][2] = sacc[nt][3] = 0.f;
                continue;
            }
            #pragma unroll
            for (int j = 0; j < 4; j++) {
                bool dead = false;
                if (needmask) {
                    const int cc = col + (j & 1);
                    const int rr = rbase + (j >> 1) * 8;
                    dead = (cc > rr);
                }
                const float v = dead ? 0.f
                    : exp2f(sacc[nt][j] * 0.18033688011112042f);
                sacc[nt][j] = v;
            }
            s0 += sacc[nt][0] + sacc[nt][1];
            s1 += sacc[nt][2] + sacc[nt][3];
        }
        s0 += __shfl_xor_sync(0xffffffffu, s0, 1);
        s0 += __shfl_xor_sync(0xffffffffu, s0, 2);
        s1 += __shfl_xor_sync(0xffffffffu, s1, 1);
        s1 += __shfl_xor_sync(0xffffffffu, s1, 2);
        l0 += s0; l1 += s1;

        // ---- O += P V (split P, split V) ----
        #pragma unroll
        for (int kkp = 0; kkp < 4; kkp++) {
            if (k0 + kkp * 16 > limit) break;      // P == 0 for these keys
            uint32_t phi[4], plo[4];
            phi[0] = packsplit(sacc[2*kkp][0],   sacc[2*kkp][1],   plo[0]);
            phi[1] = packsplit(sacc[2*kkp][2],   sacc[2*kkp][3],   plo[1]);
            phi[2] = packsplit(sacc[2*kkp+1][0], sacc[2*kkp+1][1], plo[2]);
            phi[3] = packsplit(sacc[2*kkp+1][2], sacc[2*kkp+1][3], plo[3]);
            #pragma unroll
            for (int np = 0; np < 4; np++) {
                const uint32_t va = (uint32_t)(kkp * 16) * SRS + vRowOff + np * 32;
                uint32_t vh[4], vl[4];
                ldsm_x4_t(vh, Vhi_ + va);
                ldsm_x4_t(vl, Vlo_ + va);
                #pragma unroll
                for (int t = 0; t < 2; t++) {
                    mma16816(acc_o[2 * np + t], phi, &vh[2 * t]);
                    mma16816(acc_o[2 * np + t], phi, &vl[2 * t]);
                    mma16816(acc_o[2 * np + t], plo, &vh[2 * t]);
                }
            }
        }
    }

    // ---- epilogue: O / l, write bf16 hi/lo into GEMM A buffers ----
    const float inv0 = 1.f / l0, inv1 = 1.f / l1;
    const int row0 = b * TT + q0 + wid * 16 + (lane >> 2);
    const int colb = h * DHH + 2 * (lane & 3);
    #pragma unroll
    for (int nt = 0; nt < 8; nt++) {
        const int col = colb + nt * 8;
        uint32_t lo;
        uint32_t hi = packsplit(acc_o[nt][0] * inv0, acc_o[nt][1] * inv0, lo);
        *(uint32_t*)(Ohi + (size_t)row0 * EE + col) = hi;
        *(uint32_t*)(Olo + (size_t)row0 * EE + col) = lo;
        hi = packsplit(acc_o[nt][2] * inv1, acc_o[nt][3] * inv1, lo);
        *(uint32_t*)(Ohi + (size_t)(row0 + 8) * EE + col) = hi;
        *(uint32_t*)(Olo + (size_t)(row0 + 8) * EE + col) = lo;
    }
}

// =====================================================================
// LayerNorm: block per row, 256 threads; optional fp32 + bf16 hi/lo out
// =====================================================================
__global__ __launch_bounds__(256) void layernorm_kernel(
    const float* __restrict__ x, const float* __restrict__ gam,
    const float* __restrict__ bet, float* __restrict__ outF,
    __nv_bfloat16* __restrict__ outHi, __nv_bfloat16* __restrict__ outLo)
{
    const int row = blockIdx.x;
    const int tid = threadIdx.x;
    const float4 xv = *(const float4*)(x + (size_t)row * EE + tid * 4);

    __shared__ float red[8];

    float s = xv.x + xv.y + xv.z + xv.w;
    #pragma unroll
    for (int o = 16; o; o >>= 1) s += __shfl_xor_sync(0xffffffffu, s, o);
    if ((tid & 31) == 0) red[tid >> 5] = s;
    __syncthreads();
    float tot = 0.f;
    #pragma unroll
    for (int i = 0; i < 8; i++) tot += red[i];
    const float mu = tot * (1.0f / (float)EE);
    __syncthreads();

    const float dx = xv.x - mu, dy = xv.y - mu, dz = xv.z - mu, dw = xv.w - mu;
    float ss = dx*dx + dy*dy + dz*dz + dw*dw;
    #pragma unroll
    for (int o = 16; o; o >>= 1) ss += __shfl_xor_sync(0xffffffffu, ss, o);
    if ((tid & 31) == 0) red[tid >> 5] = ss;
    __syncthreads();
    float sst = 0.f;
    #pragma unroll
    for (int i = 0; i < 8; i++) sst += red[i];
    const float inv = rsqrtf(sst * (1.0f / (float)EE) + LN_EPS);

    const float4 gv = *(const float4*)(gam + tid * 4);
    const float4 bv = *(const float4*)(bet + tid * 4);
    float4 ov;
    ov.x = dx * inv * gv.x + bv.x;
    ov.y = dy * inv * gv.y + bv.y;
    ov.z = dz * inv * gv.z + bv.z;
    ov.w = dw * inv * gv.w + bv.w;
    if (outF) *(float4*)(outF + (size_t)row * EE + tid * 4) = ov;
    uint32_t lo0, lo1;
    const uint32_t hi0 = packsplit(ov.x, ov.y, lo0);
    const uint32_t hi1 = packsplit(ov.z, ov.w, lo1);
    uint2 hv; hv.x = hi0; hv.y = hi1;
    uint2 lv; lv.x = lo0; lv.y = lo1;
    *(uint2*)(outHi + (size_t)row * EE + tid * 4) = hv;
    *(uint2*)(outLo + (size_t)row * EE + tid * 4) = lv;
}

// =====================================================================
// Argmax reduce over 16 partials per row
// =====================================================================
__global__ __launch_bounds__(256) void argmax_reduce_kernel(
    const unsigned long long* __restrict__ part, int* __restrict__ idx)
{
    const int m = blockIdx.x * 256 + threadIdx.x;
    const unsigned long long* p = part + (size_t)m * 16;
    unsigned long long k = p[0];
    #pragma unroll
    for (int i = 1; i < 16; i++) {
        const unsigned long long v = p[i];
        if (v > k) k = v;
    }
    idx[m] = dec_argmax(k);
}

// =====================================================================
// MoE routing: clear-hist / hist / scan / scatter (from g_idx)
// =====================================================================
__global__ __launch_bounds__(256) void hist_clear_kernel(int* __restrict__ hist)
{
    hist[blockIdx.x * 256 + threadIdx.x] = 0;
}

__global__ __launch_bounds__(256) void hist_kernel(
    const int* __restrict__ idx, int* __restrict__ hist)
{
    const int t = blockIdx.x * 256 + threadIdx.x;
    atomicAdd(&hist[idx[t]], 1);
}

__global__ __launch_bounds__(1024) void scan_kernel(
    const int* __restrict__ hist, int* __restrict__ cursor)
{
    __shared__ int warpsum[32];
    const int tid = threadIdx.x;
    const int lane = tid & 31, wid = tid >> 5;
    const int v0 = hist[2 * tid], v1 = hist[2 * tid + 1];
    const int tsum = v0 + v1;
    int x = tsum;
    #pragma unroll
    for (int o = 1; o < 32; o <<= 1) {
        const int y = __shfl_up_sync(0xffffffffu, x, o);
        if (lane >= o) x += y;
    }
    if (lane == 31) warpsum[wid] = x;
    __syncthreads();
    if (wid == 0) {
        int w = warpsum[lane];
        #pragma unroll
        for (int o = 1; o < 32; o <<= 1) {
            const int y = __shfl_up_sync(0xffffffffu, w, o);
            if (lane >= o) w += y;
        }
        warpsum[lane] = w;
    }
    __syncthreads();
    const int base = (wid > 0 ? warpsum[wid - 1] : 0) + (x - tsum);
    cursor[2 * tid] = base;
    cursor[2 * tid + 1] = base + v0;
}

__global__ __launch_bounds__(256) void scatter_kernel(
    const int* __restrict__ idx, int* __restrict__ cursor,
    int* __restrict__ perm)
{
    const int t = blockIdx.x * 256 + threadIdx.x;
    const int pos = atomicAdd(&cursor[idx[t]], 1);
    perm[pos] = t;
}

// =====================================================================
// MoE: one block per (expert-sorted) token
// =====================================================================
__global__ __launch_bounds__(256) void moe_kernel(
    const float* __restrict__ h, const int* __restrict__ idx,
    const int* __restrict__ perm,
    const float* __restrict__ w1, const float* __restrict__ b1,
    const float* __restrict__ w2, const float* __restrict__ b2,
    float* __restrict__ out)
{
    const int token = perm[blockIdx.x];
    const int tid = threadIdx.x;
    const int e = idx[token];

    __shared__ float xs[EE];
    __shared__ float partial[HIDD][17];
    __shared__ float hm[HIDD];

    const float* hrow = h + (size_t)token * EE;
    for (int i = tid; i < EE; i += 256) xs[i] = hrow[i];
    __syncthreads();

    const int hcol = tid & 15;
    const int grp  = tid >> 4;
    const float* w1p = w1 + (size_t)e * EE * HIDD;
    float acc = 0.f;
    for (int i = grp; i < EE; i += 16)
        acc += xs[i] * w1p[(size_t)i * HIDD + hcol];
    partial[hcol][grp] = acc;
    __syncthreads();

    if (tid < HIDD) {
        float s = b1[(size_t)e * HIDD + tid];
        #pragma unroll
        for (int g2 = 0; g2 < 16; g2++) s += partial[tid][g2];
        hm[tid] = 0.5f * s * (1.0f + erff(s * 0.70710678118654752f));
    }
    __syncthreads();

    float hreg[HIDD];
    #pragma unroll
    for (int k = 0; k < HIDD; k++) hreg[k] = hm[k];

    const float* w2p = w2 + (size_t)e * HIDD * EE;
    const float* b2p = b2 + (size_t)e * EE;
    float* orow = out + (size_t)token * EE;
    for (int j = tid; j < EE; j += 256) {
        float s = b2p[j];
        #pragma unroll
        for (int k = 0; k < HIDD; k++) s += hreg[k] * w2p[(size_t)k * EE + j];
        orow[j] += s;
    }
}

// =====================================================================
// launch
// =====================================================================
extern "C" void kernel_launch(void* const* d_in, const int* in_sizes, int n_in,
                              void* d_out, int out_size)
{
    const float* x      = (const float*)d_in[0];
    const float* ln1_g  = (const float*)d_in[1];
    const float* ln1_b  = (const float*)d_in[2];
    const float* ln2_g  = (const float*)d_in[3];
    const float* ln2_b  = (const float*)d_in[4];
    const float* qkv_w  = (const float*)d_in[5];
    const float* qkv_b  = (const float*)d_in[6];
    const float* proj_w = (const float*)d_in[7];
    const float* proj_b = (const float*)d_in[8];
    const float* gate_w = (const float*)d_in[9];
    const float* gate_b = (const float*)d_in[10];
    const float* w1     = (const float*)d_in[11];
    const float* b1     = (const float*)d_in[12];
    const float* w2     = (const float*)d_in[13];
    const float* w2b    = (const float*)d_in[14];
    float* out = (float*)d_out;

    void *p_h, *p_part, *p_idx, *p_hist, *p_cur, *p_perm,
         *p_ah, *p_al, *p_bh, *p_bl, *p_qh, *p_ql;
    cudaGetSymbolAddress(&p_h, g_h);
    cudaGetSymbolAddress(&p_part, g_part);
    cudaGetSymbolAddress(&p_idx, g_idx);
    cudaGetSymbolAddress(&p_hist, g_hist);
    cudaGetSymbolAddress(&p_cur, g_cursor);
    cudaGetSymbolAddress(&p_perm, g_perm);
    cudaGetSymbolAddress(&p_ah, g_Ahi);
    cudaGetSymbolAddress(&p_al, g_Alo);
    cudaGetSymbolAddress(&p_bh, g_Bhi);
    cudaGetSymbolAddress(&p_bl, g_Blo);
    cudaGetSymbolAddress(&p_qh, g_QKVhi);
    cudaGetSymbolAddress(&p_ql, g_QKVlo);
    float* bh      = (float*)p_h;
    unsigned long long* bpart = (unsigned long long*)p_part;
    int*   bidx    = (int*)p_idx;
    int*   hist    = (int*)p_hist;
    int*   cursor  = (int*)p_cur;
    int*   perm    = (int*)p_perm;
    __nv_bfloat16* Ahi = (__nv_bfloat16*)p_ah;
    __nv_bfloat16* Alo = (__nv_bfloat16*)p_al;
    __nv_bfloat16* Bhi = (__nv_bfloat16*)p_bh;
    __nv_bfloat16* Blo = (__nv_bfloat16*)p_bl;
    __nv_bfloat16* QKVhi = (__nv_bfloat16*)p_qh;
    __nv_bfloat16* QKVlo = (__nv_bfloat16*)p_ql;

    cudaFuncSetAttribute(gemm_tc<2>, cudaFuncAttributeMaxDynamicSharedMemorySize, GEMM_SMEM);
    cudaFuncSetAttribute(gemm_tc<3>, cudaFuncAttributeMaxDynamicSharedMemorySize, GEMM_SMEM);
    cudaFuncSetAttribute(flash_mma_kernel, cudaFuncAttributeMaxDynamicSharedMemorySize, ATT_SMEM);

    // 1) LN1(x) -> bf16 hi/lo A operand
    layernorm_kernel<<<MTOK, 256>>>(x, ln1_g, ln1_b, nullptr, Ahi, Alo);

    // 2) qkv = h @ qkv_w + qkv_b -> bf16 hi/lo  (2-term split: A-lo dropped)
    convW_kernel<<<dim3(3*EE/64, EE/64), 256>>>(qkv_w, Bhi, Blo, 3*EE, EE);
    gemm_tc<2><<<dim3(3*EE/128, MTOK/128), 256, GEMM_SMEM>>>(
        Ahi, Alo, Bhi, Blo, qkv_b, nullptr, nullptr, QKVhi, QKVlo, nullptr, 3*EE, EE);

    // 3) attention -> bf16 hi/lo into A operand buffers
    flash_mma_kernel<<<dim3(TT/128, NHH, BB), 256, ATT_SMEM>>>(QKVhi, QKVlo, Ahi, Alo);

    // 4) xmid = x + attn @ proj_w + proj_b -> d_out (fp32, full 3-term)
    convW_kernel<<<dim3(EE/64, EE/64), 256>>>(proj_w, Bhi, Blo, EE, EE);
    gemm_tc<3><<<dim3(EE/128, MTOK/128), 256, GEMM_SMEM>>>(
        Ahi, Alo, Bhi, Blo, proj_b, x, out, nullptr, nullptr, nullptr, EE, EE);

    // 5) LN2 -> fp32 (MoE) + bf16 hi/lo (gate GEMM)
    layernorm_kernel<<<MTOK, 256>>>(out, ln2_g, ln2_b, bh, Ahi, Alo);

    // 6) gate GEMM with fused argmax partials (full 3-term: argmax safety)
    convW_kernel<<<dim3(NEE/64, EE/64), 256>>>(gate_w, Bhi, Blo, NEE, EE);
    gemm_tc<3><<<dim3(NEE/128, MTOK/128), 256, GEMM_SMEM>>>(
        Ahi, Alo, Bhi, Blo, gate_b, nullptr, nullptr, nullptr, nullptr, bpart, NEE, EE);

    // 7) idx = reduce(partials); expert-locality sort
    argmax_reduce_kernel<<<MTOK/256, 256>>>(bpart, bidx);
    hist_clear_kernel<<<NEE/256, 256>>>(hist);
    hist_kernel<<<MTOK/256, 256>>>(bidx, hist);
    scan_kernel<<<1, 1024>>>(hist, cursor);
    scatter_kernel<<<MTOK/256, 256>>>(bidx, cursor, perm);

    // 8) d_out += moe(h, idx) over expert-sorted tokens (block per token)
    moe_kernel<<<MTOK, 256>>>(bh, bidx, perm, w1, b1, w2, w2b, out);
}

// round 16
// speedup vs baseline: 1.2550x; 1.0342x over previous
#include <cuda_runtime.h>
#include <cuda_bf16.h>
#include <math.h>
#include <stdint.h>

// ---------------- problem constants ----------------
#define BB 4
#define TT 2048
#define EE 1024
#define NHH 16
#define DHH 64
#define NEE 2048
#define HIDD 16
#define MTOK (BB*TT)          // 8192 tokens
#define LN_EPS 1e-5f

// ---------------- scratch (device globals; no runtime allocation) ----------
__device__ float g_h[MTOK * EE];          // LN2 output fp32 (for MoE)
__device__ unsigned long long g_part[MTOK * 16];  // per-(row, bn-tile) argmax partials
__device__ int   g_idx[MTOK];             // argmax expert per token
__device__ int   g_hist[NEE];
__device__ int   g_cursor[NEE];
__device__ int   g_perm[MTOK];
__device__ __nv_bfloat16 g_Ahi[MTOK * EE];       // GEMM A operand hi [M,K]
__device__ __nv_bfloat16 g_Alo[MTOK * EE];
__device__ __nv_bfloat16 g_Bhi[3 * EE * EE];     // weights transposed [N,K]
__device__ __nv_bfloat16 g_Blo[3 * EE * EE];
__device__ __nv_bfloat16 g_QKVhi[MTOK * 3 * EE]; // qkv bf16 hi/lo
__device__ __nv_bfloat16 g_QKVlo[MTOK * 3 * EE];

// =====================================================================
// PTX helpers (family-portable: cp.async / ldmatrix / mma.sync only)
// =====================================================================
__device__ __forceinline__ uint32_t smem_u32(const void* p){
    uint32_t a;
    asm("{ .reg .u64 t; cvta.to.shared.u64 t, %1; cvt.u32.u64 %0, t; }"
        : "=r"(a) : "l"(p));
    return a;
}
__device__ __forceinline__ void cp_async16(uint32_t dst, const void* src){
    asm volatile("cp.async.cg.shared.global [%0], [%1], 16;"
        :: "r"(dst), "l"(src));
}
__device__ __forceinline__ void cp_commit(){
    asm volatile("cp.async.commit_group;");
}
template<int N> __device__ __forceinline__ void cp_wait(){
    asm volatile("cp.async.wait_group %0;" :: "n"(N));
}
__device__ __forceinline__ void ldsm_x4(uint32_t* r, uint32_t a){
    asm volatile("ldmatrix.sync.aligned.m8n8.x4.shared.b16 {%0,%1,%2,%3}, [%4];"
        : "=r"(r[0]), "=r"(r[1]), "=r"(r[2]), "=r"(r[3]) : "r"(a));
}
__device__ __forceinline__ void ldsm_x4_t(uint32_t* r, uint32_t a){
    asm volatile("ldmatrix.sync.aligned.m8n8.x4.trans.shared.b16 {%0,%1,%2,%3}, [%4];"
        : "=r"(r[0]), "=r"(r[1]), "=r"(r[2]), "=r"(r[3]) : "r"(a));
}
__device__ __forceinline__ void mma16816(float* d, const uint32_t* a, const uint32_t* b){
    asm volatile(
        "mma.sync.aligned.m16n8k16.row.col.f32.bf16.bf16.f32 "
        "{%0,%1,%2,%3}, {%4,%5,%6,%7}, {%8,%9}, {%0,%1,%2,%3};"
        : "+f"(d[0]), "+f"(d[1]), "+f"(d[2]), "+f"(d[3])
        : "r"(a[0]), "r"(a[1]), "r"(a[2]), "r"(a[3]), "r"(b[0]), "r"(b[1]));
}
__device__ __forceinline__ uint32_t packsplit(float x, float y, uint32_t& lo){
    __nv_bfloat162 h = __floats2bfloat162_rn(x, y);
    __nv_bfloat162 l = __floats2bfloat162_rn(x - __bfloat162float(h.x),
                                             y - __bfloat162float(h.y));
    lo = *(uint32_t*)&l;
    return *(uint32_t*)&h;
}
// monotone encoding of (float value, col) for argmax-with-first-tiebreak
__device__ __forceinline__ unsigned long long enc_argmax(float v, int col){
    uint32_t u = __float_as_uint(v);
    u = (u & 0x80000000u) ? ~u : (u | 0x80000000u);
    return ((unsigned long long)u << 32) | (uint32_t)(~col);
}
__device__ __forceinline__ int dec_argmax(unsigned long long k){
    return (int)(~(uint32_t)k);
}

// =====================================================================
// Weights: fp32 W[K,N] -> transposed bf16 hi/lo [N,K]
// =====================================================================
__global__ __launch_bounds__(256) void convW_kernel(
    const float* __restrict__ W, __nv_bfloat16* __restrict__ hi,
    __nv_bfloat16* __restrict__ lo, int N, int K)
{
    __shared__ float tile[64][65];
    const int k0 = blockIdx.y * 64;
    const int n0 = blockIdx.x * 64;
    for (int i = threadIdx.x; i < 4096; i += 256) {
        const int r = i >> 6, c = i & 63;
        tile[r][c] = W[(size_t)(k0 + r) * N + n0 + c];
    }
    __syncthreads();
    for (int i = threadIdx.x; i < 4096; i += 256) {
        const int r = i >> 6, c = i & 63;
        const float v = tile[c][r];
        const __nv_bfloat16 h = __float2bfloat16(v);
        const __nv_bfloat16 l = __float2bfloat16(v - __bfloat162float(h));
        const size_t o = (size_t)(n0 + r) * K + k0 + c;
        hi[o] = h;
        lo[o] = l;
    }
}

// =====================================================================
// split-bf16 HMMA GEMM: C[M,N] = A[M,K] @ W[K,N] + bias (+ res)
// CTA 128x128, BK=32, 2-stage cp.async, 2 CTAs/SM, 8 warps (2x4),
// warp tile 64x32, term-major MMA ordering, A-fragment double buffer.
// TERMS=3: hi·hi + hi·lo + lo·hi.  TERMS=2: hi·hi + hi·lo (A-lo unused,
// not even loaded; adds ~1.1e-3 rel err — used only for the QKV GEMM).
// Epilogue: fp32 (Cf) / bf16 hi-lo (outHi/outLo) / argmax partials (part)
// =====================================================================
#define RS 80                      // smem row stride bytes (40 bf16)
#define MATB (128*RS)              // 10240 B per matrix tile
#define STGB (4*MATB)              // 40960 B per stage
#define GEMM_SMEM (512 + 2*STGB)   // bias + 2 stages = 82432 -> 2 CTAs/SM

template<int TERMS>
__global__ __launch_bounds__(256, 2)
void gemm_tc(const __nv_bfloat16* __restrict__ Ahi, const __nv_bfloat16* __restrict__ Alo,
             const __nv_bfloat16* __restrict__ Bhi, const __nv_bfloat16* __restrict__ Blo,
             const float* __restrict__ bias, const float* __restrict__ res,
             float* __restrict__ Cf,
             __nv_bfloat16* __restrict__ outHi, __nv_bfloat16* __restrict__ outLo,
             unsigned long long* __restrict__ part,
             int N, int K)
{
    extern __shared__ __align__(128) char smem[];
    const int tid = threadIdx.x;
    const int lane = tid & 31, wid = tid >> 5;
    const int warp_m = wid & 1, warp_n = wid >> 1;     // 2 x 4
    const int bn = blockIdx.x, bm = blockIdx.y;
    const uint32_t sb = smem_u32(smem);
    float* bsm = (float*)smem;

    if (tid < 128) bsm[tid] = bias[bn * 128 + tid];

    const __nv_bfloat16* gA[2] = { Ahi + (size_t)bm * 128 * K,
                                   Alo + (size_t)bm * 128 * K };
    const __nv_bfloat16* gB[2] = { Bhi + (size_t)bn * 128 * K,
                                   Blo + (size_t)bn * 128 * K };

    const int r0 = tid >> 2, c0 = tid & 3;
    const int r1 = r0 + 64;

    auto load_stage = [&](int s, int k0){
        const uint32_t st = sb + 512 + s * STGB;
        #pragma unroll
        for (int m = 0; m < 2; m++) {
            if (TERMS == 2 && m == 1) break;       // A-lo never used
            const __nv_bfloat16* src = gA[m] + k0;
            const uint32_t d = st + m * MATB;
            cp_async16(d + r0 * RS + c0 * 16, src + (size_t)r0 * K + c0 * 8);
            cp_async16(d + r1 * RS + c0 * 16, src + (size_t)r1 * K + c0 * 8);
        }
        #pragma unroll
        for (int m = 0; m < 2; m++) {
            const __nv_bfloat16* src = gB[m] + k0;
            const uint32_t d = st + (2 + m) * MATB;
            cp_async16(d + r0 * RS + c0 * 16, src + (size_t)r0 * K + c0 * 8);
            cp_async16(d + r1 * RS + c0 * 16, src + (size_t)r1 * K + c0 * 8);
        }
    };

    float acc[4][4][4];
    #pragma unroll
    for (int i = 0; i < 4; i++)
        #pragma unroll
        for (int j = 0; j < 4; j++)
            #pragma unroll
            for (int t = 0; t < 4; t++) acc[i][j][t] = 0.f;

    const int nk = K >> 5;
    load_stage(0, 0);  cp_commit();
    load_stage(1, 32); cp_commit();

    const int l15 = lane & 15;
    const uint32_t aRowOff = (uint32_t)(warp_m * 64 + l15) * RS + (uint32_t)(lane >> 4) * 16;
    const uint32_t bRowOff = (uint32_t)(warp_n * 32 + (lane & 7) + ((lane >> 4) << 3)) * RS
                           + (uint32_t)((lane >> 3) & 1) * 16;

    for (int c = 0; c < nk; c++) {
        if (c == nk - 1) cp_wait<0>(); else cp_wait<1>();
        __syncthreads();

        const uint32_t st = sb + 512 + (c & 1) * STGB;
        #pragma unroll
        for (int kk = 0; kk < 2; kk++) {
            uint32_t bh[2][4], bl[2][4];
            #pragma unroll
            for (int np = 0; np < 2; np++) {
                const uint32_t ba = st + bRowOff + (uint32_t)np * 16 * RS + kk * 32;
                ldsm_x4(bh[np], ba + 2 * MATB);
                ldsm_x4(bl[np], ba + 3 * MATB);
            }
            // A-fragment double buffer: prefetch mt+1 while issuing mt's MMAs
            uint32_t ah[2][4], al[2][4];
            {
                const uint32_t aa0 = st + aRowOff + kk * 32;
                ldsm_x4(ah[0], aa0);
                if (TERMS == 3) ldsm_x4(al[0], aa0 + MATB);
            }
            #pragma unroll
            for (int mt = 0; mt < 4; mt++) {
                const int cur = mt & 1, nxt = cur ^ 1;
                if (mt < 3) {
                    const uint32_t aa = st + aRowOff + (uint32_t)(mt + 1) * 16 * RS + kk * 32;
                    ldsm_x4(ah[nxt], aa);
                    if (TERMS == 3) ldsm_x4(al[nxt], aa + MATB);
                }
                // term-major: 4 independent accs between same-acc MMAs
                #pragma unroll
                for (int nt = 0; nt < 4; nt++)
                    mma16816(acc[mt][nt], ah[cur], &bh[nt >> 1][(nt & 1) * 2]);
                #pragma unroll
                for (int nt = 0; nt < 4; nt++)
                    mma16816(acc[mt][nt], ah[cur], &bl[nt >> 1][(nt & 1) * 2]);
                if (TERMS == 3) {
                    #pragma unroll
                    for (int nt = 0; nt < 4; nt++)
                        mma16816(acc[mt][nt], al[cur], &bh[nt >> 1][(nt & 1) * 2]);
                }
            }
        }
        __syncthreads();
        if (c + 2 < nk) { load_stage(c & 1, (c + 2) * 32); cp_commit(); }
    }

    const int mBase = bm * 128 + warp_m * 64;
    const int nBase = warp_n * 32;
    const int gn0 = bn * 128;

    if (part) {
        // fused argmax partials (gate GEMM): smem two-level reduce, no atomics
        unsigned long long* psm = (unsigned long long*)(smem + 512);  // [128][4]
        #pragma unroll
        for (int mt = 0; mt < 4; mt++) {
            #pragma unroll
            for (int hh = 0; hh < 2; hh++) {
                const int rloc = warp_m * 64 + mt * 16 + (lane >> 2) + hh * 8;
                float bestv = -3.4e38f; int bestc = 0;
                #pragma unroll
                for (int nt = 0; nt < 4; nt++) {
                    const int lc = nBase + nt * 8 + (lane & 3) * 2;
                    const float vx = acc[mt][nt][hh * 2 + 0] + bsm[lc];
                    const float vy = acc[mt][nt][hh * 2 + 1] + bsm[lc + 1];
                    if (vx > bestv) { bestv = vx; bestc = gn0 + lc; }
                    if (vy > bestv) { bestv = vy; bestc = gn0 + lc + 1; }
                }
                unsigned long long key = enc_argmax(bestv, bestc);
                unsigned long long o1 = __shfl_xor_sync(0xffffffffu, key, 1);
                if (o1 > key) key = o1;
                unsigned long long o2 = __shfl_xor_sync(0xffffffffu, key, 2);
                if (o2 > key) key = o2;
                if ((lane & 3) == 0) psm[rloc * 4 + warp_n] = key;
            }
        }
        __syncthreads();
        if (tid < 128) {
            unsigned long long k = psm[tid * 4 + 0];
            unsigned long long t1 = psm[tid * 4 + 1]; if (t1 > k) k = t1;
            unsigned long long t2 = psm[tid * 4 + 2]; if (t2 > k) k = t2;
            unsigned long long t3 = psm[tid * 4 + 3]; if (t3 > k) k = t3;
            part[(size_t)(bm * 128 + tid) * 16 + bn] = k;
        }
        return;
    }

    #pragma unroll
    for (int mt = 0; mt < 4; mt++) {
        #pragma unroll
        for (int nt = 0; nt < 4; nt++) {
            const int row = mBase + mt * 16 + (lane >> 2);
            const int col = nBase + nt * 8 + (lane & 3) * 2;
            #pragma unroll
            for (int hh = 0; hh < 2; hh++) {
                const int m = row + hh * 8;
                float vx = acc[mt][nt][hh * 2 + 0] + bsm[col];
                float vy = acc[mt][nt][hh * 2 + 1] + bsm[col + 1];
                if (outHi) {
                    uint32_t lo;
                    const uint32_t hi = packsplit(vx, vy, lo);
                    *(uint32_t*)(outHi + (size_t)m * N + gn0 + col) = hi;
                    *(uint32_t*)(outLo + (size_t)m * N + gn0 + col) = lo;
                } else {
                    if (res) {
                        const float2 rv = *(const float2*)(res + (size_t)m * N + gn0 + col);
                        vx += rv.x; vy += rv.y;
                    }
                    float2 v; v.x = vx; v.y = vy;
                    *(float2*)(Cf + (size_t)m * N + gn0 + col) = v;
                }
            }
        }
    }
}

// =====================================================================
// HMMA flash attention (causal, unnormalized exp softmax)
// QK: q_hi · k_hi only (1-term; q_lo & k_lo dropped — err << V-path err).
// P V: full 3-term split. Grid (T/128, NH, B), 256 thr, 2 CTAs/SM.
// =====================================================================
#define SRS 144                     // smem row stride (64 bf16 + 16B pad)
#define ATT_MAT (64*SRS)            // 9216 per matrix (64 rows)
#define ATT_STG (3*ATT_MAT)         // Khi,Vhi,Vlo = 27648
#define ATT_Q   (128*SRS)           // 18432 (Q hi only)
#define ATT_SMEM (ATT_Q + 2*ATT_STG)   // 73728 -> 2 CTAs/SM

__global__ __launch_bounds__(256, 2)
void flash_mma_kernel(const __nv_bfloat16* __restrict__ QKVhi,
                      const __nv_bfloat16* __restrict__ QKVlo,
                      __nv_bfloat16* __restrict__ Ohi,
                      __nv_bfloat16* __restrict__ Olo)
{
    extern __shared__ __align__(128) char smem[];
    const int tid = threadIdx.x, lane = tid & 31, wid = tid >> 5;
    const int qt = (int)gridDim.x - 1 - (int)blockIdx.x;   // heavy blocks first
    const int q0 = qt * 128;
    const int h = blockIdx.y, b = blockIdx.z;

    const uint32_t sQhi = smem_u32(smem);
    const uint32_t sKV0 = sQhi + ATT_Q;

    const size_t rowStride = 3 * EE;
    const size_t base = ((size_t)b * TT) * rowStride + (size_t)h * DHH;
    const __nv_bfloat16* Qh = QKVhi + base;
    const __nv_bfloat16* Kh = Qh + EE;
    const __nv_bfloat16* Vh = Qh + 2 * EE;
    const __nv_bfloat16* Vl = QKVlo + base + 2 * EE;

    // ---- Q tile load (128 rows x 8 16B chunks, hi only) ----
    for (int i = tid; i < 1024; i += 256) {
        const int row = i >> 3, c = i & 7;
        const size_t g = (size_t)(q0 + row) * rowStride + c * 8;
        cp_async16(sQhi + row * SRS + c * 16, Qh + g);
    }

    auto load_kv = [&](int s, int k0){
        const uint32_t st = sKV0 + s * ATT_STG;
        for (int i = tid; i < 512; i += 256) {
            const int row = i >> 3, c = i & 7;
            const size_t g = (size_t)(k0 + row) * rowStride + c * 8;
            const uint32_t d = st + row * SRS + c * 16;
            cp_async16(d + 0 * ATT_MAT, Kh + g);
            cp_async16(d + 1 * ATT_MAT, Vh + g);
            cp_async16(d + 2 * ATT_MAT, Vl + g);
        }
    };

    const int nk = 2 * qt + 2;      // 64-key tiles
    load_kv(0, 0);  cp_commit();    // group 0 carries Q too

    float acc_o[8][4];
    #pragma unroll
    for (int i = 0; i < 8; i++)
        #pragma unroll
        for (int j = 0; j < 4; j++) acc_o[i][j] = 0.f;
    float l0 = 0.f, l1 = 0.f;

    const int l15 = lane & 15;
    const uint32_t qOff = (uint32_t)(wid * 16 + l15) * SRS + (uint32_t)(lane >> 4) * 16;
    const uint32_t kRowOff = (uint32_t)((lane & 7) + ((lane >> 4) << 3)) * SRS
                           + (uint32_t)((lane >> 3) & 1) * 16;
    const uint32_t vRowOff = (uint32_t)((lane & 7) + (((lane >> 3) & 1) << 3)) * SRS
                           + (uint32_t)((lane >> 4) & 1) * 16;

    const int limit = q0 + wid * 16 + 15;   // warp's max row

    for (int c = 0; c < nk; c++) {
        cp_wait<0>();
        __syncthreads();
        if (c + 1 < nk) { load_kv((c + 1) & 1, (c + 1) * 64); cp_commit(); }

        const uint32_t Khi_ = sKV0 + (c & 1) * ATT_STG;
        const uint32_t Vhi_ = Khi_ + 1 * ATT_MAT;
        const uint32_t Vlo_ = Khi_ + 2 * ATT_MAT;
        const int k0 = c * 64;
        const bool needmask = (k0 + 63) > (q0 + wid * 16);

        // ---- S = Q K^T (q_hi · k_hi only) ----
        float sacc[8][4];
        #pragma unroll
        for (int i = 0; i < 8; i++)
            #pragma unroll
            for (int j = 0; j < 4; j++) sacc[i][j] = 0.f;

        #pragma unroll
        for (int kk = 0; kk < 4; kk++) {
            uint32_t qh[4];
            ldsm_x4(qh, sQhi + qOff + kk * 32);
            #pragma unroll
            for (int np = 0; np < 4; np++) {
                if (k0 + np * 16 > limit) break;   // fully masked 16-col tile
                const uint32_t ba = kRowOff + (uint32_t)np * 16 * SRS + kk * 32;
                uint32_t bh[4];
                ldsm_x4(bh, Khi_ + ba);
                #pragma unroll
                for (int t = 0; t < 2; t++)
                    mma16816(sacc[2 * np + t], qh, &bh[2 * t]);
            }
        }

        // ---- unnormalized softmax: p = exp2(s * 0.125/ln2), masked -> 0 ----
        const int rbase = q0 + wid * 16 + (lane >> 2);
        float s0 = 0.f, s1 = 0.f;
        #pragma unroll
        for (int nt = 0; nt < 8; nt++) {
            const int col = k0 + nt * 8 + 2 * (lane & 3);
            if (k0 + (nt >> 1) * 16 > limit) {
                sacc[nt][0] = sacc[nt][1] = sacc[nt][2] = sacc[nt][3] = 0.f;
                continue;
            }
            #pragma unroll
            for (int j = 0; j < 4; j++) {
                bool dead = false;
                if (needmask) {
                    const int cc = col + (j & 1);
                    const int rr = rbase + (j >> 1) * 8;
                    dead = (cc > rr);
                }
                const float v = dead ? 0.f
                    : exp2f(sacc[nt][j] * 0.18033688011112042f);
                sacc[nt][j] = v;
            }
            s0 += sacc[nt][0] + sacc[nt][1];
            s1 += sacc[nt][2] + sacc[nt][3];
        }
        s0 += __shfl_xor_sync(0xffffffffu, s0, 1);
        s0 += __shfl_xor_sync(0xffffffffu, s0, 2);
        s1 += __shfl_xor_sync(0xffffffffu, s1, 1);
        s1 += __shfl_xor_sync(0xffffffffu, s1, 2);
        l0 += s0; l1 += s1;

        // ---- O += P V (split P, split V) ----
        #pragma unroll
        for (int kkp = 0; kkp < 4; kkp++) {
            if (k0 + kkp * 16 > limit) break;      // P == 0 for these keys
            uint32_t phi[4], plo[4];
            phi[0] = packsplit(sacc[2*kkp][0],   sacc[2*kkp][1],   plo[0]);
            phi[1] = packsplit(sacc[2*kkp][2],   sacc[2*kkp][3],   plo[1]);
            phi[2] = packsplit(sacc[2*kkp+1][0], sacc[2*kkp+1][1], plo[2]);
            phi[3] = packsplit(sacc[2*kkp+1][2], sacc[2*kkp+1][3], plo[3]);
            #pragma unroll
            for (int np = 0; np < 4; np++) {
                const uint32_t va = (uint32_t)(kkp * 16) * SRS + vRowOff + np * 32;
                uint32_t vh[4], vl[4];
                ldsm_x4_t(vh, Vhi_ + va);
                ldsm_x4_t(vl, Vlo_ + va);
                #pragma unroll
                for (int t = 0; t < 2; t++) {
                    mma16816(acc_o[2 * np + t], phi, &vh[2 * t]);
                    mma16816(acc_o[2 * np + t], phi, &vl[2 * t]);
                    mma16816(acc_o[2 * np + t], plo, &vh[2 * t]);
                }
            }
        }
    }

    // ---- epilogue: O / l, write bf16 hi/lo into GEMM A buffers ----
    const float inv0 = 1.f / l0, inv1 = 1.f / l1;
    const int row0 = b * TT + q0 + wid * 16 + (lane >> 2);
    const int colb = h * DHH + 2 * (lane & 3);
    #pragma unroll
    for (int nt = 0; nt < 8; nt++) {
        const int col = colb + nt * 8;
        uint32_t lo;
        uint32_t hi = packsplit(acc_o[nt][0] * inv0, acc_o[nt][1] * inv0, lo);
        *(uint32_t*)(Ohi + (size_t)row0 * EE + col) = hi;
        *(uint32_t*)(Olo + (size_t)row0 * EE + col) = lo;
        hi = packsplit(acc_o[nt][2] * inv1, acc_o[nt][3] * inv1, lo);
        *(uint32_t*)(Ohi + (size_t)(row0 + 8) * EE + col) = hi;
        *(uint32_t*)(Olo + (size_t)(row0 + 8) * EE + col) = lo;
    }
}

// =====================================================================
// LayerNorm: block per row, 256 threads; optional fp32 + bf16 hi/lo out
// =====================================================================
__global__ __launch_bounds__(256) void layernorm_kernel(
    const float* __restrict__ x, const float* __restrict__ gam,
    const float* __restrict__ bet, float* __restrict__ outF,
    __nv_bfloat16* __restrict__ outHi, __nv_bfloat16* __restrict__ outLo)
{
    const int row = blockIdx.x;
    const int tid = threadIdx.x;
    const float4 xv = *(const float4*)(x + (size_t)row * EE + tid * 4);

    __shared__ float red[8];

    float s = xv.x + xv.y + xv.z + xv.w;
    #pragma unroll
    for (int o = 16; o; o >>= 1) s += __shfl_xor_sync(0xffffffffu, s, o);
    if ((tid & 31) == 0) red[tid >> 5] = s;
    __syncthreads();
    float tot = 0.f;
    #pragma unroll
    for (int i = 0; i < 8; i++) tot += red[i];
    const float mu = tot * (1.0f / (float)EE);
    __syncthreads();

    const float dx = xv.x - mu, dy = xv.y - mu, dz = xv.z - mu, dw = xv.w - mu;
    float ss = dx*dx + dy*dy + dz*dz + dw*dw;
    #pragma unroll
    for (int o = 16; o; o >>= 1) ss += __shfl_xor_sync(0xffffffffu, ss, o);
    if ((tid & 31) == 0) red[tid >> 5] = ss;
    __syncthreads();
    float sst = 0.f;
    #pragma unroll
    for (int i = 0; i < 8; i++) sst += red[i];
    const float inv = rsqrtf(sst * (1.0f / (float)EE) + LN_EPS);

    const float4 gv = *(const float4*)(gam + tid * 4);
    const float4 bv = *(const float4*)(bet + tid * 4);
    float4 ov;
    ov.x = dx * inv * gv.x + bv.x;
    ov.y = dy * inv * gv.y + bv.y;
    ov.z = dz * inv * gv.z + bv.z;
    ov.w = dw * inv * gv.w + bv.w;
    if (outF) *(float4*)(outF + (size_t)row * EE + tid * 4) = ov;
    uint32_t lo0, lo1;
    const uint32_t hi0 = packsplit(ov.x, ov.y, lo0);
    const uint32_t hi1 = packsplit(ov.z, ov.w, lo1);
    uint2 hv; hv.x = hi0; hv.y = hi1;
    uint2 lv; lv.x = lo0; lv.y = lo1;
    *(uint2*)(outHi + (size_t)row * EE + tid * 4) = hv;
    *(uint2*)(outLo + (size_t)row * EE + tid * 4) = lv;
}

// =====================================================================
// Argmax reduce over 16 partials per row
// =====================================================================
__global__ __launch_bounds__(256) void argmax_reduce_kernel(
    const unsigned long long* __restrict__ part, int* __restrict__ idx)
{
    const int m = blockIdx.x * 256 + threadIdx.x;
    const unsigned long long* p = part + (size_t)m * 16;
    unsigned long long k = p[0];
    #pragma unroll
    for (int i = 1; i < 16; i++) {
        const unsigned long long v = p[i];
        if (v > k) k = v;
    }
    idx[m] = dec_argmax(k);
}

// =====================================================================
// MoE routing: clear-hist / hist / scan / scatter (from g_idx)
// =====================================================================
__global__ __launch_bounds__(256) void hist_clear_kernel(int* __restrict__ hist)
{
    hist[blockIdx.x * 256 + threadIdx.x] = 0;
}

__global__ __launch_bounds__(256) void hist_kernel(
    const int* __restrict__ idx, int* __restrict__ hist)
{
    const int t = blockIdx.x * 256 + threadIdx.x;
    atomicAdd(&hist[idx[t]], 1);
}

__global__ __launch_bounds__(1024) void scan_kernel(
    const int* __restrict__ hist, int* __restrict__ cursor)
{
    __shared__ int warpsum[32];
    const int tid = threadIdx.x;
    const int lane = tid & 31, wid = tid >> 5;
    const int v0 = hist[2 * tid], v1 = hist[2 * tid + 1];
    const int tsum = v0 + v1;
    int x = tsum;
    #pragma unroll
    for (int o = 1; o < 32; o <<= 1) {
        const int y = __shfl_up_sync(0xffffffffu, x, o);
        if (lane >= o) x += y;
    }
    if (lane == 31) warpsum[wid] = x;
    __syncthreads();
    if (wid == 0) {
        int w = warpsum[lane];
        #pragma unroll
        for (int o = 1; o < 32; o <<= 1) {
            const int y = __shfl_up_sync(0xffffffffu, w, o);
            if (lane >= o) w += y;
        }
        warpsum[lane] = w;
    }
    __syncthreads();
    const int base = (wid > 0 ? warpsum[wid - 1] : 0) + (x - tsum);
    cursor[2 * tid] = base;
    cursor[2 * tid + 1] = base + v0;
}

__global__ __launch_bounds__(256) void scatter_kernel(
    const int* __restrict__ idx, int* __restrict__ cursor,
    int* __restrict__ perm)
{
    const int t = blockIdx.x * 256 + threadIdx.x;
    const int pos = atomicAdd(&cursor[idx[t]], 1);
    perm[pos] = t;
}

// =====================================================================
// MoE: one block per (expert-sorted) token
// =====================================================================
__global__ __launch_bounds__(256) void moe_kernel(
    const float* __restrict__ h, const int* __restrict__ idx,
    const int* __restrict__ perm,
    const float* __restrict__ w1, const float* __restrict__ b1,
    const float* __restrict__ w2, const float* __restrict__ b2,
    float* __restrict__ out)
{
    const int token = perm[blockIdx.x];
    const int tid = threadIdx.x;
    const int e = idx[token];

    __shared__ float xs[EE];
    __shared__ float partial[HIDD][17];
    __shared__ float hm[HIDD];

    const float* hrow = h + (size_t)token * EE;
    for (int i = tid; i < EE; i += 256) xs[i] = hrow[i];
    __syncthreads();

    const int hcol = tid & 15;
    const int grp  = tid >> 4;
    const float* w1p = w1 + (size_t)e * EE * HIDD;
    float acc = 0.f;
    for (int i = grp; i < EE; i += 16)
        acc += xs[i] * w1p[(size_t)i * HIDD + hcol];
    partial[hcol][grp] = acc;
    __syncthreads();

    if (tid < HIDD) {
        float s = b1[(size_t)e * HIDD + tid];
        #pragma unroll
        for (int g2 = 0; g2 < 16; g2++) s += partial[tid][g2];
        hm[tid] = 0.5f * s * (1.0f + erff(s * 0.70710678118654752f));
    }
    __syncthreads();

    float hreg[HIDD];
    #pragma unroll
    for (int k = 0; k < HIDD; k++) hreg[k] = hm[k];

    const float* w2p = w2 + (size_t)e * HIDD * EE;
    const float* b2p = b2 + (size_t)e * EE;
    float* orow = out + (size_t)token * EE;
    for (int j = tid; j < EE; j += 256) {
        float s = b2p[j];
        #pragma unroll
        for (int k = 0; k < HIDD; k++) s += hreg[k] * w2p[(size_t)k * EE + j];
        orow[j] += s;
    }
}

// =====================================================================
// launch
// =====================================================================
extern "C" void kernel_launch(void* const* d_in, const int* in_sizes, int n_in,
                              void* d_out, int out_size)
{
    const float* x      = (const float*)d_in[0];
    const float* ln1_g  = (const float*)d_in[1];
    const float* ln1_b  = (const float*)d_in[2];
    const float* ln2_g  = (const float*)d_in[3];
    const float* ln2_b  = (const float*)d_in[4];
    const float* qkv_w  = (const float*)d_in[5];
    const float* qkv_b  = (const float*)d_in[6];
    const float* proj_w = (const float*)d_in[7];
    const float* proj_b = (const float*)d_in[8];
    const float* gate_w = (const float*)d_in[9];
    const float* gate_b = (const float*)d_in[10];
    const float* w1     = (const float*)d_in[11];
    const float* b1     = (const float*)d_in[12];
    const float* w2     = (const float*)d_in[13];
    const float* w2b    = (const float*)d_in[14];
    float* out = (float*)d_out;

    void *p_h, *p_part, *p_idx, *p_hist, *p_cur, *p_perm,
         *p_ah, *p_al, *p_bh, *p_bl, *p_qh, *p_ql;
    cudaGetSymbolAddress(&p_h, g_h);
    cudaGetSymbolAddress(&p_part, g_part);
    cudaGetSymbolAddress(&p_idx, g_idx);
    cudaGetSymbolAddress(&p_hist, g_hist);
    cudaGetSymbolAddress(&p_cur, g_cursor);
    cudaGetSymbolAddress(&p_perm, g_perm);
    cudaGetSymbolAddress(&p_ah, g_Ahi);
    cudaGetSymbolAddress(&p_al, g_Alo);
    cudaGetSymbolAddress(&p_bh, g_Bhi);
    cudaGetSymbolAddress(&p_bl, g_Blo);
    cudaGetSymbolAddress(&p_qh, g_QKVhi);
    cudaGetSymbolAddress(&p_ql, g_QKVlo);
    float* bh      = (float*)p_h;
    unsigned long long* bpart = (unsigned long long*)p_part;
    int*   bidx    = (int*)p_idx;
    int*   hist    = (int*)p_hist;
    int*   cursor  = (int*)p_cur;
    int*   perm    = (int*)p_perm;
    __nv_bfloat16* Ahi = (__nv_bfloat16*)p_ah;
    __nv_bfloat16* Alo = (__nv_bfloat16*)p_al;
    __nv_bfloat16* Bhi = (__nv_bfloat16*)p_bh;
    __nv_bfloat16* Blo = (__nv_bfloat16*)p_bl;
    __nv_bfloat16* QKVhi = (__nv_bfloat16*)p_qh;
    __nv_bfloat16* QKVlo = (__nv_bfloat16*)p_ql;

    cudaFuncSetAttribute(gemm_tc<2>, cudaFuncAttributeMaxDynamicSharedMemorySize, GEMM_SMEM);
    cudaFuncSetAttribute(gemm_tc<3>, cudaFuncAttributeMaxDynamicSharedMemorySize, GEMM_SMEM);
    cudaFuncSetAttribute(flash_mma_kernel, cudaFuncAttributeMaxDynamicSharedMemorySize, ATT_SMEM);

    // 1) LN1(x) -> bf16 hi/lo A operand
    layernorm_kernel<<<MTOK, 256>>>(x, ln1_g, ln1_b, nullptr, Ahi, Alo);

    // 2) qkv = h @ qkv_w + qkv_b -> bf16 hi/lo  (2-term split: A-lo dropped)
    convW_kernel<<<dim3(3*EE/64, EE/64), 256>>>(qkv_w, Bhi, Blo, 3*EE, EE);
    gemm_tc<2><<<dim3(3*EE/128, MTOK/128), 256, GEMM_SMEM>>>(
        Ahi, Alo, Bhi, Blo, qkv_b, nullptr, nullptr, QKVhi, QKVlo, nullptr, 3*EE, EE);

    // 3) attention -> bf16 hi/lo into A operand buffers
    flash_mma_kernel<<<dim3(TT/128, NHH, BB), 256, ATT_SMEM>>>(QKVhi, QKVlo, Ahi, Alo);

    // 4) xmid = x + attn @ proj_w + proj_b -> d_out (fp32, full 3-term)
    convW_kernel<<<dim3(EE/64, EE/64), 256>>>(proj_w, Bhi, Blo, EE, EE);
    gemm_tc<3><<<dim3(EE/128, MTOK/128), 256, GEMM_SMEM>>>(
        Ahi, Alo, Bhi, Blo, proj_b, x, out, nullptr, nullptr, nullptr, EE, EE);

    // 5) LN2 -> fp32 (MoE) + bf16 hi/lo (gate GEMM)
    layernorm_kernel<<<MTOK, 256>>>(out, ln2_g, ln2_b, bh, Ahi, Alo);

    // 6) gate GEMM with fused argmax partials (full 3-term: argmax safety)
    convW_kernel<<<dim3(NEE/64, EE/64), 256>>>(gate_w, Bhi, Blo, NEE, EE);
    gemm_tc<3><<<dim3(NEE/128, MTOK/128), 256, GEMM_SMEM>>>(
        Ahi, Alo, Bhi, Blo, gate_b, nullptr, nullptr, nullptr, nullptr, bpart, NEE, EE);

    // 7) idx = reduce(partials); expert-locality sort
    argmax_reduce_kernel<<<MTOK/256, 256>>>(bpart, bidx);
    hist_clear_kernel<<<NEE/256, 256>>>(hist);
    hist_kernel<<<MTOK/256, 256>>>(bidx, hist);
    scan_kernel<<<1, 1024>>>(hist, cursor);
    scatter_kernel<<<MTOK/256, 256>>>(bidx, cursor, perm);

    // 8) d_out += moe(h, idx) over expert-sorted tokens (block per token)
    moe_kernel<<<MTOK, 256>>>(bh, bidx, perm, w1, b1, w2, w2b, out);
}

// round 17
// speedup vs baseline: 1.3209x; 1.0525x over previous
#include <cuda_runtime.h>
#include <cuda_bf16.h>
#include <math.h>
#include <stdint.h>

// ---------------- problem constants ----------------
#define BB 4
#define TT 2048
#define EE 1024
#define NHH 16
#define DHH 64
#define NEE 2048
#define HIDD 16
#define MTOK (BB*TT)          // 8192 tokens
#define LN_EPS 1e-5f

// ---------------- scratch (device globals; no runtime allocation) ----------
__device__ float g_h[MTOK * EE];          // LN2 output fp32 (for MoE)
__device__ unsigned long long g_part[MTOK * 16];  // per-(row, bn-tile) argmax partials
__device__ int   g_idx[MTOK];             // argmax expert per token
__device__ int   g_hist[NEE];
__device__ int   g_cursor[NEE];
__device__ int   g_perm[MTOK];
__device__ __nv_bfloat16 g_Ahi[MTOK * EE];       // GEMM A operand hi [M,K]
__device__ __nv_bfloat16 g_Alo[MTOK * EE];
__device__ __nv_bfloat16 g_Bhi[3 * EE * EE];     // weights transposed [N,K]
__device__ __nv_bfloat16 g_Blo[3 * EE * EE];
__device__ __nv_bfloat16 g_QKVhi[MTOK * 3 * EE]; // qkv bf16 (hi only consumed)

// =====================================================================
// PTX helpers (family-portable: cp.async / ldmatrix / mma.sync only)
// =====================================================================
__device__ __forceinline__ uint32_t smem_u32(const void* p){
    uint32_t a;
    asm("{ .reg .u64 t; cvta.to.shared.u64 t, %1; cvt.u32.u64 %0, t; }"
        : "=r"(a) : "l"(p));
    return a;
}
__device__ __forceinline__ void cp_async16(uint32_t dst, const void* src){
    asm volatile("cp.async.cg.shared.global [%0], [%1], 16;"
        :: "r"(dst), "l"(src));
}
__device__ __forceinline__ void cp_commit(){
    asm volatile("cp.async.commit_group;");
}
template<int N> __device__ __forceinline__ void cp_wait(){
    asm volatile("cp.async.wait_group %0;" :: "n"(N));
}
__device__ __forceinline__ void ldsm_x4(uint32_t* r, uint32_t a){
    asm volatile("ldmatrix.sync.aligned.m8n8.x4.shared.b16 {%0,%1,%2,%3}, [%4];"
        : "=r"(r[0]), "=r"(r[1]), "=r"(r[2]), "=r"(r[3]) : "r"(a));
}
__device__ __forceinline__ void ldsm_x4_t(uint32_t* r, uint32_t a){
    asm volatile("ldmatrix.sync.aligned.m8n8.x4.trans.shared.b16 {%0,%1,%2,%3}, [%4];"
        : "=r"(r[0]), "=r"(r[1]), "=r"(r[2]), "=r"(r[3]) : "r"(a));
}
__device__ __forceinline__ void mma16816(float* d, const uint32_t* a, const uint32_t* b){
    asm volatile(
        "mma.sync.aligned.m16n8k16.row.col.f32.bf16.bf16.f32 "
        "{%0,%1,%2,%3}, {%4,%5,%6,%7}, {%8,%9}, {%0,%1,%2,%3};"
        : "+f"(d[0]), "+f"(d[1]), "+f"(d[2]), "+f"(d[3])
        : "r"(a[0]), "r"(a[1]), "r"(a[2]), "r"(a[3]), "r"(b[0]), "r"(b[1]));
}
__device__ __forceinline__ uint32_t packsplit(float x, float y, uint32_t& lo){
    __nv_bfloat162 h = __floats2bfloat162_rn(x, y);
    __nv_bfloat162 l = __floats2bfloat162_rn(x - __bfloat162float(h.x),
                                             y - __bfloat162float(h.y));
    lo = *(uint32_t*)&l;
    return *(uint32_t*)&h;
}
__device__ __forceinline__ uint32_t packhi(float x, float y){
    __nv_bfloat162 h = __floats2bfloat162_rn(x, y);
    return *(uint32_t*)&h;
}
// monotone encoding of (float value, col) for argmax-with-first-tiebreak
__device__ __forceinline__ unsigned long long enc_argmax(float v, int col){
    uint32_t u = __float_as_uint(v);
    u = (u & 0x80000000u) ? ~u : (u | 0x80000000u);
    return ((unsigned long long)u << 32) | (uint32_t)(~col);
}
__device__ __forceinline__ int dec_argmax(unsigned long long k){
    return (int)(~(uint32_t)k);
}

// =====================================================================
// Weights: fp32 W[K,N] -> transposed bf16 hi/lo [N,K]
// =====================================================================
__global__ __launch_bounds__(256) void convW_kernel(
    const float* __restrict__ W, __nv_bfloat16* __restrict__ hi,
    __nv_bfloat16* __restrict__ lo, int N, int K)
{
    __shared__ float tile[64][65];
    const int k0 = blockIdx.y * 64;
    const int n0 = blockIdx.x * 64;
    for (int i = threadIdx.x; i < 4096; i += 256) {
        const int r = i >> 6, c = i & 63;
        tile[r][c] = W[(size_t)(k0 + r) * N + n0 + c];
    }
    __syncthreads();
    for (int i = threadIdx.x; i < 4096; i += 256) {
        const int r = i >> 6, c = i & 63;
        const float v = tile[c][r];
        const __nv_bfloat16 h = __float2bfloat16(v);
        const __nv_bfloat16 l = __float2bfloat16(v - __bfloat162float(h));
        const size_t o = (size_t)(n0 + r) * K + k0 + c;
        hi[o] = h;
        lo[o] = l;
    }
}

// =====================================================================
// split-bf16 HMMA GEMM: C[M,N] = A[M,K] @ W[K,N] + bias (+ res)
// CTA 128x128, BK=32, 2-stage cp.async, 2 CTAs/SM, 8 warps (2x4),
// warp tile 64x32, term-major MMA ordering, A-fragment double buffer.
// TERMS=3: hi·hi + hi·lo + lo·hi.  TERMS=2: hi·hi + hi·lo (A-lo unused).
// Epilogue: fp32 (Cf) / bf16 hi[+lo] (outHi/outLo) / argmax partials
// =====================================================================
#define RS 80                      // smem row stride bytes (40 bf16)
#define MATB (128*RS)              // 10240 B per matrix tile
#define STGB (4*MATB)              // 40960 B per stage
#define GEMM_SMEM (512 + 2*STGB)   // bias + 2 stages = 82432 -> 2 CTAs/SM

template<int TERMS>
__global__ __launch_bounds__(256, 2)
void gemm_tc(const __nv_bfloat16* __restrict__ Ahi, const __nv_bfloat16* __restrict__ Alo,
             const __nv_bfloat16* __restrict__ Bhi, const __nv_bfloat16* __restrict__ Blo,
             const float* __restrict__ bias, const float* __restrict__ res,
             float* __restrict__ Cf,
             __nv_bfloat16* __restrict__ outHi, __nv_bfloat16* __restrict__ outLo,
             unsigned long long* __restrict__ part,
             int N, int K)
{
    extern __shared__ __align__(128) char smem[];
    const int tid = threadIdx.x;
    const int lane = tid & 31, wid = tid >> 5;
    const int warp_m = wid & 1, warp_n = wid >> 1;     // 2 x 4
    const int bn = blockIdx.x, bm = blockIdx.y;
    const uint32_t sb = smem_u32(smem);
    float* bsm = (float*)smem;

    if (tid < 128) bsm[tid] = bias[bn * 128 + tid];

    const __nv_bfloat16* gA[2] = { Ahi + (size_t)bm * 128 * K,
                                   Alo + (size_t)bm * 128 * K };
    const __nv_bfloat16* gB[2] = { Bhi + (size_t)bn * 128 * K,
                                   Blo + (size_t)bn * 128 * K };

    const int r0 = tid >> 2, c0 = tid & 3;
    const int r1 = r0 + 64;

    auto load_stage = [&](int s, int k0){
        const uint32_t st = sb + 512 + s * STGB;
        #pragma unroll
        for (int m = 0; m < 2; m++) {
            if (TERMS == 2 && m == 1) break;       // A-lo never used
            const __nv_bfloat16* src = gA[m] + k0;
            const uint32_t d = st + m * MATB;
            cp_async16(d + r0 * RS + c0 * 16, src + (size_t)r0 * K + c0 * 8);
            cp_async16(d + r1 * RS + c0 * 16, src + (size_t)r1 * K + c0 * 8);
        }
        #pragma unroll
        for (int m = 0; m < 2; m++) {
            const __nv_bfloat16* src = gB[m] + k0;
            const uint32_t d = st + (2 + m) * MATB;
            cp_async16(d + r0 * RS + c0 * 16, src + (size_t)r0 * K + c0 * 8);
            cp_async16(d + r1 * RS + c0 * 16, src + (size_t)r1 * K + c0 * 8);
        }
    };

    float acc[4][4][4];
    #pragma unroll
    for (int i = 0; i < 4; i++)
        #pragma unroll
        for (int j = 0; j < 4; j++)
            #pragma unroll
            for (int t = 0; t < 4; t++) acc[i][j][t] = 0.f;

    const int nk = K >> 5;
    load_stage(0, 0);  cp_commit();
    load_stage(1, 32); cp_commit();

    const int l15 = lane & 15;
    const uint32_t aRowOff = (uint32_t)(warp_m * 64 + l15) * RS + (uint32_t)(lane >> 4) * 16;
    const uint32_t bRowOff = (uint32_t)(warp_n * 32 + (lane & 7) + ((lane >> 4) << 3)) * RS
                           + (uint32_t)((lane >> 3) & 1) * 16;

    for (int c = 0; c < nk; c++) {
        if (c == nk - 1) cp_wait<0>(); else cp_wait<1>();
        __syncthreads();

        const uint32_t st = sb + 512 + (c & 1) * STGB;
        #pragma unroll
        for (int kk = 0; kk < 2; kk++) {
            uint32_t bh[2][4], bl[2][4];
            #pragma unroll
            for (int np = 0; np < 2; np++) {
                const uint32_t ba = st + bRowOff + (uint32_t)np * 16 * RS + kk * 32;
                ldsm_x4(bh[np], ba + 2 * MATB);
                ldsm_x4(bl[np], ba + 3 * MATB);
            }
            // A-fragment double buffer: prefetch mt+1 while issuing mt's MMAs
            uint32_t ah[2][4], al[2][4];
            {
                const uint32_t aa0 = st + aRowOff + kk * 32;
                ldsm_x4(ah[0], aa0);
                if (TERMS == 3) ldsm_x4(al[0], aa0 + MATB);
            }
            #pragma unroll
            for (int mt = 0; mt < 4; mt++) {
                const int cur = mt & 1, nxt = cur ^ 1;
                if (mt < 3) {
                    const uint32_t aa = st + aRowOff + (uint32_t)(mt + 1) * 16 * RS + kk * 32;
                    ldsm_x4(ah[nxt], aa);
                    if (TERMS == 3) ldsm_x4(al[nxt], aa + MATB);
                }
                // term-major: 4 independent accs between same-acc MMAs
                #pragma unroll
                for (int nt = 0; nt < 4; nt++)
                    mma16816(acc[mt][nt], ah[cur], &bh[nt >> 1][(nt & 1) * 2]);
                #pragma unroll
                for (int nt = 0; nt < 4; nt++)
                    mma16816(acc[mt][nt], ah[cur], &bl[nt >> 1][(nt & 1) * 2]);
                if (TERMS == 3) {
                    #pragma unroll
                    for (int nt = 0; nt < 4; nt++)
                        mma16816(acc[mt][nt], al[cur], &bh[nt >> 1][(nt & 1) * 2]);
                }
            }
        }
        __syncthreads();
        if (c + 2 < nk) { load_stage(c & 1, (c + 2) * 32); cp_commit(); }
    }

    const int mBase = bm * 128 + warp_m * 64;
    const int nBase = warp_n * 32;
    const int gn0 = bn * 128;

    if (part) {
        // fused argmax partials (gate GEMM): smem two-level reduce, no atomics
        unsigned long long* psm = (unsigned long long*)(smem + 512);  // [128][4]
        #pragma unroll
        for (int mt = 0; mt < 4; mt++) {
            #pragma unroll
            for (int hh = 0; hh < 2; hh++) {
                const int rloc = warp_m * 64 + mt * 16 + (lane >> 2) + hh * 8;
                float bestv = -3.4e38f; int bestc = 0;
                #pragma unroll
                for (int nt = 0; nt < 4; nt++) {
                    const int lc = nBase + nt * 8 + (lane & 3) * 2;
                    const float vx = acc[mt][nt][hh * 2 + 0] + bsm[lc];
                    const float vy = acc[mt][nt][hh * 2 + 1] + bsm[lc + 1];
                    if (vx > bestv) { bestv = vx; bestc = gn0 + lc; }
                    if (vy > bestv) { bestv = vy; bestc = gn0 + lc + 1; }
                }
                unsigned long long key = enc_argmax(bestv, bestc);
                unsigned long long o1 = __shfl_xor_sync(0xffffffffu, key, 1);
                if (o1 > key) key = o1;
                unsigned long long o2 = __shfl_xor_sync(0xffffffffu, key, 2);
                if (o2 > key) key = o2;
                if ((lane & 3) == 0) psm[rloc * 4 + warp_n] = key;
            }
        }
        __syncthreads();
        if (tid < 128) {
            unsigned long long k = psm[tid * 4 + 0];
            unsigned long long t1 = psm[tid * 4 + 1]; if (t1 > k) k = t1;
            unsigned long long t2 = psm[tid * 4 + 2]; if (t2 > k) k = t2;
            unsigned long long t3 = psm[tid * 4 + 3]; if (t3 > k) k = t3;
            part[(size_t)(bm * 128 + tid) * 16 + bn] = k;
        }
        return;
    }

    #pragma unroll
    for (int mt = 0; mt < 4; mt++) {
        #pragma unroll
        for (int nt = 0; nt < 4; nt++) {
            const int row = mBase + mt * 16 + (lane >> 2);
            const int col = nBase + nt * 8 + (lane & 3) * 2;
            #pragma unroll
            for (int hh = 0; hh < 2; hh++) {
                const int m = row + hh * 8;
                float vx = acc[mt][nt][hh * 2 + 0] + bsm[col];
                float vy = acc[mt][nt][hh * 2 + 1] + bsm[col + 1];
                if (outHi) {
                    if (outLo) {
                        uint32_t lo;
                        const uint32_t hi = packsplit(vx, vy, lo);
                        *(uint32_t*)(outHi + (size_t)m * N + gn0 + col) = hi;
                        *(uint32_t*)(outLo + (size_t)m * N + gn0 + col) = lo;
                    } else {
                        *(uint32_t*)(outHi + (size_t)m * N + gn0 + col) = packhi(vx, vy);
                    }
                } else {
                    if (res) {
                        const float2 rv = *(const float2*)(res + (size_t)m * N + gn0 + col);
                        vx += rv.x; vy += rv.y;
                    }
                    float2 v; v.x = vx; v.y = vy;
                    *(float2*)(Cf + (size_t)m * N + gn0 + col) = v;
                }
            }
        }
    }
}

// =====================================================================
// HMMA flash attention (causal, unnormalized exp softmax)
// QK: q_hi · k_hi only.  P V: split P, bf16 V (p_hi·v + p_lo·v).
// Grid (T/128, NH, B), 256 thr, 2 CTAs/SM.
// =====================================================================
#define SRS 144                     // smem row stride (64 bf16 + 16B pad)
#define ATT_MAT (64*SRS)            // 9216 per matrix (64 rows)
#define ATT_STG (2*ATT_MAT)         // Khi,Vhi = 18432
#define ATT_Q   (128*SRS)           // 18432 (Q hi only)
#define ATT_SMEM (ATT_Q + 2*ATT_STG)   // 55296 -> 2 CTAs/SM

__global__ __launch_bounds__(256, 2)
void flash_mma_kernel(const __nv_bfloat16* __restrict__ QKVhi,
                      __nv_bfloat16* __restrict__ Ohi,
                      __nv_bfloat16* __restrict__ Olo)
{
    extern __shared__ __align__(128) char smem[];
    const int tid = threadIdx.x, lane = tid & 31, wid = tid >> 5;
    const int qt = (int)gridDim.x - 1 - (int)blockIdx.x;   // heavy blocks first
    const int q0 = qt * 128;
    const int h = blockIdx.y, b = blockIdx.z;

    const uint32_t sQhi = smem_u32(smem);
    const uint32_t sKV0 = sQhi + ATT_Q;

    const size_t rowStride = 3 * EE;
    const size_t base = ((size_t)b * TT) * rowStride + (size_t)h * DHH;
    const __nv_bfloat16* Qh = QKVhi + base;
    const __nv_bfloat16* Kh = Qh + EE;
    const __nv_bfloat16* Vh = Qh + 2 * EE;

    // ---- Q tile load (128 rows x 8 16B chunks, hi only) ----
    for (int i = tid; i < 1024; i += 256) {
        const int row = i >> 3, c = i & 7;
        const size_t g = (size_t)(q0 + row) * rowStride + c * 8;
        cp_async16(sQhi + row * SRS + c * 16, Qh + g);
    }

    auto load_kv = [&](int s, int k0){
        const uint32_t st = sKV0 + s * ATT_STG;
        for (int i = tid; i < 512; i += 256) {
            const int row = i >> 3, c = i & 7;
            const size_t g = (size_t)(k0 + row) * rowStride + c * 8;
            const uint32_t d = st + row * SRS + c * 16;
            cp_async16(d + 0 * ATT_MAT, Kh + g);
            cp_async16(d + 1 * ATT_MAT, Vh + g);
        }
    };

    const int nk = 2 * qt + 2;      // 64-key tiles
    load_kv(0, 0);  cp_commit();    // group 0 carries Q too

    float acc_o[8][4];
    #pragma unroll
    for (int i = 0; i < 8; i++)
        #pragma unroll
        for (int j = 0; j < 4; j++) acc_o[i][j] = 0.f;
    float l0 = 0.f, l1 = 0.f;

    const int l15 = lane & 15;
    const uint32_t qOff = (uint32_t)(wid * 16 + l15) * SRS + (uint32_t)(lane >> 4) * 16;
    const uint32_t kRowOff = (uint32_t)((lane & 7) + ((lane >> 4) << 3)) * SRS
                           + (uint32_t)((lane >> 3) & 1) * 16;
    const uint32_t vRowOff = (uint32_t)((lane & 7) + (((lane >> 3) & 1) << 3)) * SRS
                           + (uint32_t)((lane >> 4) & 1) * 16;

    const int limit = q0 + wid * 16 + 15;   // warp's max row

    for (int c = 0; c < nk; c++) {
        cp_wait<0>();
        __syncthreads();
        if (c + 1 < nk) { load_kv((c + 1) & 1, (c + 1) * 64); cp_commit(); }

        const uint32_t Khi_ = sKV0 + (c & 1) * ATT_STG;
        const uint32_t Vhi_ = Khi_ + 1 * ATT_MAT;
        const int k0 = c * 64;
        const bool needmask = (k0 + 63) > (q0 + wid * 16);

        // ---- S = Q K^T (q_hi · k_hi only) ----
        float sacc[8][4];
        #pragma unroll
        for (int i = 0; i < 8; i++)
            #pragma unroll
            for (int j = 0; j < 4; j++) sacc[i][j] = 0.f;

        #pragma unroll
        for (int kk = 0; kk < 4; kk++) {
            uint32_t qh[4];
            ldsm_x4(qh, sQhi + qOff + kk * 32);
            #pragma unroll
            for (int np = 0; np < 4; np++) {
                if (k0 + np * 16 > limit) break;   // fully masked 16-col tile
                const uint32_t ba = kRowOff + (uint32_t)np * 16 * SRS + kk * 32;
                uint32_t bh[4];
                ldsm_x4(bh, Khi_ + ba);
                #pragma unroll
                for (int t = 0; t < 2; t++)
                    mma16816(sacc[2 * np + t], qh, &bh[2 * t]);
            }
        }

        // ---- unnormalized softmax: p = exp2(s * 0.125/ln2), masked -> 0 ----
        const int rbase = q0 + wid * 16 + (lane >> 2);
        float s0 = 0.f, s1 = 0.f;
        #pragma unroll
        for (int nt = 0; nt < 8; nt++) {
            const int col = k0 + nt * 8 + 2 * (lane & 3);
            if (k0 + (nt >> 1) * 16 > limit) {
                sacc[nt][0] = sacc[nt][1] = sacc[nt][2] = sacc[nt][3] = 0.f;
                continue;
            }
            #pragma unroll
            for (int j = 0; j < 4; j++) {
                bool dead = false;
                if (needmask) {
                    const int cc = col + (j & 1);
                    const int rr = rbase + (j >> 1) * 8;
                    dead = (cc > rr);
                }
                const float v = dead ? 0.f
                    : exp2f(sacc[nt][j] * 0.18033688011112042f);
                sacc[nt][j] = v;
            }
            s0 += sacc[nt][0] + sacc[nt][1];
            s1 += sacc[nt][2] + sacc[nt][3];
        }
        s0 += __shfl_xor_sync(0xffffffffu, s0, 1);
        s0 += __shfl_xor_sync(0xffffffffu, s0, 2);
        s1 += __shfl_xor_sync(0xffffffffu, s1, 1);
        s1 += __shfl_xor_sync(0xffffffffu, s1, 2);
        l0 += s0; l1 += s1;

        // ---- O += P V (split P, bf16 V) ----
        #pragma unroll
        for (int kkp = 0; kkp < 4; kkp++) {
            if (k0 + kkp * 16 > limit) break;      // P == 0 for these keys
            uint32_t phi[4], plo[4];
            phi[0] = packsplit(sacc[2*kkp][0],   sacc[2*kkp][1],   plo[0]);
            phi[1] = packsplit(sacc[2*kkp][2],   sacc[2*kkp][3],   plo[1]);
            phi[2] = packsplit(sacc[2*kkp+1][0], sacc[2*kkp+1][1], plo[2]);
            phi[3] = packsplit(sacc[2*kkp+1][2], sacc[2*kkp+1][3], plo[3]);
            #pragma unroll
            for (int np = 0; np < 4; np++) {
                const uint32_t va = (uint32_t)(kkp * 16) * SRS + vRowOff + np * 32;
                uint32_t vh[4];
                ldsm_x4_t(vh, Vhi_ + va);
                #pragma unroll
                for (int t = 0; t < 2; t++) {
                    mma16816(acc_o[2 * np + t], phi, &vh[2 * t]);
                    mma16816(acc_o[2 * np + t], plo, &vh[2 * t]);
                }
            }
        }
    }

    // ---- epilogue: O / l, write bf16 hi/lo into GEMM A buffers ----
    const float inv0 = 1.f / l0, inv1 = 1.f / l1;
    const int row0 = b * TT + q0 + wid * 16 + (lane >> 2);
    const int colb = h * DHH + 2 * (lane & 3);
    #pragma unroll
    for (int nt = 0; nt < 8; nt++) {
        const int col = colb + nt * 8;
        uint32_t lo;
        uint32_t hi = packsplit(acc_o[nt][0] * inv0, acc_o[nt][1] * inv0, lo);
        *(uint32_t*)(Ohi + (size_t)row0 * EE + col) = hi;
        *(uint32_t*)(Olo + (size_t)row0 * EE + col) = lo;
        hi = packsplit(acc_o[nt][2] * inv1, acc_o[nt][3] * inv1, lo);
        *(uint32_t*)(Ohi + (size_t)(row0 + 8) * EE + col) = hi;
        *(uint32_t*)(Olo + (size_t)(row0 + 8) * EE + col) = lo;
    }
}

// =====================================================================
// LayerNorm: block per row, 256 threads; optional fp32 + bf16 hi/lo out
// =====================================================================
__global__ __launch_bounds__(256) void layernorm_kernel(
    const float* __restrict__ x, const float* __restrict__ gam,
    const float* __restrict__ bet, float* __restrict__ outF,
    __nv_bfloat16* __restrict__ outHi, __nv_bfloat16* __restrict__ outLo)
{
    const int row = blockIdx.x;
    const int tid = threadIdx.x;
    const float4 xv = *(const float4*)(x + (size_t)row * EE + tid * 4);

    __shared__ float red[8];

    float s = xv.x + xv.y + xv.z + xv.w;
    #pragma unroll
    for (int o = 16; o; o >>= 1) s += __shfl_xor_sync(0xffffffffu, s, o);
    if ((tid & 31) == 0) red[tid >> 5] = s;
    __syncthreads();
    float tot = 0.f;
    #pragma unroll
    for (int i = 0; i < 8; i++) tot += red[i];
    const float mu = tot * (1.0f / (float)EE);
    __syncthreads();

    const float dx = xv.x - mu, dy = xv.y - mu, dz = xv.z - mu, dw = xv.w - mu;
    float ss = dx*dx + dy*dy + dz*dz + dw*dw;
    #pragma unroll
    for (int o = 16; o; o >>= 1) ss += __shfl_xor_sync(0xffffffffu, ss, o);
    if ((tid & 31) == 0) red[tid >> 5] = ss;
    __syncthreads();
    float sst = 0.f;
    #pragma unroll
    for (int i = 0; i < 8; i++) sst += red[i];
    const float inv = rsqrtf(sst * (1.0f / (float)EE) + LN_EPS);

    const float4 gv = *(const float4*)(gam + tid * 4);
    const float4 bv = *(const float4*)(bet + tid * 4);
    float4 ov;
    ov.x = dx * inv * gv.x + bv.x;
    ov.y = dy * inv * gv.y + bv.y;
    ov.z = dz * inv * gv.z + bv.z;
    ov.w = dw * inv * gv.w + bv.w;
    if (outF) *(float4*)(outF + (size_t)row * EE + tid * 4) = ov;
    uint32_t lo0, lo1;
    const uint32_t hi0 = packsplit(ov.x, ov.y, lo0);
    const uint32_t hi1 = packsplit(ov.z, ov.w, lo1);
    uint2 hv; hv.x = hi0; hv.y = hi1;
    uint2 lv; lv.x = lo0; lv.y = lo1;
    *(uint2*)(outHi + (size_t)row * EE + tid * 4) = hv;
    *(uint2*)(outLo + (size_t)row * EE + tid * 4) = lv;
}

// =====================================================================
// Argmax reduce over 16 partials per row
// =====================================================================
__global__ __launch_bounds__(256) void argmax_reduce_kernel(
    const unsigned long long* __restrict__ part, int* __restrict__ idx)
{
    const int m = blockIdx.x * 256 + threadIdx.x;
    const unsigned long long* p = part + (size_t)m * 16;
    unsigned long long k = p[0];
    #pragma unroll
    for (int i = 1; i < 16; i++) {
        const unsigned long long v = p[i];
        if (v > k) k = v;
    }
    idx[m] = dec_argmax(k);
}

// =====================================================================
// MoE routing: clear-hist / hist / scan / scatter (from g_idx)
// =====================================================================
__global__ __launch_bounds__(256) void hist_clear_kernel(int* __restrict__ hist)
{
    hist[blockIdx.x * 256 + threadIdx.x] = 0;
}

__global__ __launch_bounds__(256) void hist_kernel(
    const int* __restrict__ idx, int* __restrict__ hist)
{
    const int t = blockIdx.x * 256 + threadIdx.x;
    atomicAdd(&hist[idx[t]], 1);
}

__global__ __launch_bounds__(1024) void scan_kernel(
    const int* __restrict__ hist, int* __restrict__ cursor)
{
    __shared__ int warpsum[32];
    const int tid = threadIdx.x;
    const int lane = tid & 31, wid = tid >> 5;
    const int v0 = hist[2 * tid], v1 = hist[2 * tid + 1];
    const int tsum = v0 + v1;
    int x = tsum;
    #pragma unroll
    for (int o = 1; o < 32; o <<= 1) {
        const int y = __shfl_up_sync(0xffffffffu, x, o);
        if (lane >= o) x += y;
    }
    if (lane == 31) warpsum[wid] = x;
    __syncthreads();
    if (wid == 0) {
        int w = warpsum[lane];
        #pragma unroll
        for (int o = 1; o < 32; o <<= 1) {
            const int y = __shfl_up_sync(0xffffffffu, w, o);
            if (lane >= o) w += y;
        }
        warpsum[lane] = w;
    }
    __syncthreads();
    const int base = (wid > 0 ? warpsum[wid - 1] : 0) + (x - tsum);
    cursor[2 * tid] = base;
    cursor[2 * tid + 1] = base + v0;
}

__global__ __launch_bounds__(256) void scatter_kernel(
    const int* __restrict__ idx, int* __restrict__ cursor,
    int* __restrict__ perm)
{
    const int t = blockIdx.x * 256 + threadIdx.x;
    const int pos = atomicAdd(&cursor[idx[t]], 1);
    perm[pos] = t;
}

// =====================================================================
// MoE: one block per (expert-sorted) token
// =====================================================================
__global__ __launch_bounds__(256) void moe_kernel(
    const float* __restrict__ h, const int* __restrict__ idx,
    const int* __restrict__ perm,
    const float* __restrict__ w1, const float* __restrict__ b1,
    const float* __restrict__ w2, const float* __restrict__ b2,
    float* __restrict__ out)
{
    const int token = perm[blockIdx.x];
    const int tid = threadIdx.x;
    const int e = idx[token];

    __shared__ float xs[EE];
    __shared__ float partial[HIDD][17];
    __shared__ float hm[HIDD];

    const float* hrow = h + (size_t)token * EE;
    for (int i = tid; i < EE; i += 256) xs[i] = hrow[i];
    __syncthreads();

    const int hcol = tid & 15;
    const int grp  = tid >> 4;
    const float* w1p = w1 + (size_t)e * EE * HIDD;
    float acc = 0.f;
    for (int i = grp; i < EE; i += 16)
        acc += xs[i] * w1p[(size_t)i * HIDD + hcol];
    partial[hcol][grp] = acc;
    __syncthreads();

    if (tid < HIDD) {
        float s = b1[(size_t)e * HIDD + tid];
        #pragma unroll
        for (int g2 = 0; g2 < 16; g2++) s += partial[tid][g2];
        hm[tid] = 0.5f * s * (1.0f + erff(s * 0.70710678118654752f));
    }
    __syncthreads();

    float hreg[HIDD];
    #pragma unroll
    for (int k = 0; k < HIDD; k++) hreg[k] = hm[k];

    const float* w2p = w2 + (size_t)e * HIDD * EE;
    const float* b2p = b2 + (size_t)e * EE;
    float* orow = out + (size_t)token * EE;
    for (int j = tid; j < EE; j += 256) {
        float s = b2p[j];
        #pragma unroll
        for (int k = 0; k < HIDD; k++) s += hreg[k] * w2p[(size_t)k * EE + j];
        orow[j] += s;
    }
}

// =====================================================================
// launch
// =====================================================================
extern "C" void kernel_launch(void* const* d_in, const int* in_sizes, int n_in,
                              void* d_out, int out_size)
{
    const float* x      = (const float*)d_in[0];
    const float* ln1_g  = (const float*)d_in[1];
    const float* ln1_b  = (const float*)d_in[2];
    const float* ln2_g  = (const float*)d_in[3];
    const float* ln2_b  = (const float*)d_in[4];
    const float* qkv_w  = (const float*)d_in[5];
    const float* qkv_b  = (const float*)d_in[6];
    const float* proj_w = (const float*)d_in[7];
    const float* proj_b = (const float*)d_in[8];
    const float* gate_w = (const float*)d_in[9];
    const float* gate_b = (const float*)d_in[10];
    const float* w1     = (const float*)d_in[11];
    const float* b1     = (const float*)d_in[12];
    const float* w2     = (const float*)d_in[13];
    const float* w2b    = (const float*)d_in[14];
    float* out = (float*)d_out;

    void *p_h, *p_part, *p_idx, *p_hist, *p_cur, *p_perm,
         *p_ah, *p_al, *p_bh, *p_bl, *p_qh;
    cudaGetSymbolAddress(&p_h, g_h);
    cudaGetSymbolAddress(&p_part, g_part);
    cudaGetSymbolAddress(&p_idx, g_idx);
    cudaGetSymbolAddress(&p_hist, g_hist);
    cudaGetSymbolAddress(&p_cur, g_cursor);
    cudaGetSymbolAddress(&p_perm, g_perm);
    cudaGetSymbolAddress(&p_ah, g_Ahi);
    cudaGetSymbolAddress(&p_al, g_Alo);
    cudaGetSymbolAddress(&p_bh, g_Bhi);
    cudaGetSymbolAddress(&p_bl, g_Blo);
    cudaGetSymbolAddress(&p_qh, g_QKVhi);
    float* bh      = (float*)p_h;
    unsigned long long* bpart = (unsigned long long*)p_part;
    int*   bidx    = (int*)p_idx;
    int*   hist    = (int*)p_hist;
    int*   cursor  = (int*)p_cur;
    int*   perm    = (int*)p_perm;
    __nv_bfloat16* Ahi = (__nv_bfloat16*)p_ah;
    __nv_bfloat16* Alo = (__nv_bfloat16*)p_al;
    __nv_bfloat16* Bhi = (__nv_bfloat16*)p_bh;
    __nv_bfloat16* Blo = (__nv_bfloat16*)p_bl;
    __nv_bfloat16* QKVhi = (__nv_bfloat16*)p_qh;

    cudaFuncSetAttribute(gemm_tc<2>, cudaFuncAttributeMaxDynamicSharedMemorySize, GEMM_SMEM);
    cudaFuncSetAttribute(gemm_tc<3>, cudaFuncAttributeMaxDynamicSharedMemorySize, GEMM_SMEM);
    cudaFuncSetAttribute(flash_mma_kernel, cudaFuncAttributeMaxDynamicSharedMemorySize, ATT_SMEM);

    // 1) LN1(x) -> bf16 hi/lo A operand
    layernorm_kernel<<<MTOK, 256>>>(x, ln1_g, ln1_b, nullptr, Ahi, Alo);

    // 2) qkv = h @ qkv_w + qkv_b -> bf16 hi only (2-term split)
    convW_kernel<<<dim3(3*EE/64, EE/64), 256>>>(qkv_w, Bhi, Blo, 3*EE, EE);
    gemm_tc<2><<<dim3(3*EE/128, MTOK/128), 256, GEMM_SMEM>>>(
        Ahi, Alo, Bhi, Blo, qkv_b, nullptr, nullptr, QKVhi, nullptr, nullptr, 3*EE, EE);

    // 3) attention -> bf16 hi/lo into A operand buffers
    flash_mma_kernel<<<dim3(TT/128, NHH, BB), 256, ATT_SMEM>>>(QKVhi, Ahi, Alo);

    // 4) xmid = x + attn @ proj_w + proj_b -> d_out (fp32, full 3-term)
    convW_kernel<<<dim3(EE/64, EE/64), 256>>>(proj_w, Bhi, Blo, EE, EE);
    gemm_tc<3><<<dim3(EE/128, MTOK/128), 256, GEMM_SMEM>>>(
        Ahi, Alo, Bhi, Blo, proj_b, x, out, nullptr, nullptr, nullptr, EE, EE);

    // 5) LN2 -> fp32 (MoE) + bf16 hi/lo (gate GEMM)
    layernorm_kernel<<<MTOK, 256>>>(out, ln2_g, ln2_b, bh, Ahi, Alo);

    // 6) gate GEMM with fused argmax partials (full 3-term: argmax safety)
    convW_kernel<<<dim3(NEE/64, EE/64), 256>>>(gate_w, Bhi, Blo, NEE, EE);
    gemm_tc<3><<<dim3(NEE/128, MTOK/128), 256, GEMM_SMEM>>>(
        Ahi, Alo, Bhi, Blo, gate_b, nullptr, nullptr, nullptr, nullptr, bpart, NEE, EE);

    // 7) idx = reduce(partials); expert-locality sort
    argmax_reduce_kernel<<<MTOK/256, 256>>>(bpart, bidx);
    hist_clear_kernel<<<NEE/256, 256>>>(hist);
    hist_kernel<<<MTOK/256, 256>>>(bidx, hist);
    scan_kernel<<<1, 1024>>>(hist, cursor);
    scatter_kernel<<<MTOK/256, 256>>>(bidx, cursor, perm);

    // 8) d_out += moe(h, idx) over expert-sorted tokens (block per token)
    moe_kernel<<<MTOK, 256>>>(bh, bidx, perm, w1, b1, w2, w2b, out);
}